// round 7
// baseline (speedup 1.0000x reference)
#include <cuda_runtime.h>
#include <math.h>

#define B_    4
#define W_    1024
#define BINS_ 1024
#define H_    4
#define DH_   256
#define FF2_  4096
#define FFH_  1024

// stage layout for pipelined GEMMs: A(4608 floats) + B(4608 floats) per stage, 3 stages
#define STAGE_F 9216
#define NSTAGE  3
#define SMEM_BYTES (NSTAGE * STAGE_F * 4)

// ---------------- scratch (static device memory; no allocations) ----------------
__device__ float g_xs [(size_t)B_*W_*BINS_];
__device__ float g_ms [(size_t)B_*W_*BINS_];
__device__ float g_q  [(size_t)B_*W_*BINS_];
__device__ float g_k  [(size_t)B_*W_*BINS_];
__device__ float g_v  [(size_t)B_*W_*BINS_];
__device__ float g_att[(size_t)B_*W_*BINS_];
__device__ float g_hs [(size_t)B_*W_*BINS_];
__device__ float g_hm [(size_t)B_*W_*BINS_];
__device__ float g_t1 [(size_t)B_*W_*BINS_];
__device__ float g_t2 [(size_t)B_*W_*BINS_];
__device__ float g_dwc[(size_t)B_*W_*BINS_];
__device__ float g_ffb[(size_t)B_*W_*FFH_];
__device__ float g_scores[(size_t)B_*H_*W_*W_];
__device__ float g_ffa[(size_t)B_*W_*FF2_];
__device__ float g_dwf[(size_t)B_*W_*FF2_];

// rounded weights: attn_w | er | c1L_pw | c1R_pw | c2_pw | c3_w | c4_w
#define OFF_AW   0L
#define OFF_ER   16777216L
#define OFF_C1L  17825792L
#define OFF_C1R  22020096L
#define OFF_C2   23068672L
#define OFF_C3   27262976L
#define OFF_C4   31457280L
#define WR_TOTAL 35651584L
__device__ float g_wr[WR_TOTAL];

// ---------------- helpers ----------------
__device__ __forceinline__ unsigned f2tf(float f) {
    unsigned r;
    asm("cvt.rna.tf32.f32 %0, %1;" : "=r"(r) : "f"(f));
    return r;
}
__device__ __forceinline__ float tfr(float f) { return __uint_as_float(f2tf(f)); }

__device__ __forceinline__ void mma8(float* d, const unsigned* a, const unsigned* b) {
    asm("mma.sync.aligned.m16n8k8.row.col.f32.tf32.tf32.f32 "
        "{%0,%1,%2,%3},{%4,%5,%6,%7},{%8,%9},{%0,%1,%2,%3};"
        : "+f"(d[0]), "+f"(d[1]), "+f"(d[2]), "+f"(d[3])
        : "r"(a[0]), "r"(a[1]), "r"(a[2]), "r"(a[3]), "r"(b[0]), "r"(b[1]));
}

__device__ __forceinline__ void cp16(float* smem_dst, const float* gsrc) {
    unsigned d = (unsigned)__cvta_generic_to_shared(smem_dst);
    asm volatile("cp.async.cg.shared.global [%0], [%1], 16;" :: "r"(d), "l"(gsrc));
}
__device__ __forceinline__ void cp_commit() { asm volatile("cp.async.commit_group;"); }
__device__ __forceinline__ void cp_wait2()  { asm volatile("cp.async.wait_group 2;"); }

__device__ __forceinline__ float apply_act(float v, int act) {
    if (act == 1) return (v >= 0.f) ? v : 0.01f * v;
    if (act == 2) return v / (1.f + __expf(-v));
    return v;
}

// ---------------- tf32 rounding copy of ALL weight operands in ONE launch ----------------
// segment boundaries in float4 units
__global__ void round_all_kernel(const float4* __restrict__ s0, const float4* __restrict__ s1,
                                 const float4* __restrict__ s2, const float4* __restrict__ s3,
                                 const float4* __restrict__ s4, const float4* __restrict__ s5,
                                 const float4* __restrict__ s6, float4* __restrict__ out)
{
    long i = (long)blockIdx.x * 256 + threadIdx.x;
    if (i >= 8912896L) return;
    const float4* src;
    long rel = i;
    if      (i < 4194304L) { src = s0; rel = i; }
    else if (i < 4456448L) { src = s1; rel = i - 4194304L; }
    else if (i < 5505024L) { src = s2; rel = i - 4456448L; }
    else if (i < 5767168L) { src = s3; rel = i - 5505024L; }
    else if (i < 6815744L) { src = s4; rel = i - 5767168L; }
    else if (i < 7864320L) { src = s5; rel = i - 6815744L; }
    else                   { src = s6; rel = i - 7864320L; }
    float4 v = src[rel];
    v.x = tfr(v.x); v.y = tfr(v.y); v.z = tfr(v.z); v.w = tfr(v.w);
    out[i] = v;
}

// ---------------- input projection: out[b,w,h] = sum_c x[b,c,h,w] * wc[c] ----------------
__global__ void project_kernel(const float* __restrict__ x, const float* __restrict__ wc,
                               int Cn, float* __restrict__ out)
{
    __shared__ float tile[32][33];
    int b  = blockIdx.z;
    int h0 = blockIdx.y * 32, w0 = blockIdx.x * 32;
    int tx = threadIdx.x, ty = threadIdx.y;   // 32 x 8

    float wreg[8];
    #pragma unroll
    for (int c = 0; c < 8; c++) wreg[c] = (c < Cn) ? wc[c] : 0.f;

    #pragma unroll
    for (int r = 0; r < 4; r++) {
        int h = h0 + ty + r * 8;
        float acc = 0.f;
        #pragma unroll
        for (int c = 0; c < 8; c++)
            acc += x[(((size_t)b * Cn + c) * BINS_ + h) * W_ + (w0 + tx)] * wreg[c];
        tile[ty + r * 8][tx] = tfr(acc);
    }
    __syncthreads();
    #pragma unroll
    for (int r = 0; r < 4; r++) {
        int w = w0 + ty + r * 8;
        out[((size_t)b * W_ + w) * BINS_ + (h0 + tx)] = tile[tx][ty + r * 8];
    }
}

// ---------------- final transpose: out[b,h,w] = in[b,w,h] ----------------
__global__ void transpose_out_kernel(const float* __restrict__ in, float* __restrict__ out)
{
    __shared__ float tile[32][33];
    int b  = blockIdx.z;
    int w0 = blockIdx.x * 32, h0 = blockIdx.y * 32;
    int tx = threadIdx.x, ty = threadIdx.y;

    #pragma unroll
    for (int r = 0; r < 4; r++)
        tile[ty + r * 8][tx] = in[((size_t)b * W_ + (w0 + ty + r * 8)) * BINS_ + (h0 + tx)];
    __syncthreads();
    #pragma unroll
    for (int r = 0; r < 4; r++)
        out[((size_t)b * BINS_ + (h0 + ty + r * 8)) * W_ + (w0 + tx)] = tile[tx][ty + r * 8];
}

// ---------------- tf32 tensor-core GEMM, cp.async 3-stage pipeline ----------------
// All operands MUST be pre-rounded to tf32 representable values (no cvt inside).
// BT=1: B is [N,K] row-major (NT); BT=0: B is [K,N] row-major (NN)
// rnd=1: round output to tf32 (for outputs feeding another GEMM directly)
template <int BT>
__global__ void __launch_bounds__(256, 2)
tgemm_kernel(const float* __restrict__ A, int lda, long soA, long siA,
             const float* __restrict__ Bp, int ldb, long soB, long siB,
             const float* __restrict__ bias,
             float* __restrict__ C, int ldc, long soC, long siC,
             int K, int zdiv, int act, int rnd)
{
    extern __shared__ float smem[];

    int z = blockIdx.z;
    long zo = z / zdiv, zi = z % zdiv;
    A  += zo * soA + zi * siA;
    Bp += zo * soB + zi * siB;
    C  += zo * soC + zi * siC;

    int m0 = blockIdx.y * 128, n0 = blockIdx.x * 128;
    int tid  = threadIdx.x;
    int lane = tid & 31, wid = tid >> 5;
    int g = lane >> 2, tg = lane & 3;
    int wm = wid & 3, wn = wid >> 2;      // warp grid 4 (m) x 2 (n)

    float acc[2][8][4] = {};

    auto issue = [&](int k0, int s) {
        float* Sa = smem + s * STAGE_F;
        float* Sb = Sa + 4608;
        #pragma unroll
        for (int i = 0; i < 4; i++) {
            int idx = tid + i * 256;
            int r = idx >> 3, c = (idx & 7) << 2;
            cp16(Sa + r * 36 + c, A + (size_t)(m0 + r) * lda + k0 + c);
            if (BT) {
                cp16(Sb + r * 36 + c, Bp + (size_t)(n0 + r) * ldb + k0 + c);
            } else {
                int kr = idx >> 5, cn = (idx & 31) << 2;
                cp16(Sb + kr * 132 + cn, Bp + (size_t)(k0 + kr) * ldb + n0 + cn);
            }
        }
        cp_commit();
    };

    int nc = K >> 5;
    issue(0, 0);
    if (nc > 1) issue(32, 1);
    for (int ch = 0; ch < nc; ch++) {
        if (ch + 2 < nc) issue((ch + 2) << 5, (ch + 2) % NSTAGE);
        else             cp_commit();
        cp_wait2();
        __syncthreads();

        const unsigned* Ua = (const unsigned*)(smem + (ch % NSTAGE) * STAGE_F);
        const unsigned* Ub = Ua + 4608;
        #pragma unroll
        for (int kk = 0; kk < 32; kk += 8) {
            unsigned af[2][4];
            #pragma unroll
            for (int mt = 0; mt < 2; mt++) {
                int m = wm * 32 + mt * 16 + g;
                af[mt][0] = Ua[m * 36 + kk + tg];
                af[mt][1] = Ua[(m + 8) * 36 + kk + tg];
                af[mt][2] = Ua[m * 36 + kk + tg + 4];
                af[mt][3] = Ua[(m + 8) * 36 + kk + tg + 4];
            }
            unsigned bf[8][2];
            #pragma unroll
            for (int nt = 0; nt < 8; nt++) {
                int n = wn * 64 + nt * 8 + g;
                if (BT) {
                    bf[nt][0] = Ub[n * 36 + kk + tg];
                    bf[nt][1] = Ub[n * 36 + kk + tg + 4];
                } else {
                    bf[nt][0] = Ub[(kk + tg) * 132 + n];
                    bf[nt][1] = Ub[(kk + tg + 4) * 132 + n];
                }
            }
            #pragma unroll
            for (int mt = 0; mt < 2; mt++)
                #pragma unroll
                for (int nt = 0; nt < 8; nt++)
                    mma8(acc[mt][nt], af[mt], bf[nt]);
        }
        __syncthreads();
    }

    // epilogue
    #pragma unroll
    for (int mt = 0; mt < 2; mt++) {
        int r0 = m0 + wm * 32 + mt * 16 + g;
        #pragma unroll
        for (int nt = 0; nt < 8; nt++) {
            int c = n0 + wn * 64 + nt * 8 + tg * 2;
            float b0 = bias ? bias[c] : 0.f, b1 = bias ? bias[c + 1] : 0.f;
            float vv[4];
            vv[0] = apply_act(acc[mt][nt][0] + b0, act);
            vv[1] = apply_act(acc[mt][nt][1] + b1, act);
            vv[2] = apply_act(acc[mt][nt][2] + b0, act);
            vv[3] = apply_act(acc[mt][nt][3] + b1, act);
            if (rnd) {
                vv[0] = tfr(vv[0]); vv[1] = tfr(vv[1]);
                vv[2] = tfr(vv[2]); vv[3] = tfr(vv[3]);
            }
            *reinterpret_cast<float2*>(C + (size_t)r0 * ldc + c)       = make_float2(vv[0], vv[1]);
            *reinterpret_cast<float2*>(C + (size_t)(r0 + 8) * ldc + c) = make_float2(vv[2], vv[3]);
        }
    }
}

// ---------------- fused attention scores as a virtual K=512 pipelined GEMM ----------------
// s[i,j] = (sum_k Q[i,k]K[j,k]  +  sum_k er[k,i]Q[j,k]) / 32
// Operands pre-rounded to tf32. chunks 0..7: Q/K (NT); chunks 8..15: er (NN) / Q (NT)
__global__ void __launch_bounds__(256, 2)
scores_kernel(const float* __restrict__ q, const float* __restrict__ kx,
              const float* __restrict__ er, float* __restrict__ s)
{
    extern __shared__ float smem[];

    int bh = blockIdx.z;
    int b = bh >> 2, h = bh & 3;
    const float* qb = q  + (size_t)b * W_ * BINS_ + h * DH_;
    const float* kb = kx + (size_t)b * W_ * BINS_ + h * DH_;
    float* sb = s + (size_t)bh * W_ * W_;

    int i0 = blockIdx.y * 128, j0 = blockIdx.x * 128;
    int tid  = threadIdx.x;
    int lane = tid & 31, wid = tid >> 5;
    int g = lane >> 2, tg = lane & 3;
    int wm = wid & 3, wn = wid >> 2;

    float acc[2][8][4] = {};

    auto issue = [&](int t) {
        float* Sa = smem + (t % NSTAGE) * STAGE_F;
        float* Sb = Sa + 4608;
        int k0 = (t & 7) << 5;
        #pragma unroll
        for (int i = 0; i < 4; i++) {
            int idx = tid + i * 256;
            int r = idx >> 3, c = (idx & 7) << 2;
            if (t < 8) {
                cp16(Sa + r * 36 + c, qb + (size_t)(i0 + r) * BINS_ + k0 + c);
                cp16(Sb + r * 36 + c, kb + (size_t)(j0 + r) * BINS_ + k0 + c);
            } else {
                int kr = idx >> 5, cn = (idx & 31) << 2;
                cp16(Sa + kr * 132 + cn, er + (size_t)(k0 + kr) * W_ + i0 + cn);
                cp16(Sb + r * 36 + c, qb + (size_t)(j0 + r) * BINS_ + k0 + c);
            }
        }
        cp_commit();
    };

    issue(0); issue(1);
    for (int t = 0; t < 16; t++) {
        if (t + 2 < 16) issue(t + 2);
        else            cp_commit();
        cp_wait2();
        __syncthreads();

        const unsigned* Ua = (const unsigned*)(smem + (t % NSTAGE) * STAGE_F);
        const unsigned* Ub = Ua + 4608;
        bool nnA = (t >= 8);
        #pragma unroll
        for (int kk = 0; kk < 32; kk += 8) {
            unsigned af[2][4];
            #pragma unroll
            for (int mt = 0; mt < 2; mt++) {
                int m = wm * 32 + mt * 16 + g;
                if (!nnA) {
                    af[mt][0] = Ua[m * 36 + kk + tg];
                    af[mt][1] = Ua[(m + 8) * 36 + kk + tg];
                    af[mt][2] = Ua[m * 36 + kk + tg + 4];
                    af[mt][3] = Ua[(m + 8) * 36 + kk + tg + 4];
                } else {
                    af[mt][0] = Ua[(kk + tg) * 132 + m];
                    af[mt][1] = Ua[(kk + tg) * 132 + m + 8];
                    af[mt][2] = Ua[(kk + tg + 4) * 132 + m];
                    af[mt][3] = Ua[(kk + tg + 4) * 132 + m + 8];
                }
            }
            unsigned bf[8][2];
            #pragma unroll
            for (int nt = 0; nt < 8; nt++) {
                int n = wn * 64 + nt * 8 + g;
                bf[nt][0] = Ub[n * 36 + kk + tg];
                bf[nt][1] = Ub[n * 36 + kk + tg + 4];
            }
            #pragma unroll
            for (int mt = 0; mt < 2; mt++)
                #pragma unroll
                for (int nt = 0; nt < 8; nt++)
                    mma8(acc[mt][nt], af[mt], bf[nt]);
        }
        __syncthreads();
    }

    #pragma unroll
    for (int mt = 0; mt < 2; mt++) {
        int r0 = i0 + wm * 32 + mt * 16 + g;
        #pragma unroll
        for (int nt = 0; nt < 8; nt++) {
            int c = j0 + wn * 64 + nt * 8 + tg * 2;
            float2 v0, v1;
            v0.x = acc[mt][nt][0] * 0.03125f;
            v0.y = acc[mt][nt][1] * 0.03125f;
            v1.x = acc[mt][nt][2] * 0.03125f;
            v1.y = acc[mt][nt][3] * 0.03125f;
            *reinterpret_cast<float2*>(sb + (size_t)r0 * W_ + c) = v0;
            *reinterpret_cast<float2*>(sb + (size_t)(r0 + 8) * W_ + c) = v1;
        }
    }
}

// ---------------- row softmax over n=1024 (output rounded to tf32) ----------------
__global__ void softmax_kernel(float* __restrict__ s)
{
    const int n = W_;
    float* row = s + (size_t)blockIdx.x * n;
    int tid = threadIdx.x;
    __shared__ float red[8];

    float m = -3.4e38f;
    for (int i = tid; i < n; i += 256) m = fmaxf(m, row[i]);
    #pragma unroll
    for (int o = 16; o; o >>= 1) m = fmaxf(m, __shfl_xor_sync(0xffffffffu, m, o));
    if ((tid & 31) == 0) red[tid >> 5] = m;
    __syncthreads();
    m = red[0];
    #pragma unroll
    for (int wi = 1; wi < 8; wi++) m = fmaxf(m, red[wi]);

    float sum = 0.f;
    for (int i = tid; i < n; i += 256) { float e = __expf(row[i] - m); row[i] = e; sum += e; }
    #pragma unroll
    for (int o = 16; o; o >>= 1) sum += __shfl_xor_sync(0xffffffffu, sum, o);
    __syncthreads();
    if ((tid & 31) == 0) red[tid >> 5] = sum;
    __syncthreads();
    float tot = 0.f;
    #pragma unroll
    for (int wi = 0; wi < 8; wi++) tot += red[wi];
    float inv = 1.f / tot;
    for (int i = tid; i < n; i += 256) row[i] = tfr(row[i] * inv);
}

// ---------------- fused (a*omega + b + c) -> LayerNorm ----------------
__global__ void ln_kernel(const float* __restrict__ a, const float* __restrict__ bsrc,
                          const float* __restrict__ csrc, const float* __restrict__ omega,
                          const float* __restrict__ g, const float* __restrict__ bet,
                          float* __restrict__ out, int R, int rnd)
{
    extern __shared__ float sm[];
    __shared__ float rs[8], rq[8];
    size_t base = (size_t)blockIdx.x * R;
    int tid = threadIdx.x;

    float s = 0.f, sq = 0.f;
    for (int i = tid; i < R; i += 256) {
        float v = a[base + i];
        if (omega) v *= omega[i];
        if (bsrc)  v += bsrc[base + i];
        if (csrc)  v += csrc[base + i];
        sm[i] = v; s += v; sq += v * v;
    }
    #pragma unroll
    for (int o = 16; o; o >>= 1) {
        s  += __shfl_xor_sync(0xffffffffu, s, o);
        sq += __shfl_xor_sync(0xffffffffu, sq, o);
    }
    if ((tid & 31) == 0) { rs[tid >> 5] = s; rq[tid >> 5] = sq; }
    __syncthreads();
    float ts = 0.f, tq = 0.f;
    #pragma unroll
    for (int wi = 0; wi < 8; wi++) { ts += rs[wi]; tq += rq[wi]; }
    float mean = ts / (float)R;
    float var  = tq / (float)R - mean * mean;
    float inv  = rsqrtf(var + 1e-5f);
    for (int i = tid; i < R; i += 256) {
        float v = (sm[i] - mean) * inv * g[i] + bet[i];
        out[base + i] = rnd ? tfr(v) : v;
    }
}

// ---------------- depthwise conv along w, layout [B, W, Ch] (output rounded) ----------------
__global__ void dwconv_kernel(const float* __restrict__ in, const float* __restrict__ wk,
                              float* __restrict__ out, int Ch, int Kt, int pad)
{
    int c = blockIdx.x * blockDim.x + threadIdx.x;
    int w = blockIdx.y, b = blockIdx.z;
    const float* ib = in + ((size_t)b * W_) * Ch;
    float acc = 0.f;
    for (int t = 0; t < Kt; t++) {
        int ww = w + t - pad;
        if (ww >= 0 && ww < W_) acc += ib[(size_t)ww * Ch + c] * wk[c * Kt + t];
    }
    out[((size_t)b * W_ + w) * Ch + c] = tfr(acc);
}

// ---------------- hL[:, :FFH] += hR ----------------
__global__ void add_pad_kernel(float* __restrict__ ffa, const float* __restrict__ ffb)
{
    size_t idx = (size_t)blockIdx.x * 256 + threadIdx.x;   // over B*W*FFH
    size_t row = idx / FFH_, f = idx % FFH_;
    ffa[row * FF2_ + f] += ffb[idx];
}

// =========================================================================
static void launch_tgemm(const float* A, int lda, long soA, long siA,
                         const float* Bp, int ldb, long soB, long siB,
                         const float* bias, float* C, int ldc, long soC, long siC,
                         int M, int N, int K, int nz, int zdiv, int BT, int act, int rnd)
{
    dim3 g(N / 128, M / 128, nz);
    if (BT)
        tgemm_kernel<1><<<g, 256, SMEM_BYTES>>>(A, lda, soA, siA, Bp, ldb, soB, siB, bias,
                                                C, ldc, soC, siC, K, zdiv, act, rnd);
    else
        tgemm_kernel<0><<<g, 256, SMEM_BYTES>>>(A, lda, soA, siA, Bp, ldb, soB, siB, bias,
                                                C, ldc, soC, siC, K, zdiv, act, rnd);
}

static void run_attn(const float* xin, const float* min_,
                     const float* w, const float* bias, const float* er,
                     float* q, float* k, float* v, float* att, float* scores,
                     float* outp)
{
    const long NK = (long)BINS_ * BINS_;
    const int M = B_ * W_;
    launch_tgemm(xin,  BINS_, 0, 0, w + 0 * NK, BINS_, 0, 0, bias + 0 * BINS_, q,   BINS_, 0, 0, M, BINS_, BINS_, 1, 1, 1, 0, 1);
    launch_tgemm(min_, BINS_, 0, 0, w + 1 * NK, BINS_, 0, 0, bias + 1 * BINS_, k,   BINS_, 0, 0, M, BINS_, BINS_, 1, 1, 1, 0, 1);
    launch_tgemm(min_, BINS_, 0, 0, w + 2 * NK, BINS_, 0, 0, bias + 2 * BINS_, v,   BINS_, 0, 0, M, BINS_, BINS_, 1, 1, 1, 0, 1);

    dim3 gs(W_ / 128, W_ / 128, B_ * H_);
    scores_kernel<<<gs, 256, SMEM_BYTES>>>(q, k, er, scores);
    softmax_kernel<<<B_ * H_ * W_, 256>>>(scores);

    // att[b, i, h*DH+d] = sum_j scores[b,h,i,j] * v[b, j, h*DH+d]   (batched NN)
    launch_tgemm(scores, W_, 4L * W_ * W_, (long)W_ * W_,
                 v, BINS_, (long)W_ * BINS_, DH_,
                 nullptr,
                 att, BINS_, (long)W_ * BINS_, DH_,
                 W_, DH_, W_, B_ * H_, H_, 0, 0, 1);

    launch_tgemm(att, BINS_, 0, 0, w + 3 * NK, BINS_, 0, 0, bias + 3 * BINS_, outp, BINS_, 0, 0, M, BINS_, BINS_, 1, 1, 1, 0, 0);
}

extern "C" void kernel_launch(void* const* d_in, const int* in_sizes, int n_in,
                              void* d_out, int out_size)
{
    (void)in_sizes; (void)n_in; (void)out_size;

    cudaFuncSetAttribute(tgemm_kernel<0>, cudaFuncAttributeMaxDynamicSharedMemorySize, SMEM_BYTES);
    cudaFuncSetAttribute(tgemm_kernel<1>, cudaFuncAttributeMaxDynamicSharedMemorySize, SMEM_BYTES);
    cudaFuncSetAttribute(scores_kernel,   cudaFuncAttributeMaxDynamicSharedMemorySize, SMEM_BYTES);

    const float* x      = (const float*)d_in[0];
    const float* mem    = (const float*)d_in[1];
    const float* in_w   = (const float*)d_in[2];
    const float* skip_w = (const float*)d_in[3];
    const float* attn_w = (const float*)d_in[4];
    const float* attn_b = (const float*)d_in[5];
    const float* er     = (const float*)d_in[6];
    const float* omega  = (const float*)d_in[7];
    const float* ln_g   = (const float*)d_in[8];
    const float* ln_b   = (const float*)d_in[9];
    const float* ln2_g  = (const float*)d_in[10];
    const float* ln2_b  = (const float*)d_in[11];
    const float* c1L_dw = (const float*)d_in[12];
    const float* c1L_pw = (const float*)d_in[13];
    const float* c1R_dw = (const float*)d_in[14];
    const float* c1R_pw = (const float*)d_in[15];
    const float* c2_dw  = (const float*)d_in[16];
    const float* c2_pw  = (const float*)d_in[17];
    const float* c3_w   = (const float*)d_in[18];
    const float* c4_w   = (const float*)d_in[19];

    float *p_xs, *p_ms, *p_q, *p_k, *p_v, *p_att, *p_hs, *p_hm, *p_t1, *p_t2;
    float *p_dwc, *p_ffb, *p_scores, *p_ffa, *p_dwf, *p_wr;
    cudaGetSymbolAddress((void**)&p_xs,  g_xs);
    cudaGetSymbolAddress((void**)&p_ms,  g_ms);
    cudaGetSymbolAddress((void**)&p_q,   g_q);
    cudaGetSymbolAddress((void**)&p_k,   g_k);
    cudaGetSymbolAddress((void**)&p_v,   g_v);
    cudaGetSymbolAddress((void**)&p_att, g_att);
    cudaGetSymbolAddress((void**)&p_hs,  g_hs);
    cudaGetSymbolAddress((void**)&p_hm,  g_hm);
    cudaGetSymbolAddress((void**)&p_t1,  g_t1);
    cudaGetSymbolAddress((void**)&p_t2,  g_t2);
    cudaGetSymbolAddress((void**)&p_dwc, g_dwc);
    cudaGetSymbolAddress((void**)&p_ffb, g_ffb);
    cudaGetSymbolAddress((void**)&p_scores, g_scores);
    cudaGetSymbolAddress((void**)&p_ffa, g_ffa);
    cudaGetSymbolAddress((void**)&p_dwf, g_dwf);
    cudaGetSymbolAddress((void**)&p_wr,  g_wr);

    // ---- round all GEMM weight operands to tf32, ONE launch ----
    round_all_kernel<<<(8912896L + 255) / 256, 256>>>(
        (const float4*)attn_w, (const float4*)er, (const float4*)c1L_pw,
        (const float4*)c1R_pw, (const float4*)c2_pw, (const float4*)c3_w,
        (const float4*)c4_w, (float4*)p_wr);

    const float* aw_r  = p_wr + OFF_AW;
    const float* er_r  = p_wr + OFF_ER;
    const float* c1L_r = p_wr + OFF_C1L;
    const float* c1R_r = p_wr + OFF_C1R;
    const float* c2_r  = p_wr + OFF_C2;
    const float* c3_r  = p_wr + OFF_C3;
    const float* c4_r  = p_wr + OFF_C4;

    const int  M  = B_ * W_;
    const long ANK = 4L * BINS_ * BINS_;   // per-attention weight stride
    const long ERS = (long)DH_ * W_;

    // input / skip projections
    {
        dim3 g(W_ / 32, BINS_ / 32, B_), blk(32, 8);
        project_kernel<<<g, blk>>>(x,   in_w,   8, p_xs);
        project_kernel<<<g, blk>>>(mem, skip_w, 8, p_ms);
    }

    // self_attn1 / enc_attn1
    run_attn(p_xs, p_xs, aw_r + 0 * ANK, attn_b + 0 * 4 * BINS_, er_r + 0 * ERS,
             p_q, p_k, p_v, p_att, p_scores, p_hs);
    run_attn(p_xs, p_ms, aw_r + 1 * ANK, attn_b + 1 * 4 * BINS_, er_r + 1 * ERS,
             p_q, p_k, p_v, p_att, p_scores, p_hm);

    // x1 = LN(xs*omega0 + hs + hm)   (feeds dwconv only -> no round)
    ln_kernel<<<M, 256, BINS_ * 4>>>(p_xs, p_hs, p_hm, omega + 0 * BINS_,
                                     ln_g + 0 * BINS_, ln_b + 0 * BINS_, p_t1, BINS_, 0);

    // conv block
    dwconv_kernel<<<dim3(BINS_ / 256, W_, B_), 256>>>(p_t1, c1L_dw, p_dwc, BINS_, 11, 5);
    launch_tgemm(p_dwc, BINS_, 0, 0, c1L_r, BINS_, 0, 0, nullptr, p_ffa, FF2_, 0, 0,
                 M, FF2_, BINS_, 1, 1, 1, 1 /*lrelu*/, 0);
    dwconv_kernel<<<dim3(BINS_ / 256, W_, B_), 256>>>(p_t1, c1R_dw, p_dwc, BINS_, 7, 3);
    launch_tgemm(p_dwc, BINS_, 0, 0, c1R_r, BINS_, 0, 0, nullptr, p_ffb, FFH_, 0, 0,
                 M, FFH_, BINS_, 1, 1, 1, 0, 0);
    add_pad_kernel<<<(B_ * W_ * FFH_) / 256, 256>>>(p_ffa, p_ffb);
    ln_kernel<<<M, 256, FF2_ * 4>>>(p_ffa, nullptr, nullptr, nullptr, ln2_g, ln2_b, p_ffa, FF2_, 0);
    dwconv_kernel<<<dim3(FF2_ / 256, W_, B_), 256>>>(p_ffa, c2_dw, p_dwf, FF2_, 7, 3);
    launch_tgemm(p_dwf, FF2_, 0, 0, c2_r, FF2_, 0, 0, nullptr, p_hs, BINS_, 0, 0,
                 M, BINS_, FF2_, 1, 1, 1, 0, 0);

    // x2 = LN(x1*omega1 + h)  (feeds self_attn2 GEMM A -> round)
    ln_kernel<<<M, 256, BINS_ * 4>>>(p_t1, p_hs, nullptr, omega + 1 * BINS_,
                                     ln_g + 1 * BINS_, ln_b + 1 * BINS_, p_t2, BINS_, 1);

    // self_attn2 ; x3 = LN(x2*omega2 + h)  (feeds enc_attn2 -> round)
    run_attn(p_t2, p_t2, aw_r + 2 * ANK, attn_b + 2 * 4 * BINS_, er_r + 2 * ERS,
             p_q, p_k, p_v, p_att, p_scores, p_hs);
    ln_kernel<<<M, 256, BINS_ * 4>>>(p_t2, p_hs, nullptr, omega + 2 * BINS_,
                                     ln_g + 2 * BINS_, ln_b + 2 * BINS_, p_t1, BINS_, 1);

    // enc_attn2 ; x4 = LN(x3*omega3 + h)  (feeds c3 GEMM -> round)
    run_attn(p_t1, p_ms, aw_r + 3 * ANK, attn_b + 3 * 4 * BINS_, er_r + 3 * ERS,
             p_q, p_k, p_v, p_att, p_scores, p_hs);
    ln_kernel<<<M, 256, BINS_ * 4>>>(p_t1, p_hs, nullptr, omega + 3 * BINS_,
                                     ln_g + 3 * BINS_, ln_b + 3 * BINS_, p_t2, BINS_, 1);

    // FFN: silu(x4 @ c3^T) @ c4^T   (silu output feeds c4 GEMM -> round)
    launch_tgemm(p_t2, BINS_, 0, 0, c3_r, BINS_, 0, 0, nullptr, p_ffa, FF2_, 0, 0,
                 M, FF2_, BINS_, 1, 1, 1, 2 /*silu*/, 1);
    launch_tgemm(p_ffa, FF2_, 0, 0, c4_r, FF2_, 0, 0, nullptr, p_hs, BINS_, 0, 0,
                 M, BINS_, FF2_, 1, 1, 1, 0, 0);

    // out = LN(x4*omega4 + h) (final output -> NO round), then transpose to [B, BINS, W]
    ln_kernel<<<M, 256, BINS_ * 4>>>(p_t2, p_hs, nullptr, omega + 4 * BINS_,
                                     ln_g + 4 * BINS_, ln_b + 4 * BINS_, p_t1, BINS_, 0);
    {
        dim3 g(W_ / 32, BINS_ / 32, B_), blk(32, 8);
        transpose_out_kernel<<<g, blk>>>(p_t1, (float*)d_out);
    }
}

// round 11
// speedup vs baseline: 1.0276x; 1.0276x over previous
#include <cuda_runtime.h>
#include <math.h>

#define B_    4
#define W_    1024
#define BINS_ 1024
#define H_    4
#define DH_   256
#define FF2_  4096
#define FFH_  1024

// stage layout for pipelined GEMMs: A(4608 floats) + B(4608 floats) per stage, 3 stages
#define STAGE_F 9216
#define NSTAGE  3
#define SMEM_BYTES (NSTAGE * STAGE_F * 4)

// ---------------- scratch (static device memory; no allocations) ----------------
__device__ float g_xs [(size_t)B_*W_*BINS_];
__device__ float g_ms [(size_t)B_*W_*BINS_];
__device__ float g_q  [(size_t)B_*W_*BINS_];
__device__ float g_k  [(size_t)B_*W_*BINS_];
__device__ float g_v  [(size_t)B_*W_*BINS_];
__device__ float g_att[(size_t)B_*W_*BINS_];
__device__ float g_hs [(size_t)B_*W_*BINS_];
__device__ float g_hm [(size_t)B_*W_*BINS_];
__device__ float g_t1 [(size_t)B_*W_*BINS_];
__device__ float g_t2 [(size_t)B_*W_*BINS_];
__device__ float g_dwc[(size_t)B_*W_*BINS_];
__device__ float g_ffb[(size_t)B_*W_*FFH_];
__device__ float g_scores[(size_t)B_*H_*W_*W_];
__device__ float g_ffa[(size_t)B_*W_*FF2_];
__device__ float g_dwf[(size_t)B_*W_*FF2_];

// rounded weights: attn_w | er | c1L_pw | c1R_pw | c2_pw | c3_w | c4_w
#define OFF_AW   0L
#define OFF_ER   16777216L
#define OFF_C1L  17825792L
#define OFF_C1R  22020096L
#define OFF_C2   23068672L
#define OFF_C3   27262976L
#define OFF_C4   31457280L
#define WR_TOTAL 35651584L
__device__ float g_wr[WR_TOTAL];

// ---------------- helpers ----------------
__device__ __forceinline__ unsigned f2tf(float f) {
    unsigned r;
    asm("cvt.rna.tf32.f32 %0, %1;" : "=r"(r) : "f"(f));
    return r;
}
__device__ __forceinline__ float tfr(float f) { return __uint_as_float(f2tf(f)); }

__device__ __forceinline__ void mma8(float* d, const unsigned* a, const unsigned* b) {
    asm("mma.sync.aligned.m16n8k8.row.col.f32.tf32.tf32.f32 "
        "{%0,%1,%2,%3},{%4,%5,%6,%7},{%8,%9},{%0,%1,%2,%3};"
        : "+f"(d[0]), "+f"(d[1]), "+f"(d[2]), "+f"(d[3])
        : "r"(a[0]), "r"(a[1]), "r"(a[2]), "r"(a[3]), "r"(b[0]), "r"(b[1]));
}

__device__ __forceinline__ void cp16(float* smem_dst, const float* gsrc) {
    unsigned d = (unsigned)__cvta_generic_to_shared(smem_dst);
    asm volatile("cp.async.cg.shared.global [%0], [%1], 16;" :: "r"(d), "l"(gsrc));
}
__device__ __forceinline__ void cp_commit() { asm volatile("cp.async.commit_group;"); }
__device__ __forceinline__ void cp_wait2()  { asm volatile("cp.async.wait_group 2;"); }

__device__ __forceinline__ float apply_act(float v, int act) {
    if (act == 1) return (v >= 0.f) ? v : 0.01f * v;
    if (act == 2) return v / (1.f + __expf(-v));
    return v;
}

// ---------------- tf32 rounding copy of ALL weight operands in ONE launch ----------------
__global__ void round_all_kernel(const float4* __restrict__ s0, const float4* __restrict__ s1,
                                 const float4* __restrict__ s2, const float4* __restrict__ s3,
                                 const float4* __restrict__ s4, const float4* __restrict__ s5,
                                 const float4* __restrict__ s6, float4* __restrict__ out)
{
    long i = (long)blockIdx.x * 256 + threadIdx.x;
    if (i >= 8912896L) return;
    const float4* src;
    long rel = i;
    if      (i < 4194304L) { src = s0; rel = i; }
    else if (i < 4456448L) { src = s1; rel = i - 4194304L; }
    else if (i < 5505024L) { src = s2; rel = i - 4456448L; }
    else if (i < 5767168L) { src = s3; rel = i - 5505024L; }
    else if (i < 6815744L) { src = s4; rel = i - 5767168L; }
    else if (i < 7864320L) { src = s5; rel = i - 6815744L; }
    else                   { src = s6; rel = i - 7864320L; }
    float4 v = src[rel];
    v.x = tfr(v.x); v.y = tfr(v.y); v.z = tfr(v.z); v.w = tfr(v.w);
    out[i] = v;
}

// ---------------- input projection: out[b,w,h] = sum_c x[b,c,h,w] * wc[c] ----------------
__global__ void project_kernel(const float* __restrict__ x, const float* __restrict__ wc,
                               int Cn, float* __restrict__ out)
{
    __shared__ float tile[32][33];
    int b  = blockIdx.z;
    int h0 = blockIdx.y * 32, w0 = blockIdx.x * 32;
    int tx = threadIdx.x, ty = threadIdx.y;   // 32 x 8

    float wreg[8];
    #pragma unroll
    for (int c = 0; c < 8; c++) wreg[c] = (c < Cn) ? wc[c] : 0.f;

    #pragma unroll
    for (int r = 0; r < 4; r++) {
        int h = h0 + ty + r * 8;
        float acc = 0.f;
        #pragma unroll
        for (int c = 0; c < 8; c++)
            acc += x[(((size_t)b * Cn + c) * BINS_ + h) * W_ + (w0 + tx)] * wreg[c];
        tile[ty + r * 8][tx] = tfr(acc);
    }
    __syncthreads();
    #pragma unroll
    for (int r = 0; r < 4; r++) {
        int w = w0 + ty + r * 8;
        out[((size_t)b * W_ + w) * BINS_ + (h0 + tx)] = tile[tx][ty + r * 8];
    }
}

// ---------------- final transpose: out[b,h,w] = in[b,w,h] ----------------
__global__ void transpose_out_kernel(const float* __restrict__ in, float* __restrict__ out)
{
    __shared__ float tile[32][33];
    int b  = blockIdx.z;
    int w0 = blockIdx.x * 32, h0 = blockIdx.y * 32;
    int tx = threadIdx.x, ty = threadIdx.y;

    #pragma unroll
    for (int r = 0; r < 4; r++)
        tile[ty + r * 8][tx] = in[((size_t)b * W_ + (w0 + ty + r * 8)) * BINS_ + (h0 + tx)];
    __syncthreads();
    #pragma unroll
    for (int r = 0; r < 4; r++)
        out[((size_t)b * BINS_ + (h0 + ty + r * 8)) * W_ + (w0 + tx)] = tile[tx][ty + r * 8];
}

// ---------------- tf32 tensor-core GEMM, 64x64 warp tiles, 3-stage cp.async ----------------
// 128 threads = 4 warps in a 2(m) x 2(n) grid; CTA tile 128x128.
// All operands pre-rounded to tf32. BT=1: B is [N,K] (NT); BT=0: B is [K,N] (NN).
template <int BT>
__global__ void __launch_bounds__(128, 2)
tgemm_kernel(const float* __restrict__ A, int lda, long soA, long siA,
             const float* __restrict__ Bp, int ldb, long soB, long siB,
             const float* __restrict__ bias,
             float* __restrict__ C, int ldc, long soC, long siC,
             int K, int zdiv, int act, int rnd)
{
    extern __shared__ float smem[];

    int z = blockIdx.z;
    long zo = z / zdiv, zi = z % zdiv;
    A  += zo * soA + zi * siA;
    Bp += zo * soB + zi * siB;
    C  += zo * soC + zi * siC;

    int m0 = blockIdx.y * 128, n0 = blockIdx.x * 128;
    int tid  = threadIdx.x;
    int lane = tid & 31, wid = tid >> 5;
    int g = lane >> 2, tg = lane & 3;
    int wm = wid & 1, wn = wid >> 1;      // warp grid 2 (m) x 2 (n), 64x64 tiles

    float acc[4][8][4] = {};

    auto issue = [&](int k0, int s) {
        float* Sa = smem + s * STAGE_F;
        float* Sb = Sa + 4608;
        #pragma unroll
        for (int i = 0; i < 8; i++) {
            int idx = tid + i * 128;
            int r = idx >> 3, c = (idx & 7) << 2;
            cp16(Sa + r * 36 + c, A + (size_t)(m0 + r) * lda + k0 + c);
            if (BT) {
                cp16(Sb + r * 36 + c, Bp + (size_t)(n0 + r) * ldb + k0 + c);
            } else {
                int kr = idx >> 5, cn = (idx & 31) << 2;
                cp16(Sb + kr * 132 + cn, Bp + (size_t)(k0 + kr) * ldb + n0 + cn);
            }
        }
        cp_commit();
    };

    int nc = K >> 5;
    issue(0, 0);
    if (nc > 1) issue(32, 1);
    for (int ch = 0; ch < nc; ch++) {
        if (ch + 2 < nc) issue((ch + 2) << 5, (ch + 2) % NSTAGE);
        else             cp_commit();
        cp_wait2();
        __syncthreads();

        const unsigned* Ua = (const unsigned*)(smem + (ch % NSTAGE) * STAGE_F);
        const unsigned* Ub = Ua + 4608;
        #pragma unroll
        for (int kk = 0; kk < 32; kk += 8) {
            unsigned af[4][4];
            #pragma unroll
            for (int mt = 0; mt < 4; mt++) {
                int m = wm * 64 + mt * 16 + g;
                af[mt][0] = Ua[m * 36 + kk + tg];
                af[mt][1] = Ua[(m + 8) * 36 + kk + tg];
                af[mt][2] = Ua[m * 36 + kk + tg + 4];
                af[mt][3] = Ua[(m + 8) * 36 + kk + tg + 4];
            }
            unsigned bf[8][2];
            #pragma unroll
            for (int nt = 0; nt < 8; nt++) {
                int n = wn * 64 + nt * 8 + g;
                if (BT) {
                    bf[nt][0] = Ub[n * 36 + kk + tg];
                    bf[nt][1] = Ub[n * 36 + kk + tg + 4];
                } else {
                    bf[nt][0] = Ub[(kk + tg) * 132 + n];
                    bf[nt][1] = Ub[(kk + tg + 4) * 132 + n];
                }
            }
            #pragma unroll
            for (int mt = 0; mt < 4; mt++)
                #pragma unroll
                for (int nt = 0; nt < 8; nt++)
                    mma8(acc[mt][nt], af[mt], bf[nt]);
        }
        __syncthreads();
    }

    // epilogue
    #pragma unroll
    for (int mt = 0; mt < 4; mt++) {
        int r0 = m0 + wm * 64 + mt * 16 + g;
        #pragma unroll
        for (int nt = 0; nt < 8; nt++) {
            int c = n0 + wn * 64 + nt * 8 + tg * 2;
            float b0 = bias ? bias[c] : 0.f, b1 = bias ? bias[c + 1] : 0.f;
            float vv[4];
            vv[0] = apply_act(acc[mt][nt][0] + b0, act);
            vv[1] = apply_act(acc[mt][nt][1] + b1, act);
            vv[2] = apply_act(acc[mt][nt][2] + b0, act);
            vv[3] = apply_act(acc[mt][nt][3] + b1, act);
            if (rnd) {
                vv[0] = tfr(vv[0]); vv[1] = tfr(vv[1]);
                vv[2] = tfr(vv[2]); vv[3] = tfr(vv[3]);
            }
            *reinterpret_cast<float2*>(C + (size_t)r0 * ldc + c)       = make_float2(vv[0], vv[1]);
            *reinterpret_cast<float2*>(C + (size_t)(r0 + 8) * ldc + c) = make_float2(vv[2], vv[3]);
        }
    }
}

// ---------------- fused attention scores as a virtual K=512 pipelined GEMM ----------------
// s[i,j] = (sum_k Q[i,k]K[j,k]  +  sum_k er[k,i]Q[j,k]) / 32
// 128 threads, 64x64 warp tiles. chunks 0..7: Q/K (NT); chunks 8..15: er (NN) / Q (NT)
__global__ void __launch_bounds__(128, 2)
scores_kernel(const float* __restrict__ q, const float* __restrict__ kx,
              const float* __restrict__ er, float* __restrict__ s)
{
    extern __shared__ float smem[];

    int bh = blockIdx.z;
    int b = bh >> 2, h = bh & 3;
    const float* qb = q  + (size_t)b * W_ * BINS_ + h * DH_;
    const float* kb = kx + (size_t)b * W_ * BINS_ + h * DH_;
    float* sb = s + (size_t)bh * W_ * W_;

    int i0 = blockIdx.y * 128, j0 = blockIdx.x * 128;
    int tid  = threadIdx.x;
    int lane = tid & 31, wid = tid >> 5;
    int g = lane >> 2, tg = lane & 3;
    int wm = wid & 1, wn = wid >> 1;

    float acc[4][8][4] = {};

    auto issue = [&](int t) {
        float* Sa = smem + (t % NSTAGE) * STAGE_F;
        float* Sb = Sa + 4608;
        int k0 = (t & 7) << 5;
        #pragma unroll
        for (int i = 0; i < 8; i++) {
            int idx = tid + i * 128;
            int r = idx >> 3, c = (idx & 7) << 2;
            if (t < 8) {
                cp16(Sa + r * 36 + c, qb + (size_t)(i0 + r) * BINS_ + k0 + c);
                cp16(Sb + r * 36 + c, kb + (size_t)(j0 + r) * BINS_ + k0 + c);
            } else {
                int kr = idx >> 5, cn = (idx & 31) << 2;
                cp16(Sa + kr * 132 + cn, er + (size_t)(k0 + kr) * W_ + i0 + cn);
                cp16(Sb + r * 36 + c, qb + (size_t)(j0 + r) * BINS_ + k0 + c);
            }
        }
        cp_commit();
    };

    issue(0); issue(1);
    for (int t = 0; t < 16; t++) {
        if (t + 2 < 16) issue(t + 2);
        else            cp_commit();
        cp_wait2();
        __syncthreads();

        const unsigned* Ua = (const unsigned*)(smem + (t % NSTAGE) * STAGE_F);
        const unsigned* Ub = Ua + 4608;
        bool nnA = (t >= 8);
        #pragma unroll
        for (int kk = 0; kk < 32; kk += 8) {
            unsigned af[4][4];
            #pragma unroll
            for (int mt = 0; mt < 4; mt++) {
                int m = wm * 64 + mt * 16 + g;
                if (!nnA) {
                    af[mt][0] = Ua[m * 36 + kk + tg];
                    af[mt][1] = Ua[(m + 8) * 36 + kk + tg];
                    af[mt][2] = Ua[m * 36 + kk + tg + 4];
                    af[mt][3] = Ua[(m + 8) * 36 + kk + tg + 4];
                } else {
                    af[mt][0] = Ua[(kk + tg) * 132 + m];
                    af[mt][1] = Ua[(kk + tg) * 132 + m + 8];
                    af[mt][2] = Ua[(kk + tg + 4) * 132 + m];
                    af[mt][3] = Ua[(kk + tg + 4) * 132 + m + 8];
                }
            }
            unsigned bf[8][2];
            #pragma unroll
            for (int nt = 0; nt < 8; nt++) {
                int n = wn * 64 + nt * 8 + g;
                bf[nt][0] = Ub[n * 36 + kk + tg];
                bf[nt][1] = Ub[n * 36 + kk + tg + 4];
            }
            #pragma unroll
            for (int mt = 0; mt < 4; mt++)
                #pragma unroll
                for (int nt = 0; nt < 8; nt++)
                    mma8(acc[mt][nt], af[mt], bf[nt]);
        }
        __syncthreads();
    }

    #pragma unroll
    for (int mt = 0; mt < 4; mt++) {
        int r0 = i0 + wm * 64 + mt * 16 + g;
        #pragma unroll
        for (int nt = 0; nt < 8; nt++) {
            int c = j0 + wn * 64 + nt * 8 + tg * 2;
            float2 v0, v1;
            v0.x = acc[mt][nt][0] * 0.03125f;
            v0.y = acc[mt][nt][1] * 0.03125f;
            v1.x = acc[mt][nt][2] * 0.03125f;
            v1.y = acc[mt][nt][3] * 0.03125f;
            *reinterpret_cast<float2*>(sb + (size_t)r0 * W_ + c) = v0;
            *reinterpret_cast<float2*>(sb + (size_t)(r0 + 8) * W_ + c) = v1;
        }
    }
}

// ---------------- row softmax over n=1024 (output rounded to tf32) ----------------
__global__ void softmax_kernel(float* __restrict__ s)
{
    const int n = W_;
    float* row = s + (size_t)blockIdx.x * n;
    int tid = threadIdx.x;
    __shared__ float red[8];

    float m = -3.4e38f;
    for (int i = tid; i < n; i += 256) m = fmaxf(m, row[i]);
    #pragma unroll
    for (int o = 16; o; o >>= 1) m = fmaxf(m, __shfl_xor_sync(0xffffffffu, m, o));
    if ((tid & 31) == 0) red[tid >> 5] = m;
    __syncthreads();
    m = red[0];
    #pragma unroll
    for (int wi = 1; wi < 8; wi++) m = fmaxf(m, red[wi]);

    float sum = 0.f;
    for (int i = tid; i < n; i += 256) { float e = __expf(row[i] - m); row[i] = e; sum += e; }
    #pragma unroll
    for (int o = 16; o; o >>= 1) sum += __shfl_xor_sync(0xffffffffu, sum, o);
    __syncthreads();
    if ((tid & 31) == 0) red[tid >> 5] = sum;
    __syncthreads();
    float tot = 0.f;
    #pragma unroll
    for (int wi = 0; wi < 8; wi++) tot += red[wi];
    float inv = 1.f / tot;
    for (int i = tid; i < n; i += 256) row[i] = tfr(row[i] * inv);
}

// ---------------- fused (a*omega + b + c) -> LayerNorm ----------------
__global__ void ln_kernel(const float* __restrict__ a, const float* __restrict__ bsrc,
                          const float* __restrict__ csrc, const float* __restrict__ omega,
                          const float* __restrict__ g, const float* __restrict__ bet,
                          float* __restrict__ out, int R, int rnd)
{
    extern __shared__ float sm[];
    __shared__ float rs[8], rq[8];
    size_t base = (size_t)blockIdx.x * R;
    int tid = threadIdx.x;

    float s = 0.f, sq = 0.f;
    for (int i = tid; i < R; i += 256) {
        float v = a[base + i];
        if (omega) v *= omega[i];
        if (bsrc)  v += bsrc[base + i];
        if (csrc)  v += csrc[base + i];
        sm[i] = v; s += v; sq += v * v;
    }
    #pragma unroll
    for (int o = 16; o; o >>= 1) {
        s  += __shfl_xor_sync(0xffffffffu, s, o);
        sq += __shfl_xor_sync(0xffffffffu, sq, o);
    }
    if ((tid & 31) == 0) { rs[tid >> 5] = s; rq[tid >> 5] = sq; }
    __syncthreads();
    float ts = 0.f, tq = 0.f;
    #pragma unroll
    for (int wi = 0; wi < 8; wi++) { ts += rs[wi]; tq += rq[wi]; }
    float mean = ts / (float)R;
    float var  = tq / (float)R - mean * mean;
    float inv  = rsqrtf(var + 1e-5f);
    for (int i = tid; i < R; i += 256) {
        float v = (sm[i] - mean) * inv * g[i] + bet[i];
        out[base + i] = rnd ? tfr(v) : v;
    }
}

// ---------------- depthwise conv along w, layout [B, W, Ch] (output rounded) ----------------
__global__ void dwconv_kernel(const float* __restrict__ in, const float* __restrict__ wk,
                              float* __restrict__ out, int Ch, int Kt, int pad)
{
    int c = blockIdx.x * blockDim.x + threadIdx.x;
    int w = blockIdx.y, b = blockIdx.z;
    const float* ib = in + ((size_t)b * W_) * Ch;
    float acc = 0.f;
    for (int t = 0; t < Kt; t++) {
        int ww = w + t - pad;
        if (ww >= 0 && ww < W_) acc += ib[(size_t)ww * Ch + c] * wk[c * Kt + t];
    }
    out[((size_t)b * W_ + w) * Ch + c] = tfr(acc);
}

// ---------------- hL[:, :FFH] += hR ----------------
__global__ void add_pad_kernel(float* __restrict__ ffa, const float* __restrict__ ffb)
{
    size_t idx = (size_t)blockIdx.x * 256 + threadIdx.x;   // over B*W*FFH
    size_t row = idx / FFH_, f = idx % FFH_;
    ffa[row * FF2_ + f] += ffb[idx];
}

// =========================================================================
static void launch_tgemm(const float* A, int lda, long soA, long siA,
                         const float* Bp, int ldb, long soB, long siB,
                         const float* bias, float* C, int ldc, long soC, long siC,
                         int M, int N, int K, int nz, int zdiv, int BT, int act, int rnd)
{
    dim3 g(N / 128, M / 128, nz);
    if (BT)
        tgemm_kernel<1><<<g, 128, SMEM_BYTES>>>(A, lda, soA, siA, Bp, ldb, soB, siB, bias,
                                                C, ldc, soC, siC, K, zdiv, act, rnd);
    else
        tgemm_kernel<0><<<g, 128, SMEM_BYTES>>>(A, lda, soA, siA, Bp, ldb, soB, siB, bias,
                                                C, ldc, soC, siC, K, zdiv, act, rnd);
}

static void run_attn(const float* xin, const float* min_,
                     const float* w, const float* bias, const float* er,
                     float* q, float* k, float* v, float* att, float* scores,
                     float* outp)
{
    const long NK = (long)BINS_ * BINS_;
    const int M = B_ * W_;
    launch_tgemm(xin,  BINS_, 0, 0, w + 0 * NK, BINS_, 0, 0, bias + 0 * BINS_, q,   BINS_, 0, 0, M, BINS_, BINS_, 1, 1, 1, 0, 1);
    launch_tgemm(min_, BINS_, 0, 0, w + 1 * NK, BINS_, 0, 0, bias + 1 * BINS_, k,   BINS_, 0, 0, M, BINS_, BINS_, 1, 1, 1, 0, 1);
    launch_tgemm(min_, BINS_, 0, 0, w + 2 * NK, BINS_, 0, 0, bias + 2 * BINS_, v,   BINS_, 0, 0, M, BINS_, BINS_, 1, 1, 1, 0, 1);

    dim3 gs(W_ / 128, W_ / 128, B_ * H_);
    scores_kernel<<<gs, 128, SMEM_BYTES>>>(q, k, er, scores);
    softmax_kernel<<<B_ * H_ * W_, 256>>>(scores);

    // att[b, i, h*DH+d] = sum_j scores[b,h,i,j] * v[b, j, h*DH+d]   (batched NN)
    launch_tgemm(scores, W_, 4L * W_ * W_, (long)W_ * W_,
                 v, BINS_, (long)W_ * BINS_, DH_,
                 nullptr,
                 att, BINS_, (long)W_ * BINS_, DH_,
                 W_, DH_, W_, B_ * H_, H_, 0, 0, 1);

    launch_tgemm(att, BINS_, 0, 0, w + 3 * NK, BINS_, 0, 0, bias + 3 * BINS_, outp, BINS_, 0, 0, M, BINS_, BINS_, 1, 1, 1, 0, 0);
}

extern "C" void kernel_launch(void* const* d_in, const int* in_sizes, int n_in,
                              void* d_out, int out_size)
{
    (void)in_sizes; (void)n_in; (void)out_size;

    cudaFuncSetAttribute(tgemm_kernel<0>, cudaFuncAttributeMaxDynamicSharedMemorySize, SMEM_BYTES);
    cudaFuncSetAttribute(tgemm_kernel<1>, cudaFuncAttributeMaxDynamicSharedMemorySize, SMEM_BYTES);
    cudaFuncSetAttribute(scores_kernel,   cudaFuncAttributeMaxDynamicSharedMemorySize, SMEM_BYTES);

    const float* x      = (const float*)d_in[0];
    const float* mem    = (const float*)d_in[1];
    const float* in_w   = (const float*)d_in[2];
    const float* skip_w = (const float*)d_in[3];
    const float* attn_w = (const float*)d_in[4];
    const float* attn_b = (const float*)d_in[5];
    const float* er     = (const float*)d_in[6];
    const float* omega  = (const float*)d_in[7];
    const float* ln_g   = (const float*)d_in[8];
    const float* ln_b   = (const float*)d_in[9];
    const float* ln2_g  = (const float*)d_in[10];
    const float* ln2_b  = (const float*)d_in[11];
    const float* c1L_dw = (const float*)d_in[12];
    const float* c1L_pw = (const float*)d_in[13];
    const float* c1R_dw = (const float*)d_in[14];
    const float* c1R_pw = (const float*)d_in[15];
    const float* c2_dw  = (const float*)d_in[16];
    const float* c2_pw  = (const float*)d_in[17];
    const float* c3_w   = (const float*)d_in[18];
    const float* c4_w   = (const float*)d_in[19];

    float *p_xs, *p_ms, *p_q, *p_k, *p_v, *p_att, *p_hs, *p_hm, *p_t1, *p_t2;
    float *p_dwc, *p_ffb, *p_scores, *p_ffa, *p_dwf, *p_wr;
    cudaGetSymbolAddress((void**)&p_xs,  g_xs);
    cudaGetSymbolAddress((void**)&p_ms,  g_ms);
    cudaGetSymbolAddress((void**)&p_q,   g_q);
    cudaGetSymbolAddress((void**)&p_k,   g_k);
    cudaGetSymbolAddress((void**)&p_v,   g_v);
    cudaGetSymbolAddress((void**)&p_att, g_att);
    cudaGetSymbolAddress((void**)&p_hs,  g_hs);
    cudaGetSymbolAddress((void**)&p_hm,  g_hm);
    cudaGetSymbolAddress((void**)&p_t1,  g_t1);
    cudaGetSymbolAddress((void**)&p_t2,  g_t2);
    cudaGetSymbolAddress((void**)&p_dwc, g_dwc);
    cudaGetSymbolAddress((void**)&p_ffb, g_ffb);
    cudaGetSymbolAddress((void**)&p_scores, g_scores);
    cudaGetSymbolAddress((void**)&p_ffa, g_ffa);
    cudaGetSymbolAddress((void**)&p_dwf, g_dwf);
    cudaGetSymbolAddress((void**)&p_wr,  g_wr);

    // ---- round all GEMM weight operands to tf32, ONE launch ----
    round_all_kernel<<<(int)((8912896L + 255) / 256), 256>>>(
        (const float4*)attn_w, (const float4*)er, (const float4*)c1L_pw,
        (const float4*)c1R_pw, (const float4*)c2_pw, (const float4*)c3_w,
        (const float4*)c4_w, (float4*)p_wr);

    const float* aw_r  = p_wr + OFF_AW;
    const float* er_r  = p_wr + OFF_ER;
    const float* c1L_r = p_wr + OFF_C1L;
    const float* c1R_r = p_wr + OFF_C1R;
    const float* c2_r  = p_wr + OFF_C2;
    const float* c3_r  = p_wr + OFF_C3;
    const float* c4_r  = p_wr + OFF_C4;

    const int  M  = B_ * W_;
    const long ANK = 4L * BINS_ * BINS_;   // per-attention weight stride
    const long ERS = (long)DH_ * W_;

    // input / skip projections
    {
        dim3 g(W_ / 32, BINS_ / 32, B_), blk(32, 8);
        project_kernel<<<g, blk>>>(x,   in_w,   8, p_xs);
        project_kernel<<<g, blk>>>(mem, skip_w, 8, p_ms);
    }

    // self_attn1 / enc_attn1
    run_attn(p_xs, p_xs, aw_r + 0 * ANK, attn_b + 0 * 4 * BINS_, er_r + 0 * ERS,
             p_q, p_k, p_v, p_att, p_scores, p_hs);
    run_attn(p_xs, p_ms, aw_r + 1 * ANK, attn_b + 1 * 4 * BINS_, er_r + 1 * ERS,
             p_q, p_k, p_v, p_att, p_scores, p_hm);

    // x1 = LN(xs*omega0 + hs + hm)   (feeds dwconv only -> no round)
    ln_kernel<<<M, 256, BINS_ * 4>>>(p_xs, p_hs, p_hm, omega + 0 * BINS_,
                                     ln_g + 0 * BINS_, ln_b + 0 * BINS_, p_t1, BINS_, 0);

    // conv block
    dwconv_kernel<<<dim3(BINS_ / 256, W_, B_), 256>>>(p_t1, c1L_dw, p_dwc, BINS_, 11, 5);
    launch_tgemm(p_dwc, BINS_, 0, 0, c1L_r, BINS_, 0, 0, nullptr, p_ffa, FF2_, 0, 0,
                 M, FF2_, BINS_, 1, 1, 1, 1 /*lrelu*/, 0);
    dwconv_kernel<<<dim3(BINS_ / 256, W_, B_), 256>>>(p_t1, c1R_dw, p_dwc, BINS_, 7, 3);
    launch_tgemm(p_dwc, BINS_, 0, 0, c1R_r, BINS_, 0, 0, nullptr, p_ffb, FFH_, 0, 0,
                 M, FFH_, BINS_, 1, 1, 1, 0, 0);
    add_pad_kernel<<<(B_ * W_ * FFH_) / 256, 256>>>(p_ffa, p_ffb);
    ln_kernel<<<M, 256, FF2_ * 4>>>(p_ffa, nullptr, nullptr, nullptr, ln2_g, ln2_b, p_ffa, FF2_, 0);
    dwconv_kernel<<<dim3(FF2_ / 256, W_, B_), 256>>>(p_ffa, c2_dw, p_dwf, FF2_, 7, 3);
    launch_tgemm(p_dwf, FF2_, 0, 0, c2_r, FF2_, 0, 0, nullptr, p_hs, BINS_, 0, 0,
                 M, BINS_, FF2_, 1, 1, 1, 0, 0);

    // x2 = LN(x1*omega1 + h)  (feeds self_attn2 GEMM A -> round)
    ln_kernel<<<M, 256, BINS_ * 4>>>(p_t1, p_hs, nullptr, omega + 1 * BINS_,
                                     ln_g + 1 * BINS_, ln_b + 1 * BINS_, p_t2, BINS_, 1);

    // self_attn2 ; x3 = LN(x2*omega2 + h)  (feeds enc_attn2 -> round)
    run_attn(p_t2, p_t2, aw_r + 2 * ANK, attn_b + 2 * 4 * BINS_, er_r + 2 * ERS,
             p_q, p_k, p_v, p_att, p_scores, p_hs);
    ln_kernel<<<M, 256, BINS_ * 4>>>(p_t2, p_hs, nullptr, omega + 2 * BINS_,
                                     ln_g + 2 * BINS_, ln_b + 2 * BINS_, p_t1, BINS_, 1);

    // enc_attn2 ; x4 = LN(x3*omega3 + h)  (feeds c3 GEMM -> round)
    run_attn(p_t1, p_ms, aw_r + 3 * ANK, attn_b + 3 * 4 * BINS_, er_r + 3 * ERS,
             p_q, p_k, p_v, p_att, p_scores, p_hs);
    ln_kernel<<<M, 256, BINS_ * 4>>>(p_t1, p_hs, nullptr, omega + 3 * BINS_,
                                     ln_g + 3 * BINS_, ln_b + 3 * BINS_, p_t2, BINS_, 1);

    // FFN: silu(x4 @ c3^T) @ c4^T   (silu output feeds c4 GEMM -> round)
    launch_tgemm(p_t2, BINS_, 0, 0, c3_r, BINS_, 0, 0, nullptr, p_ffa, FF2_, 0, 0,
                 M, FF2_, BINS_, 1, 1, 1, 2 /*silu*/, 1);
    launch_tgemm(p_ffa, FF2_, 0, 0, c4_r, FF2_, 0, 0, nullptr, p_hs, BINS_, 0, 0,
                 M, BINS_, FF2_, 1, 1, 1, 0, 0);

    // out = LN(x4*omega4 + h) (final output -> NO round), then transpose to [B, BINS, W]
    ln_kernel<<<M, 256, BINS_ * 4>>>(p_t2, p_hs, nullptr, omega + 4 * BINS_,
                                     ln_g + 4 * BINS_, ln_b + 4 * BINS_, p_t1, BINS_, 0);
    {
        dim3 g(W_ / 32, BINS_ / 32, B_), blk(32, 8);
        transpose_out_kernel<<<g, blk>>>(p_t1, (float*)d_out);
    }
}

// round 12
// speedup vs baseline: 1.0502x; 1.0221x over previous
#include <cuda_runtime.h>
#include <math.h>

#define B_    4
#define W_    1024
#define BINS_ 1024
#define H_    4
#define DH_   256
#define FF2_  4096
#define FFH_  1024

// stage layout for pipelined GEMMs: A(4608 floats) + B(4608 floats) per stage, 3 stages
#define STAGE_F 9216
#define NSTAGE  3
#define SMEM_BYTES (NSTAGE * STAGE_F * 4)

// ---------------- scratch (static device memory; no allocations) ----------------
__device__ float g_xs [(size_t)B_*W_*BINS_];
__device__ float g_ms [(size_t)B_*W_*BINS_];
__device__ float g_q  [(size_t)B_*W_*BINS_];
__device__ float g_k  [(size_t)B_*W_*BINS_];
__device__ float g_v  [(size_t)B_*W_*BINS_];
__device__ float g_att[(size_t)B_*W_*BINS_];
__device__ float g_hs [(size_t)B_*W_*BINS_];
__device__ float g_hm [(size_t)B_*W_*BINS_];
__device__ float g_t1 [(size_t)B_*W_*BINS_];
__device__ float g_t2 [(size_t)B_*W_*BINS_];
__device__ float g_dwc[(size_t)B_*W_*BINS_];
__device__ float g_ffb[(size_t)B_*W_*FFH_];
__device__ float g_scores[(size_t)B_*H_*W_*W_];
__device__ float g_ffa[(size_t)B_*W_*FF2_];
__device__ float g_dwf[(size_t)B_*W_*FF2_];

// rounded weights: attn_w | er | c1L_pw | c1R_pw | c2_pw | c3_w | c4_w
#define OFF_AW   0L
#define OFF_ER   16777216L
#define OFF_C1L  17825792L
#define OFF_C1R  22020096L
#define OFF_C2   23068672L
#define OFF_C3   27262976L
#define OFF_C4   31457280L
#define WR_TOTAL 35651584L
__device__ float g_wr[WR_TOTAL];

// ---------------- helpers ----------------
__device__ __forceinline__ unsigned f2tf(float f) {
    unsigned r;
    asm("cvt.rna.tf32.f32 %0, %1;" : "=r"(r) : "f"(f));
    return r;
}
__device__ __forceinline__ float tfr(float f) { return __uint_as_float(f2tf(f)); }

__device__ __forceinline__ void mma8(float* d, const unsigned* a, const unsigned* b) {
    asm("mma.sync.aligned.m16n8k8.row.col.f32.tf32.tf32.f32 "
        "{%0,%1,%2,%3},{%4,%5,%6,%7},{%8,%9},{%0,%1,%2,%3};"
        : "+f"(d[0]), "+f"(d[1]), "+f"(d[2]), "+f"(d[3])
        : "r"(a[0]), "r"(a[1]), "r"(a[2]), "r"(a[3]), "r"(b[0]), "r"(b[1]));
}

__device__ __forceinline__ void cp16(float* smem_dst, const float* gsrc) {
    unsigned d = (unsigned)__cvta_generic_to_shared(smem_dst);
    asm volatile("cp.async.cg.shared.global [%0], [%1], 16;" :: "r"(d), "l"(gsrc));
}
__device__ __forceinline__ void cp_commit() { asm volatile("cp.async.commit_group;"); }
__device__ __forceinline__ void cp_wait2()  { asm volatile("cp.async.wait_group 2;"); }

__device__ __forceinline__ float apply_act(float v, int act) {
    if (act == 1) return (v >= 0.f) ? v : 0.01f * v;
    if (act == 2) return v / (1.f + __expf(-v));
    return v;
}

// ---------------- tf32 rounding copy of ALL weight operands in ONE launch ----------------
__global__ void round_all_kernel(const float4* __restrict__ s0, const float4* __restrict__ s1,
                                 const float4* __restrict__ s2, const float4* __restrict__ s3,
                                 const float4* __restrict__ s4, const float4* __restrict__ s5,
                                 const float4* __restrict__ s6, float4* __restrict__ out)
{
    long i = (long)blockIdx.x * 256 + threadIdx.x;
    if (i >= 8912896L) return;
    const float4* src;
    long rel = i;
    if      (i < 4194304L) { src = s0; rel = i; }
    else if (i < 4456448L) { src = s1; rel = i - 4194304L; }
    else if (i < 5505024L) { src = s2; rel = i - 4456448L; }
    else if (i < 5767168L) { src = s3; rel = i - 5505024L; }
    else if (i < 6815744L) { src = s4; rel = i - 5767168L; }
    else if (i < 7864320L) { src = s5; rel = i - 6815744L; }
    else                   { src = s6; rel = i - 7864320L; }
    float4 v = src[rel];
    v.x = tfr(v.x); v.y = tfr(v.y); v.z = tfr(v.z); v.w = tfr(v.w);
    out[i] = v;
}

// ---------------- input projection: out[b,w,h] = sum_c x[b,c,h,w] * wc[c] ----------------
__global__ void project_kernel(const float* __restrict__ x, const float* __restrict__ wc,
                               int Cn, float* __restrict__ out)
{
    __shared__ float tile[32][33];
    int b  = blockIdx.z;
    int h0 = blockIdx.y * 32, w0 = blockIdx.x * 32;
    int tx = threadIdx.x, ty = threadIdx.y;   // 32 x 8

    float wreg[8];
    #pragma unroll
    for (int c = 0; c < 8; c++) wreg[c] = (c < Cn) ? wc[c] : 0.f;

    #pragma unroll
    for (int r = 0; r < 4; r++) {
        int h = h0 + ty + r * 8;
        float acc = 0.f;
        #pragma unroll
        for (int c = 0; c < 8; c++)
            acc += x[(((size_t)b * Cn + c) * BINS_ + h) * W_ + (w0 + tx)] * wreg[c];
        tile[ty + r * 8][tx] = tfr(acc);
    }
    __syncthreads();
    #pragma unroll
    for (int r = 0; r < 4; r++) {
        int w = w0 + ty + r * 8;
        out[((size_t)b * W_ + w) * BINS_ + (h0 + tx)] = tile[tx][ty + r * 8];
    }
}

// ---------------- final transpose: out[b,h,w] = in[b,w,h] ----------------
__global__ void transpose_out_kernel(const float* __restrict__ in, float* __restrict__ out)
{
    __shared__ float tile[32][33];
    int b  = blockIdx.z;
    int w0 = blockIdx.x * 32, h0 = blockIdx.y * 32;
    int tx = threadIdx.x, ty = threadIdx.y;

    #pragma unroll
    for (int r = 0; r < 4; r++)
        tile[ty + r * 8][tx] = in[((size_t)b * W_ + (w0 + ty + r * 8)) * BINS_ + (h0 + tx)];
    __syncthreads();
    #pragma unroll
    for (int r = 0; r < 4; r++)
        out[((size_t)b * BINS_ + (h0 + ty + r * 8)) * W_ + (w0 + tx)] = tile[tx][ty + r * 8];
}

// ---------------- tf32 tensor-core GEMM, 64x64 warp tiles, 3-stage cp.async ----------------
// 128 threads = 4 warps in a 2(m) x 2(n) grid; CTA tile 128x128.
// Fragments are double-buffered across kk-steps so LDS of step kk+1 overlaps mma of kk.
// All operands pre-rounded to tf32. BT=1: B is [N,K] (NT); BT=0: B is [K,N] (NN).
template <int BT>
__global__ void __launch_bounds__(128, 2)
tgemm_kernel(const float* __restrict__ A, int lda, long soA, long siA,
             const float* __restrict__ Bp, int ldb, long soB, long siB,
             const float* __restrict__ bias,
             float* __restrict__ C, int ldc, long soC, long siC,
             int K, int zdiv, int act, int rnd)
{
    extern __shared__ float smem[];

    int z = blockIdx.z;
    long zo = z / zdiv, zi = z % zdiv;
    A  += zo * soA + zi * siA;
    Bp += zo * soB + zi * siB;
    C  += zo * soC + zi * siC;

    int m0 = blockIdx.y * 128, n0 = blockIdx.x * 128;
    int tid  = threadIdx.x;
    int lane = tid & 31, wid = tid >> 5;
    int g = lane >> 2, tg = lane & 3;
    int wm = wid & 1, wn = wid >> 1;      // warp grid 2 (m) x 2 (n), 64x64 tiles

    float acc[4][8][4] = {};

    auto issue = [&](int k0, int s) {
        float* Sa = smem + s * STAGE_F;
        float* Sb = Sa + 4608;
        #pragma unroll
        for (int i = 0; i < 8; i++) {
            int idx = tid + i * 128;
            int r = idx >> 3, c = (idx & 7) << 2;
            cp16(Sa + r * 36 + c, A + (size_t)(m0 + r) * lda + k0 + c);
            if (BT) {
                cp16(Sb + r * 36 + c, Bp + (size_t)(n0 + r) * ldb + k0 + c);
            } else {
                int kr = idx >> 5, cn = (idx & 31) << 2;
                cp16(Sb + kr * 132 + cn, Bp + (size_t)(k0 + kr) * ldb + n0 + cn);
            }
        }
        cp_commit();
    };

    int nc = K >> 5;
    issue(0, 0);
    if (nc > 1) issue(32, 1);
    for (int ch = 0; ch < nc; ch++) {
        if (ch + 2 < nc) issue((ch + 2) << 5, (ch + 2) % NSTAGE);
        else             cp_commit();
        cp_wait2();
        __syncthreads();

        const unsigned* Ua = (const unsigned*)(smem + (ch % NSTAGE) * STAGE_F);
        const unsigned* Ub = Ua + 4608;

        unsigned af[2][4][4], bf[2][8][2];
        auto ldf = [&](int kk, int bi) {
            #pragma unroll
            for (int mt = 0; mt < 4; mt++) {
                int m = wm * 64 + mt * 16 + g;
                af[bi][mt][0] = Ua[m * 36 + kk + tg];
                af[bi][mt][1] = Ua[(m + 8) * 36 + kk + tg];
                af[bi][mt][2] = Ua[m * 36 + kk + tg + 4];
                af[bi][mt][3] = Ua[(m + 8) * 36 + kk + tg + 4];
            }
            #pragma unroll
            for (int nt = 0; nt < 8; nt++) {
                int n = wn * 64 + nt * 8 + g;
                if (BT) {
                    bf[bi][nt][0] = Ub[n * 36 + kk + tg];
                    bf[bi][nt][1] = Ub[n * 36 + kk + tg + 4];
                } else {
                    bf[bi][nt][0] = Ub[(kk + tg) * 132 + n];
                    bf[bi][nt][1] = Ub[(kk + tg + 4) * 132 + n];
                }
            }
        };

        ldf(0, 0);
        #pragma unroll
        for (int kk8 = 0; kk8 < 4; kk8++) {
            if (kk8 < 3) ldf((kk8 + 1) * 8, (kk8 + 1) & 1);
            #pragma unroll
            for (int mt = 0; mt < 4; mt++)
                #pragma unroll
                for (int nt = 0; nt < 8; nt++)
                    mma8(acc[mt][nt], af[kk8 & 1][mt], bf[kk8 & 1][nt]);
        }
        __syncthreads();
    }

    // epilogue
    #pragma unroll
    for (int mt = 0; mt < 4; mt++) {
        int r0 = m0 + wm * 64 + mt * 16 + g;
        #pragma unroll
        for (int nt = 0; nt < 8; nt++) {
            int c = n0 + wn * 64 + nt * 8 + tg * 2;
            float b0 = bias ? bias[c] : 0.f, b1 = bias ? bias[c + 1] : 0.f;
            float vv[4];
            vv[0] = apply_act(acc[mt][nt][0] + b0, act);
            vv[1] = apply_act(acc[mt][nt][1] + b1, act);
            vv[2] = apply_act(acc[mt][nt][2] + b0, act);
            vv[3] = apply_act(acc[mt][nt][3] + b1, act);
            if (rnd) {
                vv[0] = tfr(vv[0]); vv[1] = tfr(vv[1]);
                vv[2] = tfr(vv[2]); vv[3] = tfr(vv[3]);
            }
            *reinterpret_cast<float2*>(C + (size_t)r0 * ldc + c)       = make_float2(vv[0], vv[1]);
            *reinterpret_cast<float2*>(C + (size_t)(r0 + 8) * ldc + c) = make_float2(vv[2], vv[3]);
        }
    }
}

// ---------------- fused attention scores as a virtual K=512 pipelined GEMM ----------------
// s[i,j] = (sum_k Q[i,k]K[j,k]  +  sum_k er[k,i]Q[j,k]) / 32
// 128 threads, 64x64 warp tiles, fragment double-buffering.
// chunks 0..7: Q/K (NT); chunks 8..15: er (NN) / Q (NT)
__global__ void __launch_bounds__(128, 2)
scores_kernel(const float* __restrict__ q, const float* __restrict__ kx,
              const float* __restrict__ er, float* __restrict__ s)
{
    extern __shared__ float smem[];

    int bh = blockIdx.z;
    int b = bh >> 2, h = bh & 3;
    const float* qb = q  + (size_t)b * W_ * BINS_ + h * DH_;
    const float* kb = kx + (size_t)b * W_ * BINS_ + h * DH_;
    float* sb = s + (size_t)bh * W_ * W_;

    int i0 = blockIdx.y * 128, j0 = blockIdx.x * 128;
    int tid  = threadIdx.x;
    int lane = tid & 31, wid = tid >> 5;
    int g = lane >> 2, tg = lane & 3;
    int wm = wid & 1, wn = wid >> 1;

    float acc[4][8][4] = {};

    auto issue = [&](int t) {
        float* Sa = smem + (t % NSTAGE) * STAGE_F;
        float* Sb = Sa + 4608;
        int k0 = (t & 7) << 5;
        #pragma unroll
        for (int i = 0; i < 8; i++) {
            int idx = tid + i * 128;
            int r = idx >> 3, c = (idx & 7) << 2;
            if (t < 8) {
                cp16(Sa + r * 36 + c, qb + (size_t)(i0 + r) * BINS_ + k0 + c);
                cp16(Sb + r * 36 + c, kb + (size_t)(j0 + r) * BINS_ + k0 + c);
            } else {
                int kr = idx >> 5, cn = (idx & 31) << 2;
                cp16(Sa + kr * 132 + cn, er + (size_t)(k0 + kr) * W_ + i0 + cn);
                cp16(Sb + r * 36 + c, qb + (size_t)(j0 + r) * BINS_ + k0 + c);
            }
        }
        cp_commit();
    };

    issue(0); issue(1);
    for (int t = 0; t < 16; t++) {
        if (t + 2 < 16) issue(t + 2);
        else            cp_commit();
        cp_wait2();
        __syncthreads();

        const unsigned* Ua = (const unsigned*)(smem + (t % NSTAGE) * STAGE_F);
        const unsigned* Ub = Ua + 4608;
        bool nnA = (t >= 8);

        unsigned af[2][4][4], bf[2][8][2];
        auto ldf = [&](int kk, int bi) {
            #pragma unroll
            for (int mt = 0; mt < 4; mt++) {
                int m = wm * 64 + mt * 16 + g;
                if (!nnA) {
                    af[bi][mt][0] = Ua[m * 36 + kk + tg];
                    af[bi][mt][1] = Ua[(m + 8) * 36 + kk + tg];
                    af[bi][mt][2] = Ua[m * 36 + kk + tg + 4];
                    af[bi][mt][3] = Ua[(m + 8) * 36 + kk + tg + 4];
                } else {
                    af[bi][mt][0] = Ua[(kk + tg) * 132 + m];
                    af[bi][mt][1] = Ua[(kk + tg) * 132 + m + 8];
                    af[bi][mt][2] = Ua[(kk + tg + 4) * 132 + m];
                    af[bi][mt][3] = Ua[(kk + tg + 4) * 132 + m + 8];
                }
            }
            #pragma unroll
            for (int nt = 0; nt < 8; nt++) {
                int n = wn * 64 + nt * 8 + g;
                bf[bi][nt][0] = Ub[n * 36 + kk + tg];
                bf[bi][nt][1] = Ub[n * 36 + kk + tg + 4];
            }
        };

        ldf(0, 0);
        #pragma unroll
        for (int kk8 = 0; kk8 < 4; kk8++) {
            if (kk8 < 3) ldf((kk8 + 1) * 8, (kk8 + 1) & 1);
            #pragma unroll
            for (int mt = 0; mt < 4; mt++)
                #pragma unroll
                for (int nt = 0; nt < 8; nt++)
                    mma8(acc[mt][nt], af[kk8 & 1][mt], bf[kk8 & 1][nt]);
        }
        __syncthreads();
    }

    #pragma unroll
    for (int mt = 0; mt < 4; mt++) {
        int r0 = i0 + wm * 64 + mt * 16 + g;
        #pragma unroll
        for (int nt = 0; nt < 8; nt++) {
            int c = j0 + wn * 64 + nt * 8 + tg * 2;
            float2 v0, v1;
            v0.x = acc[mt][nt][0] * 0.03125f;
            v0.y = acc[mt][nt][1] * 0.03125f;
            v1.x = acc[mt][nt][2] * 0.03125f;
            v1.y = acc[mt][nt][3] * 0.03125f;
            *reinterpret_cast<float2*>(sb + (size_t)r0 * W_ + c) = v0;
            *reinterpret_cast<float2*>(sb + (size_t)(r0 + 8) * W_ + c) = v1;
        }
    }
}

// ---------------- row softmax over n=1024 (output rounded to tf32) ----------------
__global__ void softmax_kernel(float* __restrict__ s)
{
    const int n = W_;
    float* row = s + (size_t)blockIdx.x * n;
    int tid = threadIdx.x;
    __shared__ float red[8];

    float m = -3.4e38f;
    for (int i = tid; i < n; i += 256) m = fmaxf(m, row[i]);
    #pragma unroll
    for (int o = 16; o; o >>= 1) m = fmaxf(m, __shfl_xor_sync(0xffffffffu, m, o));
    if ((tid & 31) == 0) red[tid >> 5] = m;
    __syncthreads();
    m = red[0];
    #pragma unroll
    for (int wi = 1; wi < 8; wi++) m = fmaxf(m, red[wi]);

    float sum = 0.f;
    for (int i = tid; i < n; i += 256) { float e = __expf(row[i] - m); row[i] = e; sum += e; }
    #pragma unroll
    for (int o = 16; o; o >>= 1) sum += __shfl_xor_sync(0xffffffffu, sum, o);
    __syncthreads();
    if ((tid & 31) == 0) red[tid >> 5] = sum;
    __syncthreads();
    float tot = 0.f;
    #pragma unroll
    for (int wi = 0; wi < 8; wi++) tot += red[wi];
    float inv = 1.f / tot;
    for (int i = tid; i < n; i += 256) row[i] = tfr(row[i] * inv);
}

// ---------------- fused (a*omega + b + c) -> LayerNorm ----------------
__global__ void ln_kernel(const float* __restrict__ a, const float* __restrict__ bsrc,
                          const float* __restrict__ csrc, const float* __restrict__ omega,
                          const float* __restrict__ g, const float* __restrict__ bet,
                          float* __restrict__ out, int R, int rnd)
{
    extern __shared__ float sm[];
    __shared__ float rs[8], rq[8];
    size_t base = (size_t)blockIdx.x * R;
    int tid = threadIdx.x;

    float s = 0.f, sq = 0.f;
    for (int i = tid; i < R; i += 256) {
        float v = a[base + i];
        if (omega) v *= omega[i];
        if (bsrc)  v += bsrc[base + i];
        if (csrc)  v += csrc[base + i];
        sm[i] = v; s += v; sq += v * v;
    }
    #pragma unroll
    for (int o = 16; o; o >>= 1) {
        s  += __shfl_xor_sync(0xffffffffu, s, o);
        sq += __shfl_xor_sync(0xffffffffu, sq, o);
    }
    if ((tid & 31) == 0) { rs[tid >> 5] = s; rq[tid >> 5] = sq; }
    __syncthreads();
    float ts = 0.f, tq = 0.f;
    #pragma unroll
    for (int wi = 0; wi < 8; wi++) { ts += rs[wi]; tq += rq[wi]; }
    float mean = ts / (float)R;
    float var  = tq / (float)R - mean * mean;
    float inv  = rsqrtf(var + 1e-5f);
    for (int i = tid; i < R; i += 256) {
        float v = (sm[i] - mean) * inv * g[i] + bet[i];
        out[base + i] = rnd ? tfr(v) : v;
    }
}

// ---------------- depthwise conv along w, layout [B, W, Ch] (output rounded) ----------------
__global__ void dwconv_kernel(const float* __restrict__ in, const float* __restrict__ wk,
                              float* __restrict__ out, int Ch, int Kt, int pad)
{
    int c = blockIdx.x * blockDim.x + threadIdx.x;
    int w = blockIdx.y, b = blockIdx.z;
    const float* ib = in + ((size_t)b * W_) * Ch;
    float acc = 0.f;
    for (int t = 0; t < Kt; t++) {
        int ww = w + t - pad;
        if (ww >= 0 && ww < W_) acc += ib[(size_t)ww * Ch + c] * wk[c * Kt + t];
    }
    out[((size_t)b * W_ + w) * Ch + c] = tfr(acc);
}

// ---------------- hL[:, :FFH] += hR ----------------
__global__ void add_pad_kernel(float* __restrict__ ffa, const float* __restrict__ ffb)
{
    size_t idx = (size_t)blockIdx.x * 256 + threadIdx.x;   // over B*W*FFH
    size_t row = idx / FFH_, f = idx % FFH_;
    ffa[row * FF2_ + f] += ffb[idx];
}

// =========================================================================
static void launch_tgemm(const float* A, int lda, long soA, long siA,
                         const float* Bp, int ldb, long soB, long siB,
                         const float* bias, float* C, int ldc, long soC, long siC,
                         int M, int N, int K, int nz, int zdiv, int BT, int act, int rnd)
{
    dim3 g(N / 128, M / 128, nz);
    if (BT)
        tgemm_kernel<1><<<g, 128, SMEM_BYTES>>>(A, lda, soA, siA, Bp, ldb, soB, siB, bias,
                                                C, ldc, soC, siC, K, zdiv, act, rnd);
    else
        tgemm_kernel<0><<<g, 128, SMEM_BYTES>>>(A, lda, soA, siA, Bp, ldb, soB, siB, bias,
                                                C, ldc, soC, siC, K, zdiv, act, rnd);
}

static void run_attn(const float* xin, const float* min_,
                     const float* w, const float* bias, const float* er,
                     float* q, float* k, float* v, float* att, float* scores,
                     float* outp)
{
    const long NK = (long)BINS_ * BINS_;
    const int M = B_ * W_;
    launch_tgemm(xin,  BINS_, 0, 0, w + 0 * NK, BINS_, 0, 0, bias + 0 * BINS_, q,   BINS_, 0, 0, M, BINS_, BINS_, 1, 1, 1, 0, 1);
    launch_tgemm(min_, BINS_, 0, 0, w + 1 * NK, BINS_, 0, 0, bias + 1 * BINS_, k,   BINS_, 0, 0, M, BINS_, BINS_, 1, 1, 1, 0, 1);
    launch_tgemm(min_, BINS_, 0, 0, w + 2 * NK, BINS_, 0, 0, bias + 2 * BINS_, v,   BINS_, 0, 0, M, BINS_, BINS_, 1, 1, 1, 0, 1);

    dim3 gs(W_ / 128, W_ / 128, B_ * H_);
    scores_kernel<<<gs, 128, SMEM_BYTES>>>(q, k, er, scores);
    softmax_kernel<<<B_ * H_ * W_, 256>>>(scores);

    // att[b, i, h*DH+d] = sum_j scores[b,h,i,j] * v[b, j, h*DH+d]   (batched NN)
    launch_tgemm(scores, W_, 4L * W_ * W_, (long)W_ * W_,
                 v, BINS_, (long)W_ * BINS_, DH_,
                 nullptr,
                 att, BINS_, (long)W_ * BINS_, DH_,
                 W_, DH_, W_, B_ * H_, H_, 0, 0, 1);

    launch_tgemm(att, BINS_, 0, 0, w + 3 * NK, BINS_, 0, 0, bias + 3 * BINS_, outp, BINS_, 0, 0, M, BINS_, BINS_, 1, 1, 1, 0, 0);
}

extern "C" void kernel_launch(void* const* d_in, const int* in_sizes, int n_in,
                              void* d_out, int out_size)
{
    (void)in_sizes; (void)n_in; (void)out_size;

    cudaFuncSetAttribute(tgemm_kernel<0>, cudaFuncAttributeMaxDynamicSharedMemorySize, SMEM_BYTES);
    cudaFuncSetAttribute(tgemm_kernel<1>, cudaFuncAttributeMaxDynamicSharedMemorySize, SMEM_BYTES);
    cudaFuncSetAttribute(scores_kernel,   cudaFuncAttributeMaxDynamicSharedMemorySize, SMEM_BYTES);

    const float* x      = (const float*)d_in[0];
    const float* mem    = (const float*)d_in[1];
    const float* in_w   = (const float*)d_in[2];
    const float* skip_w = (const float*)d_in[3];
    const float* attn_w = (const float*)d_in[4];
    const float* attn_b = (const float*)d_in[5];
    const float* er     = (const float*)d_in[6];
    const float* omega  = (const float*)d_in[7];
    const float* ln_g   = (const float*)d_in[8];
    const float* ln_b   = (const float*)d_in[9];
    const float* ln2_g  = (const float*)d_in[10];
    const float* ln2_b  = (const float*)d_in[11];
    const float* c1L_dw = (const float*)d_in[12];
    const float* c1L_pw = (const float*)d_in[13];
    const float* c1R_dw = (const float*)d_in[14];
    const float* c1R_pw = (const float*)d_in[15];
    const float* c2_dw  = (const float*)d_in[16];
    const float* c2_pw  = (const float*)d_in[17];
    const float* c3_w   = (const float*)d_in[18];
    const float* c4_w   = (const float*)d_in[19];

    float *p_xs, *p_ms, *p_q, *p_k, *p_v, *p_att, *p_hs, *p_hm, *p_t1, *p_t2;
    float *p_dwc, *p_ffb, *p_scores, *p_ffa, *p_dwf, *p_wr;
    cudaGetSymbolAddress((void**)&p_xs,  g_xs);
    cudaGetSymbolAddress((void**)&p_ms,  g_ms);
    cudaGetSymbolAddress((void**)&p_q,   g_q);
    cudaGetSymbolAddress((void**)&p_k,   g_k);
    cudaGetSymbolAddress((void**)&p_v,   g_v);
    cudaGetSymbolAddress((void**)&p_att, g_att);
    cudaGetSymbolAddress((void**)&p_hs,  g_hs);
    cudaGetSymbolAddress((void**)&p_hm,  g_hm);
    cudaGetSymbolAddress((void**)&p_t1,  g_t1);
    cudaGetSymbolAddress((void**)&p_t2,  g_t2);
    cudaGetSymbolAddress((void**)&p_dwc, g_dwc);
    cudaGetSymbolAddress((void**)&p_ffb, g_ffb);
    cudaGetSymbolAddress((void**)&p_scores, g_scores);
    cudaGetSymbolAddress((void**)&p_ffa, g_ffa);
    cudaGetSymbolAddress((void**)&p_dwf, g_dwf);
    cudaGetSymbolAddress((void**)&p_wr,  g_wr);

    // ---- round all GEMM weight operands to tf32, ONE launch ----
    round_all_kernel<<<(int)((8912896L + 255) / 256), 256>>>(
        (const float4*)attn_w, (const float4*)er, (const float4*)c1L_pw,
        (const float4*)c1R_pw, (const float4*)c2_pw, (const float4*)c3_w,
        (const float4*)c4_w, (float4*)p_wr);

    const float* aw_r  = p_wr + OFF_AW;
    const float* er_r  = p_wr + OFF_ER;
    const float* c1L_r = p_wr + OFF_C1L;
    const float* c1R_r = p_wr + OFF_C1R;
    const float* c2_r  = p_wr + OFF_C2;
    const float* c3_r  = p_wr + OFF_C3;
    const float* c4_r  = p_wr + OFF_C4;

    const int  M  = B_ * W_;
    const long ANK = 4L * BINS_ * BINS_;   // per-attention weight stride
    const long ERS = (long)DH_ * W_;

    // input / skip projections
    {
        dim3 g(W_ / 32, BINS_ / 32, B_), blk(32, 8);
        project_kernel<<<g, blk>>>(x,   in_w,   8, p_xs);
        project_kernel<<<g, blk>>>(mem, skip_w, 8, p_ms);
    }

    // self_attn1 / enc_attn1
    run_attn(p_xs, p_xs, aw_r + 0 * ANK, attn_b + 0 * 4 * BINS_, er_r + 0 * ERS,
             p_q, p_k, p_v, p_att, p_scores, p_hs);
    run_attn(p_xs, p_ms, aw_r + 1 * ANK, attn_b + 1 * 4 * BINS_, er_r + 1 * ERS,
             p_q, p_k, p_v, p_att, p_scores, p_hm);

    // x1 = LN(xs*omega0 + hs + hm)   (feeds dwconv only -> no round)
    ln_kernel<<<M, 256, BINS_ * 4>>>(p_xs, p_hs, p_hm, omega + 0 * BINS_,
                                     ln_g + 0 * BINS_, ln_b + 0 * BINS_, p_t1, BINS_, 0);

    // conv block
    dwconv_kernel<<<dim3(BINS_ / 256, W_, B_), 256>>>(p_t1, c1L_dw, p_dwc, BINS_, 11, 5);
    launch_tgemm(p_dwc, BINS_, 0, 0, c1L_r, BINS_, 0, 0, nullptr, p_ffa, FF2_, 0, 0,
                 M, FF2_, BINS_, 1, 1, 1, 1 /*lrelu*/, 0);
    dwconv_kernel<<<dim3(BINS_ / 256, W_, B_), 256>>>(p_t1, c1R_dw, p_dwc, BINS_, 7, 3);
    launch_tgemm(p_dwc, BINS_, 0, 0, c1R_r, BINS_, 0, 0, nullptr, p_ffb, FFH_, 0, 0,
                 M, FFH_, BINS_, 1, 1, 1, 0, 0);
    add_pad_kernel<<<(B_ * W_ * FFH_) / 256, 256>>>(p_ffa, p_ffb);
    ln_kernel<<<M, 256, FF2_ * 4>>>(p_ffa, nullptr, nullptr, nullptr, ln2_g, ln2_b, p_ffa, FF2_, 0);
    dwconv_kernel<<<dim3(FF2_ / 256, W_, B_), 256>>>(p_ffa, c2_dw, p_dwf, FF2_, 7, 3);
    launch_tgemm(p_dwf, FF2_, 0, 0, c2_r, FF2_, 0, 0, nullptr, p_hs, BINS_, 0, 0,
                 M, BINS_, FF2_, 1, 1, 1, 0, 0);

    // x2 = LN(x1*omega1 + h)  (feeds self_attn2 GEMM A -> round)
    ln_kernel<<<M, 256, BINS_ * 4>>>(p_t1, p_hs, nullptr, omega + 1 * BINS_,
                                     ln_g + 1 * BINS_, ln_b + 1 * BINS_, p_t2, BINS_, 1);

    // self_attn2 ; x3 = LN(x2*omega2 + h)  (feeds enc_attn2 -> round)
    run_attn(p_t2, p_t2, aw_r + 2 * ANK, attn_b + 2 * 4 * BINS_, er_r + 2 * ERS,
             p_q, p_k, p_v, p_att, p_scores, p_hs);
    ln_kernel<<<M, 256, BINS_ * 4>>>(p_t2, p_hs, nullptr, omega + 2 * BINS_,
                                     ln_g + 2 * BINS_, ln_b + 2 * BINS_, p_t1, BINS_, 1);

    // enc_attn2 ; x4 = LN(x3*omega3 + h)  (feeds c3 GEMM -> round)
    run_attn(p_t1, p_ms, aw_r + 3 * ANK, attn_b + 3 * 4 * BINS_, er_r + 3 * ERS,
             p_q, p_k, p_v, p_att, p_scores, p_hs);
    ln_kernel<<<M, 256, BINS_ * 4>>>(p_t1, p_hs, nullptr, omega + 3 * BINS_,
                                     ln_g + 3 * BINS_, ln_b + 3 * BINS_, p_t2, BINS_, 1);

    // FFN: silu(x4 @ c3^T) @ c4^T   (silu output feeds c4 GEMM -> round)
    launch_tgemm(p_t2, BINS_, 0, 0, c3_r, BINS_, 0, 0, nullptr, p_ffa, FF2_, 0, 0,
                 M, FF2_, BINS_, 1, 1, 1, 2 /*silu*/, 1);
    launch_tgemm(p_ffa, FF2_, 0, 0, c4_r, FF2_, 0, 0, nullptr, p_hs, BINS_, 0, 0,
                 M, BINS_, FF2_, 1, 1, 1, 0, 0);

    // out = LN(x4*omega4 + h) (final output -> NO round), then transpose to [B, BINS, W]
    ln_kernel<<<M, 256, BINS_ * 4>>>(p_t2, p_hs, nullptr, omega + 4 * BINS_,
                                     ln_g + 4 * BINS_, ln_b + 4 * BINS_, p_t1, BINS_, 0);
    {
        dim3 g(W_ / 32, BINS_ / 32, B_), blk(32, 8);
        transpose_out_kernel<<<g, blk>>>(p_t1, (float*)d_out);
    }
}

// round 13
// speedup vs baseline: 1.0871x; 1.0351x over previous
#include <cuda_runtime.h>
#include <math.h>

#define B_    4
#define W_    1024
#define BINS_ 1024
#define H_    4
#define DH_   256
#define FF2_  4096
#define FFH_  1024
#define QKV_  (3 * BINS_)

// stage layout for pipelined GEMMs: A(4608 floats) + B(4608 floats) per stage, 3 stages
#define STAGE_F 9216
#define NSTAGE  3
#define SMEM_BYTES (NSTAGE * STAGE_F * 4)

// ---------------- scratch (static device memory; no allocations) ----------------
__device__ float g_xs  [(size_t)B_*W_*BINS_];
__device__ float g_ms  [(size_t)B_*W_*BINS_];
__device__ float g_qkv [(size_t)B_*W_*QKV_];
__device__ float g_qkv2[(size_t)B_*W_*QKV_];
__device__ float g_att [(size_t)B_*W_*BINS_];
__device__ float g_att2[(size_t)B_*W_*BINS_];
__device__ float g_hs  [(size_t)B_*W_*BINS_];
__device__ float g_hm  [(size_t)B_*W_*BINS_];
__device__ float g_t1  [(size_t)B_*W_*BINS_];
__device__ float g_t2  [(size_t)B_*W_*BINS_];
__device__ float g_dwc [(size_t)B_*W_*BINS_];
__device__ float g_dwc2[(size_t)B_*W_*BINS_];
__device__ float g_ffb [(size_t)B_*W_*FFH_];
__device__ float g_scores [(size_t)B_*H_*W_*W_];
__device__ float g_scores2[(size_t)B_*H_*W_*W_];
__device__ float g_ffa [(size_t)B_*W_*FF2_];
__device__ float g_dwf [(size_t)B_*W_*FF2_];

// rounded weights: attn_w | er | c1L_pw | c1R_pw | c2_pw | c3_w | c4_w
#define OFF_AW   0L
#define OFF_ER   16777216L
#define OFF_C1L  17825792L
#define OFF_C1R  22020096L
#define OFF_C2   23068672L
#define OFF_C3   27262976L
#define OFF_C4   31457280L
#define WR_TOTAL 35651584L
__device__ float g_wr[WR_TOTAL];

// ---------------- helpers ----------------
__device__ __forceinline__ unsigned f2tf(float f) {
    unsigned r;
    asm("cvt.rna.tf32.f32 %0, %1;" : "=r"(r) : "f"(f));
    return r;
}
__device__ __forceinline__ float tfr(float f) { return __uint_as_float(f2tf(f)); }

__device__ __forceinline__ void mma8(float* d, const unsigned* a, const unsigned* b) {
    asm("mma.sync.aligned.m16n8k8.row.col.f32.tf32.tf32.f32 "
        "{%0,%1,%2,%3},{%4,%5,%6,%7},{%8,%9},{%0,%1,%2,%3};"
        : "+f"(d[0]), "+f"(d[1]), "+f"(d[2]), "+f"(d[3])
        : "r"(a[0]), "r"(a[1]), "r"(a[2]), "r"(a[3]), "r"(b[0]), "r"(b[1]));
}

__device__ __forceinline__ void cp16(float* smem_dst, const float* gsrc) {
    unsigned d = (unsigned)__cvta_generic_to_shared(smem_dst);
    asm volatile("cp.async.cg.shared.global [%0], [%1], 16;" :: "r"(d), "l"(gsrc));
}
__device__ __forceinline__ void cp_commit() { asm volatile("cp.async.commit_group;"); }
__device__ __forceinline__ void cp_wait2()  { asm volatile("cp.async.wait_group 2;"); }

__device__ __forceinline__ float apply_act(float v, int act) {
    if (act == 1) return (v >= 0.f) ? v : 0.01f * v;
    if (act == 2) return v / (1.f + __expf(-v));
    return v;
}

// ---------------- tf32 rounding copy of ALL weight operands in ONE launch ----------------
__global__ void round_all_kernel(const float4* __restrict__ s0, const float4* __restrict__ s1,
                                 const float4* __restrict__ s2, const float4* __restrict__ s3,
                                 const float4* __restrict__ s4, const float4* __restrict__ s5,
                                 const float4* __restrict__ s6, float4* __restrict__ out)
{
    long i = (long)blockIdx.x * 256 + threadIdx.x;
    if (i >= 8912896L) return;
    const float4* src;
    long rel = i;
    if      (i < 4194304L) { src = s0; rel = i; }
    else if (i < 4456448L) { src = s1; rel = i - 4194304L; }
    else if (i < 5505024L) { src = s2; rel = i - 4456448L; }
    else if (i < 5767168L) { src = s3; rel = i - 5505024L; }
    else if (i < 6815744L) { src = s4; rel = i - 5767168L; }
    else if (i < 7864320L) { src = s5; rel = i - 6815744L; }
    else                   { src = s6; rel = i - 7864320L; }
    float4 v = src[rel];
    v.x = tfr(v.x); v.y = tfr(v.y); v.z = tfr(v.z); v.w = tfr(v.w);
    out[i] = v;
}

// ---------------- input projection: out[b,w,h] = sum_c x[b,c,h,w] * wc[c] ----------------
__global__ void project_kernel(const float* __restrict__ x, const float* __restrict__ wc,
                               int Cn, float* __restrict__ out)
{
    __shared__ float tile[32][33];
    int b  = blockIdx.z;
    int h0 = blockIdx.y * 32, w0 = blockIdx.x * 32;
    int tx = threadIdx.x, ty = threadIdx.y;   // 32 x 8

    float wreg[8];
    #pragma unroll
    for (int c = 0; c < 8; c++) wreg[c] = (c < Cn) ? wc[c] : 0.f;

    #pragma unroll
    for (int r = 0; r < 4; r++) {
        int h = h0 + ty + r * 8;
        float acc = 0.f;
        #pragma unroll
        for (int c = 0; c < 8; c++)
            acc += x[(((size_t)b * Cn + c) * BINS_ + h) * W_ + (w0 + tx)] * wreg[c];
        tile[ty + r * 8][tx] = tfr(acc);
    }
    __syncthreads();
    #pragma unroll
    for (int r = 0; r < 4; r++) {
        int w = w0 + ty + r * 8;
        out[((size_t)b * W_ + w) * BINS_ + (h0 + tx)] = tile[tx][ty + r * 8];
    }
}

// ---------------- final transpose: out[b,h,w] = in[b,w,h] ----------------
__global__ void transpose_out_kernel(const float* __restrict__ in, float* __restrict__ out)
{
    __shared__ float tile[32][33];
    int b  = blockIdx.z;
    int w0 = blockIdx.x * 32, h0 = blockIdx.y * 32;
    int tx = threadIdx.x, ty = threadIdx.y;

    #pragma unroll
    for (int r = 0; r < 4; r++)
        tile[ty + r * 8][tx] = in[((size_t)b * W_ + (w0 + ty + r * 8)) * BINS_ + (h0 + tx)];
    __syncthreads();
    #pragma unroll
    for (int r = 0; r < 4; r++)
        out[((size_t)b * BINS_ + (h0 + ty + r * 8)) * W_ + (w0 + tx)] = tile[tx][ty + r * 8];
}

// ---------------- tf32 tensor-core GEMM, 64x64 warp tiles, 3-stage cp.async ----------------
// 128 threads = 4 warps in a 2(m) x 2(n) grid; CTA tile 128x128.
// All operands pre-rounded to tf32. BT=1: B is [N,K] (NT); BT=0: B is [K,N] (NN).
template <int BT>
__global__ void __launch_bounds__(128, 2)
tgemm_kernel(const float* __restrict__ A, int lda, long soA, long siA,
             const float* __restrict__ Bp, int ldb, long soB, long siB,
             const float* __restrict__ bias,
             float* __restrict__ C, int ldc, long soC, long siC,
             int K, int zdiv, int act, int rnd)
{
    extern __shared__ float smem[];

    int z = blockIdx.z;
    long zo = z / zdiv, zi = z % zdiv;
    A  += zo * soA + zi * siA;
    Bp += zo * soB + zi * siB;
    C  += zo * soC + zi * siC;

    int m0 = blockIdx.y * 128, n0 = blockIdx.x * 128;
    int tid  = threadIdx.x;
    int lane = tid & 31, wid = tid >> 5;
    int g = lane >> 2, tg = lane & 3;
    int wm = wid & 1, wn = wid >> 1;      // warp grid 2 (m) x 2 (n), 64x64 tiles

    float acc[4][8][4] = {};

    auto issue = [&](int k0, int s) {
        float* Sa = smem + s * STAGE_F;
        float* Sb = Sa + 4608;
        #pragma unroll
        for (int i = 0; i < 8; i++) {
            int idx = tid + i * 128;
            int r = idx >> 3, c = (idx & 7) << 2;
            cp16(Sa + r * 36 + c, A + (size_t)(m0 + r) * lda + k0 + c);
            if (BT) {
                cp16(Sb + r * 36 + c, Bp + (size_t)(n0 + r) * ldb + k0 + c);
            } else {
                int kr = idx >> 5, cn = (idx & 31) << 2;
                cp16(Sb + kr * 132 + cn, Bp + (size_t)(k0 + kr) * ldb + n0 + cn);
            }
        }
        cp_commit();
    };

    int nc = K >> 5;
    issue(0, 0);
    if (nc > 1) issue(32, 1);
    for (int ch = 0; ch < nc; ch++) {
        if (ch + 2 < nc) issue((ch + 2) << 5, (ch + 2) % NSTAGE);
        else             cp_commit();
        cp_wait2();
        __syncthreads();

        const unsigned* Ua = (const unsigned*)(smem + (ch % NSTAGE) * STAGE_F);
        const unsigned* Ub = Ua + 4608;

        unsigned af[2][4][4], bf[2][8][2];
        auto ldf = [&](int kk, int bi) {
            #pragma unroll
            for (int mt = 0; mt < 4; mt++) {
                int m = wm * 64 + mt * 16 + g;
                af[bi][mt][0] = Ua[m * 36 + kk + tg];
                af[bi][mt][1] = Ua[(m + 8) * 36 + kk + tg];
                af[bi][mt][2] = Ua[m * 36 + kk + tg + 4];
                af[bi][mt][3] = Ua[(m + 8) * 36 + kk + tg + 4];
            }
            #pragma unroll
            for (int nt = 0; nt < 8; nt++) {
                int n = wn * 64 + nt * 8 + g;
                if (BT) {
                    bf[bi][nt][0] = Ub[n * 36 + kk + tg];
                    bf[bi][nt][1] = Ub[n * 36 + kk + tg + 4];
                } else {
                    bf[bi][nt][0] = Ub[(kk + tg) * 132 + n];
                    bf[bi][nt][1] = Ub[(kk + tg + 4) * 132 + n];
                }
            }
        };

        ldf(0, 0);
        #pragma unroll
        for (int kk8 = 0; kk8 < 4; kk8++) {
            if (kk8 < 3) ldf((kk8 + 1) * 8, (kk8 + 1) & 1);
            #pragma unroll
            for (int mt = 0; mt < 4; mt++)
                #pragma unroll
                for (int nt = 0; nt < 8; nt++)
                    mma8(acc[mt][nt], af[kk8 & 1][mt], bf[kk8 & 1][nt]);
        }
        __syncthreads();
    }

    // epilogue
    #pragma unroll
    for (int mt = 0; mt < 4; mt++) {
        int r0 = m0 + wm * 64 + mt * 16 + g;
        #pragma unroll
        for (int nt = 0; nt < 8; nt++) {
            int c = n0 + wn * 64 + nt * 8 + tg * 2;
            float b0 = bias ? bias[c] : 0.f, b1 = bias ? bias[c + 1] : 0.f;
            float vv[4];
            vv[0] = apply_act(acc[mt][nt][0] + b0, act);
            vv[1] = apply_act(acc[mt][nt][1] + b1, act);
            vv[2] = apply_act(acc[mt][nt][2] + b0, act);
            vv[3] = apply_act(acc[mt][nt][3] + b1, act);
            if (rnd) {
                vv[0] = tfr(vv[0]); vv[1] = tfr(vv[1]);
                vv[2] = tfr(vv[2]); vv[3] = tfr(vv[3]);
            }
            *reinterpret_cast<float2*>(C + (size_t)r0 * ldc + c)       = make_float2(vv[0], vv[1]);
            *reinterpret_cast<float2*>(C + (size_t)(r0 + 8) * ldc + c) = make_float2(vv[2], vv[3]);
        }
    }
}

// ---------------- fused attention scores as a virtual K=512 pipelined GEMM ----------------
// s[i,j] = (sum_k Q[i,k]K[j,k]  +  sum_k er[k,i]Q[j,k]) / 32
// Q/K given by base pointers + runtime row strides (packed-QKV friendly).
__global__ void __launch_bounds__(128, 2)
scores_kernel(const float* __restrict__ q, int ldq,
              const float* __restrict__ kx, int ldk,
              const float* __restrict__ er, float* __restrict__ s)
{
    extern __shared__ float smem[];

    int bh = blockIdx.z;
    int b = bh >> 2, h = bh & 3;
    const float* qb = q  + (size_t)b * W_ * ldq + h * DH_;
    const float* kb = kx + (size_t)b * W_ * ldk + h * DH_;
    float* sb = s + (size_t)bh * W_ * W_;

    int i0 = blockIdx.y * 128, j0 = blockIdx.x * 128;
    int tid  = threadIdx.x;
    int lane = tid & 31, wid = tid >> 5;
    int g = lane >> 2, tg = lane & 3;
    int wm = wid & 1, wn = wid >> 1;

    float acc[4][8][4] = {};

    auto issue = [&](int t) {
        float* Sa = smem + (t % NSTAGE) * STAGE_F;
        float* Sb = Sa + 4608;
        int k0 = (t & 7) << 5;
        #pragma unroll
        for (int i = 0; i < 8; i++) {
            int idx = tid + i * 128;
            int r = idx >> 3, c = (idx & 7) << 2;
            if (t < 8) {
                cp16(Sa + r * 36 + c, qb + (size_t)(i0 + r) * ldq + k0 + c);
                cp16(Sb + r * 36 + c, kb + (size_t)(j0 + r) * ldk + k0 + c);
            } else {
                int kr = idx >> 5, cn = (idx & 31) << 2;
                cp16(Sa + kr * 132 + cn, er + (size_t)(k0 + kr) * W_ + i0 + cn);
                cp16(Sb + r * 36 + c, qb + (size_t)(j0 + r) * ldq + k0 + c);
            }
        }
        cp_commit();
    };

    issue(0); issue(1);
    for (int t = 0; t < 16; t++) {
        if (t + 2 < 16) issue(t + 2);
        else            cp_commit();
        cp_wait2();
        __syncthreads();

        const unsigned* Ua = (const unsigned*)(smem + (t % NSTAGE) * STAGE_F);
        const unsigned* Ub = Ua + 4608;
        bool nnA = (t >= 8);

        unsigned af[2][4][4], bf[2][8][2];
        auto ldf = [&](int kk, int bi) {
            #pragma unroll
            for (int mt = 0; mt < 4; mt++) {
                int m = wm * 64 + mt * 16 + g;
                if (!nnA) {
                    af[bi][mt][0] = Ua[m * 36 + kk + tg];
                    af[bi][mt][1] = Ua[(m + 8) * 36 + kk + tg];
                    af[bi][mt][2] = Ua[m * 36 + kk + tg + 4];
                    af[bi][mt][3] = Ua[(m + 8) * 36 + kk + tg + 4];
                } else {
                    af[bi][mt][0] = Ua[(kk + tg) * 132 + m];
                    af[bi][mt][1] = Ua[(kk + tg) * 132 + m + 8];
                    af[bi][mt][2] = Ua[(kk + tg + 4) * 132 + m];
                    af[bi][mt][3] = Ua[(kk + tg + 4) * 132 + m + 8];
                }
            }
            #pragma unroll
            for (int nt = 0; nt < 8; nt++) {
                int n = wn * 64 + nt * 8 + g;
                bf[bi][nt][0] = Ub[n * 36 + kk + tg];
                bf[bi][nt][1] = Ub[n * 36 + kk + tg + 4];
            }
        };

        ldf(0, 0);
        #pragma unroll
        for (int kk8 = 0; kk8 < 4; kk8++) {
            if (kk8 < 3) ldf((kk8 + 1) * 8, (kk8 + 1) & 1);
            #pragma unroll
            for (int mt = 0; mt < 4; mt++)
                #pragma unroll
                for (int nt = 0; nt < 8; nt++)
                    mma8(acc[mt][nt], af[kk8 & 1][mt], bf[kk8 & 1][nt]);
        }
        __syncthreads();
    }

    #pragma unroll
    for (int mt = 0; mt < 4; mt++) {
        int r0 = i0 + wm * 64 + mt * 16 + g;
        #pragma unroll
        for (int nt = 0; nt < 8; nt++) {
            int c = j0 + wn * 64 + nt * 8 + tg * 2;
            float2 v0, v1;
            v0.x = acc[mt][nt][0] * 0.03125f;
            v0.y = acc[mt][nt][1] * 0.03125f;
            v1.x = acc[mt][nt][2] * 0.03125f;
            v1.y = acc[mt][nt][3] * 0.03125f;
            *reinterpret_cast<float2*>(sb + (size_t)r0 * W_ + c) = v0;
            *reinterpret_cast<float2*>(sb + (size_t)(r0 + 8) * W_ + c) = v1;
        }
    }
}

// ---------------- row softmax over n=1024 (output rounded to tf32) ----------------
__global__ void softmax_kernel(float* __restrict__ s)
{
    const int n = W_;
    float* row = s + (size_t)blockIdx.x * n;
    int tid = threadIdx.x;
    __shared__ float red[8];

    float m = -3.4e38f;
    for (int i = tid; i < n; i += 256) m = fmaxf(m, row[i]);
    #pragma unroll
    for (int o = 16; o; o >>= 1) m = fmaxf(m, __shfl_xor_sync(0xffffffffu, m, o));
    if ((tid & 31) == 0) red[tid >> 5] = m;
    __syncthreads();
    m = red[0];
    #pragma unroll
    for (int wi = 1; wi < 8; wi++) m = fmaxf(m, red[wi]);

    float sum = 0.f;
    for (int i = tid; i < n; i += 256) { float e = __expf(row[i] - m); row[i] = e; sum += e; }
    #pragma unroll
    for (int o = 16; o; o >>= 1) sum += __shfl_xor_sync(0xffffffffu, sum, o);
    __syncthreads();
    if ((tid & 31) == 0) red[tid >> 5] = sum;
    __syncthreads();
    float tot = 0.f;
    #pragma unroll
    for (int wi = 0; wi < 8; wi++) tot += red[wi];
    float inv = 1.f / tot;
    for (int i = tid; i < n; i += 256) row[i] = tfr(row[i] * inv);
}

// ---------------- fused (a*omega + b + c) -> LayerNorm ----------------
__global__ void ln_kernel(const float* __restrict__ a, const float* __restrict__ bsrc,
                          const float* __restrict__ csrc, const float* __restrict__ omega,
                          const float* __restrict__ g, const float* __restrict__ bet,
                          float* __restrict__ out, int R, int rnd)
{
    extern __shared__ float sm[];
    __shared__ float rs[8], rq[8];
    size_t base = (size_t)blockIdx.x * R;
    int tid = threadIdx.x;

    float s = 0.f, sq = 0.f;
    for (int i = tid; i < R; i += 256) {
        float v = a[base + i];
        if (omega) v *= omega[i];
        if (bsrc)  v += bsrc[base + i];
        if (csrc)  v += csrc[base + i];
        sm[i] = v; s += v; sq += v * v;
    }
    #pragma unroll
    for (int o = 16; o; o >>= 1) {
        s  += __shfl_xor_sync(0xffffffffu, s, o);
        sq += __shfl_xor_sync(0xffffffffu, sq, o);
    }
    if ((tid & 31) == 0) { rs[tid >> 5] = s; rq[tid >> 5] = sq; }
    __syncthreads();
    float ts = 0.f, tq = 0.f;
    #pragma unroll
    for (int wi = 0; wi < 8; wi++) { ts += rs[wi]; tq += rq[wi]; }
    float mean = ts / (float)R;
    float var  = tq / (float)R - mean * mean;
    float inv  = rsqrtf(var + 1e-5f);
    for (int i = tid; i < R; i += 256) {
        float v = (sm[i] - mean) * inv * g[i] + bet[i];
        out[base + i] = rnd ? tfr(v) : v;
    }
}

// ---------------- depthwise conv along w, layout [B, W, Ch] (output rounded) ----------------
__global__ void dwconv_kernel(const float* __restrict__ in, const float* __restrict__ wk,
                              float* __restrict__ out, int Ch, int Kt, int pad)
{
    int c = blockIdx.x * blockDim.x + threadIdx.x;
    int w = blockIdx.y, b = blockIdx.z;
    const float* ib = in + ((size_t)b * W_) * Ch;
    float acc = 0.f;
    for (int t = 0; t < Kt; t++) {
        int ww = w + t - pad;
        if (ww >= 0 && ww < W_) acc += ib[(size_t)ww * Ch + c] * wk[c * Kt + t];
    }
    out[((size_t)b * W_ + w) * Ch + c] = tfr(acc);
}

// ---------------- hL[:, :FFH] += hR ----------------
__global__ void add_pad_kernel(float* __restrict__ ffa, const float* __restrict__ ffb)
{
    size_t idx = (size_t)blockIdx.x * 256 + threadIdx.x;   // over B*W*FFH
    size_t row = idx / FFH_, f = idx % FFH_;
    ffa[row * FF2_ + f] += ffb[idx];
}

// =========================================================================
static void launch_tgemm(const float* A, int lda, long soA, long siA,
                         const float* Bp, int ldb, long soB, long siB,
                         const float* bias, float* C, int ldc, long soC, long siC,
                         int M, int N, int K, int nz, int zdiv, int BT, int act, int rnd,
                         cudaStream_t st)
{
    dim3 g(N / 128, M / 128, nz);
    if (BT)
        tgemm_kernel<1><<<g, 128, SMEM_BYTES, st>>>(A, lda, soA, siA, Bp, ldb, soB, siB, bias,
                                                    C, ldc, soC, siC, K, zdiv, act, rnd);
    else
        tgemm_kernel<0><<<g, 128, SMEM_BYTES, st>>>(A, lda, soA, siA, Bp, ldb, soB, siB, bias,
                                                    C, ldc, soC, siC, K, zdiv, act, rnd);
}

// Fused-QKV attention block. qkv layout: [B*W, 3072] = Q|K|V.
static void run_attn(const float* xin, const float* min_, int self_,
                     const float* w, const float* bias, const float* er,
                     float* qkv, float* att, float* scores, float* outp,
                     int rnd_out, cudaStream_t st)
{
    const long NK = (long)BINS_ * BINS_;
    const int  M  = B_ * W_;
    if (self_) {
        launch_tgemm(xin, BINS_, 0, 0, w, BINS_, 0, 0, bias,
                     qkv, QKV_, 0, 0, M, QKV_, BINS_, 1, 1, 1, 0, 1, st);
    } else {
        launch_tgemm(xin, BINS_, 0, 0, w, BINS_, 0, 0, bias,
                     qkv, QKV_, 0, 0, M, BINS_, BINS_, 1, 1, 1, 0, 1, st);
        launch_tgemm(min_, BINS_, 0, 0, w + NK, BINS_, 0, 0, bias + BINS_,
                     qkv + BINS_, QKV_, 0, 0, M, 2 * BINS_, BINS_, 1, 1, 1, 0, 1, st);
    }

    dim3 gs(W_ / 128, W_ / 128, B_ * H_);
    scores_kernel<<<gs, 128, SMEM_BYTES, st>>>(qkv, QKV_, qkv + BINS_, QKV_, er, scores);
    softmax_kernel<<<B_ * H_ * W_, 256, 0, st>>>(scores);

    // att[b, i, h*DH+d] = sum_j scores[b,h,i,j] * V[b, j, h*DH+d]   (batched NN vs packed V)
    launch_tgemm(scores, W_, 4L * W_ * W_, (long)W_ * W_,
                 qkv + 2 * BINS_, QKV_, (long)W_ * QKV_, DH_,
                 nullptr,
                 att, BINS_, (long)W_ * BINS_, DH_,
                 W_, DH_, W_, B_ * H_, H_, 0, 0, 1, st);

    launch_tgemm(att, BINS_, 0, 0, w + 3 * NK, BINS_, 0, 0, bias + 3 * BINS_,
                 outp, BINS_, 0, 0, M, BINS_, BINS_, 1, 1, 1, 0, rnd_out, st);
}

extern "C" void kernel_launch(void* const* d_in, const int* in_sizes, int n_in,
                              void* d_out, int out_size)
{
    (void)in_sizes; (void)n_in; (void)out_size;

    cudaFuncSetAttribute(tgemm_kernel<0>, cudaFuncAttributeMaxDynamicSharedMemorySize, SMEM_BYTES);
    cudaFuncSetAttribute(tgemm_kernel<1>, cudaFuncAttributeMaxDynamicSharedMemorySize, SMEM_BYTES);
    cudaFuncSetAttribute(scores_kernel,   cudaFuncAttributeMaxDynamicSharedMemorySize, SMEM_BYTES);

    // Side stream + fork/join events (created once on the first, uncaptured, call).
    static cudaStream_t s2 = nullptr;
    static cudaEvent_t  ev0 = nullptr, ev1 = nullptr, ev2 = nullptr, ev3 = nullptr;
    if (!s2) {
        cudaStreamCreateWithFlags(&s2, cudaStreamNonBlocking);
        cudaEventCreateWithFlags(&ev0, cudaEventDisableTiming);
        cudaEventCreateWithFlags(&ev1, cudaEventDisableTiming);
        cudaEventCreateWithFlags(&ev2, cudaEventDisableTiming);
        cudaEventCreateWithFlags(&ev3, cudaEventDisableTiming);
    }

    const float* x      = (const float*)d_in[0];
    const float* mem    = (const float*)d_in[1];
    const float* in_w   = (const float*)d_in[2];
    const float* skip_w = (const float*)d_in[3];
    const float* attn_w = (const float*)d_in[4];
    const float* attn_b = (const float*)d_in[5];
    const float* er     = (const float*)d_in[6];
    const float* omega  = (const float*)d_in[7];
    const float* ln_g   = (const float*)d_in[8];
    const float* ln_b   = (const float*)d_in[9];
    const float* ln2_g  = (const float*)d_in[10];
    const float* ln2_b  = (const float*)d_in[11];
    const float* c1L_dw = (const float*)d_in[12];
    const float* c1L_pw = (const float*)d_in[13];
    const float* c1R_dw = (const float*)d_in[14];
    const float* c1R_pw = (const float*)d_in[15];
    const float* c2_dw  = (const float*)d_in[16];
    const float* c2_pw  = (const float*)d_in[17];
    const float* c3_w   = (const float*)d_in[18];
    const float* c4_w   = (const float*)d_in[19];

    float *p_xs, *p_ms, *p_qkv, *p_qkv2, *p_att, *p_att2, *p_hs, *p_hm, *p_t1, *p_t2;
    float *p_dwc, *p_dwc2, *p_ffb, *p_scores, *p_scores2, *p_ffa, *p_dwf, *p_wr;
    cudaGetSymbolAddress((void**)&p_xs,   g_xs);
    cudaGetSymbolAddress((void**)&p_ms,   g_ms);
    cudaGetSymbolAddress((void**)&p_qkv,  g_qkv);
    cudaGetSymbolAddress((void**)&p_qkv2, g_qkv2);
    cudaGetSymbolAddress((void**)&p_att,  g_att);
    cudaGetSymbolAddress((void**)&p_att2, g_att2);
    cudaGetSymbolAddress((void**)&p_hs,   g_hs);
    cudaGetSymbolAddress((void**)&p_hm,   g_hm);
    cudaGetSymbolAddress((void**)&p_t1,   g_t1);
    cudaGetSymbolAddress((void**)&p_t2,   g_t2);
    cudaGetSymbolAddress((void**)&p_dwc,  g_dwc);
    cudaGetSymbolAddress((void**)&p_dwc2, g_dwc2);
    cudaGetSymbolAddress((void**)&p_ffb,  g_ffb);
    cudaGetSymbolAddress((void**)&p_scores,  g_scores);
    cudaGetSymbolAddress((void**)&p_scores2, g_scores2);
    cudaGetSymbolAddress((void**)&p_ffa,  g_ffa);
    cudaGetSymbolAddress((void**)&p_dwf,  g_dwf);
    cudaGetSymbolAddress((void**)&p_wr,   g_wr);

    // ---- round all GEMM weight operands to tf32, ONE launch ----
    round_all_kernel<<<(int)((8912896L + 255) / 256), 256>>>(
        (const float4*)attn_w, (const float4*)er, (const float4*)c1L_pw,
        (const float4*)c1R_pw, (const float4*)c2_pw, (const float4*)c3_w,
        (const float4*)c4_w, (float4*)p_wr);

    const float* aw_r  = p_wr + OFF_AW;
    const float* er_r  = p_wr + OFF_ER;
    const float* c1L_r = p_wr + OFF_C1L;
    const float* c1R_r = p_wr + OFF_C1R;
    const float* c2_r  = p_wr + OFF_C2;
    const float* c3_r  = p_wr + OFF_C3;
    const float* c4_r  = p_wr + OFF_C4;

    const int  M  = B_ * W_;
    const long ANK = 4L * BINS_ * BINS_;   // per-attention weight stride
    const long ERS = (long)DH_ * W_;

    // input / skip projections
    {
        dim3 g(W_ / 32, BINS_ / 32, B_), blk(32, 8);
        project_kernel<<<g, blk>>>(x,   in_w,   8, p_xs);
        project_kernel<<<g, blk>>>(mem, skip_w, 8, p_ms);
    }

    // self_attn1 (stream 0)  ||  enc_attn1 (stream s2), independent scratch sets
    cudaEventRecord(ev0, 0);
    cudaStreamWaitEvent(s2, ev0, 0);
    run_attn(p_xs, p_xs, 1, aw_r + 0 * ANK, attn_b + 0 * 4 * BINS_, er_r + 0 * ERS,
             p_qkv, p_att, p_scores, p_hs, 0, 0);
    run_attn(p_xs, p_ms, 0, aw_r + 1 * ANK, attn_b + 1 * 4 * BINS_, er_r + 1 * ERS,
             p_qkv2, p_att2, p_scores2, p_hm, 0, s2);
    cudaEventRecord(ev1, s2);
    cudaStreamWaitEvent(0, ev1, 0);

    // x1 = LN(xs*omega0 + hs + hm)   (feeds dwconv only -> no round)
    ln_kernel<<<M, 256, BINS_ * 4>>>(p_xs, p_hs, p_hm, omega + 0 * BINS_,
                                     ln_g + 0 * BINS_, ln_b + 0 * BINS_, p_t1, BINS_, 0);

    // conv block: c1L chain (stream 0) || c1R chain (s2)
    cudaEventRecord(ev2, 0);
    cudaStreamWaitEvent(s2, ev2, 0);
    dwconv_kernel<<<dim3(BINS_ / 256, W_, B_), 256>>>(p_t1, c1L_dw, p_dwc, BINS_, 11, 5);
    launch_tgemm(p_dwc, BINS_, 0, 0, c1L_r, BINS_, 0, 0, nullptr, p_ffa, FF2_, 0, 0,
                 M, FF2_, BINS_, 1, 1, 1, 1 /*lrelu*/, 0, 0);
    dwconv_kernel<<<dim3(BINS_ / 256, W_, B_), 256, 0, s2>>>(p_t1, c1R_dw, p_dwc2, BINS_, 7, 3);
    launch_tgemm(p_dwc2, BINS_, 0, 0, c1R_r, BINS_, 0, 0, nullptr, p_ffb, FFH_, 0, 0,
                 M, FFH_, BINS_, 1, 1, 1, 0, 0, s2);
    cudaEventRecord(ev3, s2);
    cudaStreamWaitEvent(0, ev3, 0);

    add_pad_kernel<<<(B_ * W_ * FFH_) / 256, 256>>>(p_ffa, p_ffb);
    ln_kernel<<<M, 256, FF2_ * 4>>>(p_ffa, nullptr, nullptr, nullptr, ln2_g, ln2_b, p_ffa, FF2_, 0);
    dwconv_kernel<<<dim3(FF2_ / 256, W_, B_), 256>>>(p_ffa, c2_dw, p_dwf, FF2_, 7, 3);
    launch_tgemm(p_dwf, FF2_, 0, 0, c2_r, FF2_, 0, 0, nullptr, p_hs, BINS_, 0, 0,
                 M, BINS_, FF2_, 1, 1, 1, 0, 0, 0);

    // x2 = LN(x1*omega1 + h)  (feeds self_attn2 GEMM A -> round)
    ln_kernel<<<M, 256, BINS_ * 4>>>(p_t1, p_hs, nullptr, omega + 1 * BINS_,
                                     ln_g + 1 * BINS_, ln_b + 1 * BINS_, p_t2, BINS_, 1);

    // self_attn2 ; x3 = LN(x2*omega2 + h)  (feeds enc_attn2 -> round)
    run_attn(p_t2, p_t2, 1, aw_r + 2 * ANK, attn_b + 2 * 4 * BINS_, er_r + 2 * ERS,
             p_qkv, p_att, p_scores, p_hs, 0, 0);
    ln_kernel<<<M, 256, BINS_ * 4>>>(p_t2, p_hs, nullptr, omega + 2 * BINS_,
                                     ln_g + 2 * BINS_, ln_b + 2 * BINS_, p_t1, BINS_, 1);

    // enc_attn2 ; x4 = LN(x3*omega3 + h)  (feeds c3 GEMM -> round)
    run_attn(p_t1, p_ms, 0, aw_r + 3 * ANK, attn_b + 3 * 4 * BINS_, er_r + 3 * ERS,
             p_qkv, p_att, p_scores, p_hs, 0, 0);
    ln_kernel<<<M, 256, BINS_ * 4>>>(p_t1, p_hs, nullptr, omega + 3 * BINS_,
                                     ln_g + 3 * BINS_, ln_b + 3 * BINS_, p_t2, BINS_, 1);

    // FFN: silu(x4 @ c3^T) @ c4^T   (silu output feeds c4 GEMM -> round)
    launch_tgemm(p_t2, BINS_, 0, 0, c3_r, BINS_, 0, 0, nullptr, p_ffa, FF2_, 0, 0,
                 M, FF2_, BINS_, 1, 1, 1, 2 /*silu*/, 1, 0);
    launch_tgemm(p_ffa, FF2_, 0, 0, c4_r, FF2_, 0, 0, nullptr, p_hs, BINS_, 0, 0,
                 M, BINS_, FF2_, 1, 1, 1, 0, 0, 0);

    // out = LN(x4*omega4 + h) (final output -> NO round), then transpose to [B, BINS, W]
    ln_kernel<<<M, 256, BINS_ * 4>>>(p_t2, p_hs, nullptr, omega + 4 * BINS_,
                                     ln_g + 4 * BINS_, ln_b + 4 * BINS_, p_t1, BINS_, 0);
    {
        dim3 g(W_ / 32, BINS_ / 32, B_), blk(32, 8);
        transpose_out_kernel<<<g, blk>>>(p_t1, (float*)d_out);
    }
}

// round 14
// speedup vs baseline: 1.0965x; 1.0086x over previous
#include <cuda_runtime.h>
#include <math.h>

#define B_    4
#define W_    1024
#define BINS_ 1024
#define H_    4
#define DH_   256
#define FF2_  4096
#define FFH_  1024
#define QKV_  (3 * BINS_)

// stage layout for pipelined GEMMs: A(4608 floats) + B(4608 floats) per stage, 3 stages
#define STAGE_F 9216
#define NSTAGE  3
#define SMEM_BYTES (NSTAGE * STAGE_F * 4)

// ---------------- scratch (static device memory; no allocations) ----------------
__device__ float g_xs  [(size_t)B_*W_*BINS_];
__device__ float g_ms  [(size_t)B_*W_*BINS_];
__device__ float g_qkv [(size_t)B_*W_*QKV_];
__device__ float g_qkv2[(size_t)B_*W_*QKV_];
__device__ float g_att [(size_t)B_*W_*BINS_];
__device__ float g_att2[(size_t)B_*W_*BINS_];
__device__ float g_hs  [(size_t)B_*W_*BINS_];
__device__ float g_hm  [(size_t)B_*W_*BINS_];
__device__ float g_t1  [(size_t)B_*W_*BINS_];
__device__ float g_t2  [(size_t)B_*W_*BINS_];
__device__ float g_dwc [(size_t)B_*W_*BINS_];
__device__ float g_dwc2[(size_t)B_*W_*BINS_];
__device__ float g_ffb [(size_t)B_*W_*FFH_];
__device__ float g_scores [(size_t)B_*H_*W_*W_];
__device__ float g_scores2[(size_t)B_*H_*W_*W_];
__device__ float g_ffa [(size_t)B_*W_*FF2_];
__device__ float g_dwf [(size_t)B_*W_*FF2_];

// rounded weights: attn_w | er | c1L_pw | c1R_pw | c2_pw | c3_w | c4_w
#define OFF_AW   0L
#define OFF_ER   16777216L
#define OFF_C1L  17825792L
#define OFF_C1R  22020096L
#define OFF_C2   23068672L
#define OFF_C3   27262976L
#define OFF_C4   31457280L
#define WR_TOTAL 35651584L
__device__ float g_wr[WR_TOTAL];

// ---------------- helpers ----------------
__device__ __forceinline__ unsigned f2tf(float f) {
    unsigned r;
    asm("cvt.rna.tf32.f32 %0, %1;" : "=r"(r) : "f"(f));
    return r;
}
__device__ __forceinline__ float tfr(float f) { return __uint_as_float(f2tf(f)); }

__device__ __forceinline__ void mma8(float* d, const unsigned* a, const unsigned* b) {
    asm("mma.sync.aligned.m16n8k8.row.col.f32.tf32.tf32.f32 "
        "{%0,%1,%2,%3},{%4,%5,%6,%7},{%8,%9},{%0,%1,%2,%3};"
        : "+f"(d[0]), "+f"(d[1]), "+f"(d[2]), "+f"(d[3])
        : "r"(a[0]), "r"(a[1]), "r"(a[2]), "r"(a[3]), "r"(b[0]), "r"(b[1]));
}

__device__ __forceinline__ void cp16(float* smem_dst, const float* gsrc) {
    unsigned d = (unsigned)__cvta_generic_to_shared(smem_dst);
    asm volatile("cp.async.cg.shared.global [%0], [%1], 16;" :: "r"(d), "l"(gsrc));
}
__device__ __forceinline__ void cp_commit() { asm volatile("cp.async.commit_group;"); }
__device__ __forceinline__ void cp_wait2()  { asm volatile("cp.async.wait_group 2;"); }

__device__ __forceinline__ float apply_act(float v, int act) {
    if (act == 1) return (v >= 0.f) ? v : 0.01f * v;
    if (act == 2) return v / (1.f + __expf(-v));
    return v;
}

// ---------------- tf32 rounding copy of ALL weight operands in ONE launch ----------------
__global__ void round_all_kernel(const float4* __restrict__ s0, const float4* __restrict__ s1,
                                 const float4* __restrict__ s2, const float4* __restrict__ s3,
                                 const float4* __restrict__ s4, const float4* __restrict__ s5,
                                 const float4* __restrict__ s6, float4* __restrict__ out)
{
    long i = (long)blockIdx.x * 256 + threadIdx.x;
    if (i >= 8912896L) return;
    const float4* src;
    long rel = i;
    if      (i < 4194304L) { src = s0; rel = i; }
    else if (i < 4456448L) { src = s1; rel = i - 4194304L; }
    else if (i < 5505024L) { src = s2; rel = i - 4456448L; }
    else if (i < 5767168L) { src = s3; rel = i - 5505024L; }
    else if (i < 6815744L) { src = s4; rel = i - 5767168L; }
    else if (i < 7864320L) { src = s5; rel = i - 6815744L; }
    else                   { src = s6; rel = i - 7864320L; }
    float4 v = src[rel];
    v.x = tfr(v.x); v.y = tfr(v.y); v.z = tfr(v.z); v.w = tfr(v.w);
    out[i] = v;
}

// ---------------- input projection: out[b,w,h] = sum_c x[b,c,h,w] * wc[c] ----------------
__global__ void project_kernel(const float* __restrict__ x, const float* __restrict__ wc,
                               int Cn, float* __restrict__ out)
{
    __shared__ float tile[32][33];
    int b  = blockIdx.z;
    int h0 = blockIdx.y * 32, w0 = blockIdx.x * 32;
    int tx = threadIdx.x, ty = threadIdx.y;   // 32 x 8

    float wreg[8];
    #pragma unroll
    for (int c = 0; c < 8; c++) wreg[c] = (c < Cn) ? wc[c] : 0.f;

    #pragma unroll
    for (int r = 0; r < 4; r++) {
        int h = h0 + ty + r * 8;
        float acc = 0.f;
        #pragma unroll
        for (int c = 0; c < 8; c++)
            acc += x[(((size_t)b * Cn + c) * BINS_ + h) * W_ + (w0 + tx)] * wreg[c];
        tile[ty + r * 8][tx] = tfr(acc);
    }
    __syncthreads();
    #pragma unroll
    for (int r = 0; r < 4; r++) {
        int w = w0 + ty + r * 8;
        out[((size_t)b * W_ + w) * BINS_ + (h0 + tx)] = tile[tx][ty + r * 8];
    }
}

// ---------------- final transpose: out[b,h,w] = in[b,w,h] ----------------
__global__ void transpose_out_kernel(const float* __restrict__ in, float* __restrict__ out)
{
    __shared__ float tile[32][33];
    int b  = blockIdx.z;
    int w0 = blockIdx.x * 32, h0 = blockIdx.y * 32;
    int tx = threadIdx.x, ty = threadIdx.y;

    #pragma unroll
    for (int r = 0; r < 4; r++)
        tile[ty + r * 8][tx] = in[((size_t)b * W_ + (w0 + ty + r * 8)) * BINS_ + (h0 + tx)];
    __syncthreads();
    #pragma unroll
    for (int r = 0; r < 4; r++)
        out[((size_t)b * BINS_ + (h0 + ty + r * 8)) * W_ + (w0 + tx)] = tile[tx][ty + r * 8];
}

// ---------------- tf32 tensor-core GEMM, 64x64 warp tiles, 3-stage cp.async ----------------
// 128 threads = 4 warps in a 2(m) x 2(n) grid; CTA tile 128x128.
// All operands pre-rounded to tf32. BT=1: B is [N,K] (NT); BT=0: B is [K,N] (NN).
template <int BT>
__global__ void __launch_bounds__(128, 2)
tgemm_kernel(const float* __restrict__ A, int lda, long soA, long siA,
             const float* __restrict__ Bp, int ldb, long soB, long siB,
             const float* __restrict__ bias,
             float* __restrict__ C, int ldc, long soC, long siC,
             int K, int zdiv, int act, int rnd)
{
    extern __shared__ float smem[];

    int z = blockIdx.z;
    long zo = z / zdiv, zi = z % zdiv;
    A  += zo * soA + zi * siA;
    Bp += zo * soB + zi * siB;
    C  += zo * soC + zi * siC;

    int m0 = blockIdx.y * 128, n0 = blockIdx.x * 128;
    int tid  = threadIdx.x;
    int lane = tid & 31, wid = tid >> 5;
    int g = lane >> 2, tg = lane & 3;
    int wm = wid & 1, wn = wid >> 1;      // warp grid 2 (m) x 2 (n), 64x64 tiles

    float acc[4][8][4] = {};

    auto issue = [&](int k0, int s) {
        float* Sa = smem + s * STAGE_F;
        float* Sb = Sa + 4608;
        #pragma unroll
        for (int i = 0; i < 8; i++) {
            int idx = tid + i * 128;
            int r = idx >> 3, c = (idx & 7) << 2;
            cp16(Sa + r * 36 + c, A + (size_t)(m0 + r) * lda + k0 + c);
            if (BT) {
                cp16(Sb + r * 36 + c, Bp + (size_t)(n0 + r) * ldb + k0 + c);
            } else {
                int kr = idx >> 5, cn = (idx & 31) << 2;
                cp16(Sb + kr * 132 + cn, Bp + (size_t)(k0 + kr) * ldb + n0 + cn);
            }
        }
        cp_commit();
    };

    int nc = K >> 5;
    issue(0, 0);
    if (nc > 1) issue(32, 1);
    for (int ch = 0; ch < nc; ch++) {
        if (ch + 2 < nc) issue((ch + 2) << 5, (ch + 2) % NSTAGE);
        else             cp_commit();
        cp_wait2();
        __syncthreads();

        const unsigned* Ua = (const unsigned*)(smem + (ch % NSTAGE) * STAGE_F);
        const unsigned* Ub = Ua + 4608;

        unsigned af[2][4][4], bf[2][8][2];
        auto ldf = [&](int kk, int bi) {
            #pragma unroll
            for (int mt = 0; mt < 4; mt++) {
                int m = wm * 64 + mt * 16 + g;
                af[bi][mt][0] = Ua[m * 36 + kk + tg];
                af[bi][mt][1] = Ua[(m + 8) * 36 + kk + tg];
                af[bi][mt][2] = Ua[m * 36 + kk + tg + 4];
                af[bi][mt][3] = Ua[(m + 8) * 36 + kk + tg + 4];
            }
            #pragma unroll
            for (int nt = 0; nt < 8; nt++) {
                int n = wn * 64 + nt * 8 + g;
                if (BT) {
                    bf[bi][nt][0] = Ub[n * 36 + kk + tg];
                    bf[bi][nt][1] = Ub[n * 36 + kk + tg + 4];
                } else {
                    bf[bi][nt][0] = Ub[(kk + tg) * 132 + n];
                    bf[bi][nt][1] = Ub[(kk + tg + 4) * 132 + n];
                }
            }
        };

        ldf(0, 0);
        #pragma unroll
        for (int kk8 = 0; kk8 < 4; kk8++) {
            if (kk8 < 3) ldf((kk8 + 1) * 8, (kk8 + 1) & 1);
            #pragma unroll
            for (int mt = 0; mt < 4; mt++)
                #pragma unroll
                for (int nt = 0; nt < 8; nt++)
                    mma8(acc[mt][nt], af[kk8 & 1][mt], bf[kk8 & 1][nt]);
        }
        __syncthreads();
    }

    // epilogue
    #pragma unroll
    for (int mt = 0; mt < 4; mt++) {
        int r0 = m0 + wm * 64 + mt * 16 + g;
        #pragma unroll
        for (int nt = 0; nt < 8; nt++) {
            int c = n0 + wn * 64 + nt * 8 + tg * 2;
            float b0 = bias ? bias[c] : 0.f, b1 = bias ? bias[c + 1] : 0.f;
            float vv[4];
            vv[0] = apply_act(acc[mt][nt][0] + b0, act);
            vv[1] = apply_act(acc[mt][nt][1] + b1, act);
            vv[2] = apply_act(acc[mt][nt][2] + b0, act);
            vv[3] = apply_act(acc[mt][nt][3] + b1, act);
            if (rnd) {
                vv[0] = tfr(vv[0]); vv[1] = tfr(vv[1]);
                vv[2] = tfr(vv[2]); vv[3] = tfr(vv[3]);
            }
            *reinterpret_cast<float2*>(C + (size_t)r0 * ldc + c)       = make_float2(vv[0], vv[1]);
            *reinterpret_cast<float2*>(C + (size_t)(r0 + 8) * ldc + c) = make_float2(vv[2], vv[3]);
        }
    }
}

// ---------------- fused attention scores as a virtual K=512 pipelined GEMM ----------------
// s[i,j] = (sum_k Q[i,k]K[j,k]  +  sum_k er[k,i]Q[j,k]) / 32
// Q/K given by base pointers + runtime row strides (packed-QKV friendly).
__global__ void __launch_bounds__(128, 2)
scores_kernel(const float* __restrict__ q, int ldq,
              const float* __restrict__ kx, int ldk,
              const float* __restrict__ er, float* __restrict__ s)
{
    extern __shared__ float smem[];

    int bh = blockIdx.z;
    int b = bh >> 2, h = bh & 3;
    const float* qb = q  + (size_t)b * W_ * ldq + h * DH_;
    const float* kb = kx + (size_t)b * W_ * ldk + h * DH_;
    float* sb = s + (size_t)bh * W_ * W_;

    int i0 = blockIdx.y * 128, j0 = blockIdx.x * 128;
    int tid  = threadIdx.x;
    int lane = tid & 31, wid = tid >> 5;
    int g = lane >> 2, tg = lane & 3;
    int wm = wid & 1, wn = wid >> 1;

    float acc[4][8][4] = {};

    auto issue = [&](int t) {
        float* Sa = smem + (t % NSTAGE) * STAGE_F;
        float* Sb = Sa + 4608;
        int k0 = (t & 7) << 5;
        #pragma unroll
        for (int i = 0; i < 8; i++) {
            int idx = tid + i * 128;
            int r = idx >> 3, c = (idx & 7) << 2;
            if (t < 8) {
                cp16(Sa + r * 36 + c, qb + (size_t)(i0 + r) * ldq + k0 + c);
                cp16(Sb + r * 36 + c, kb + (size_t)(j0 + r) * ldk + k0 + c);
            } else {
                int kr = idx >> 5, cn = (idx & 31) << 2;
                cp16(Sa + kr * 132 + cn, er + (size_t)(k0 + kr) * W_ + i0 + cn);
                cp16(Sb + r * 36 + c, qb + (size_t)(j0 + r) * ldq + k0 + c);
            }
        }
        cp_commit();
    };

    issue(0); issue(1);
    for (int t = 0; t < 16; t++) {
        if (t + 2 < 16) issue(t + 2);
        else            cp_commit();
        cp_wait2();
        __syncthreads();

        const unsigned* Ua = (const unsigned*)(smem + (t % NSTAGE) * STAGE_F);
        const unsigned* Ub = Ua + 4608;
        bool nnA = (t >= 8);

        unsigned af[2][4][4], bf[2][8][2];
        auto ldf = [&](int kk, int bi) {
            #pragma unroll
            for (int mt = 0; mt < 4; mt++) {
                int m = wm * 64 + mt * 16 + g;
                if (!nnA) {
                    af[bi][mt][0] = Ua[m * 36 + kk + tg];
                    af[bi][mt][1] = Ua[(m + 8) * 36 + kk + tg];
                    af[bi][mt][2] = Ua[m * 36 + kk + tg + 4];
                    af[bi][mt][3] = Ua[(m + 8) * 36 + kk + tg + 4];
                } else {
                    af[bi][mt][0] = Ua[(kk + tg) * 132 + m];
                    af[bi][mt][1] = Ua[(kk + tg) * 132 + m + 8];
                    af[bi][mt][2] = Ua[(kk + tg + 4) * 132 + m];
                    af[bi][mt][3] = Ua[(kk + tg + 4) * 132 + m + 8];
                }
            }
            #pragma unroll
            for (int nt = 0; nt < 8; nt++) {
                int n = wn * 64 + nt * 8 + g;
                bf[bi][nt][0] = Ub[n * 36 + kk + tg];
                bf[bi][nt][1] = Ub[n * 36 + kk + tg + 4];
            }
        };

        ldf(0, 0);
        #pragma unroll
        for (int kk8 = 0; kk8 < 4; kk8++) {
            if (kk8 < 3) ldf((kk8 + 1) * 8, (kk8 + 1) & 1);
            #pragma unroll
            for (int mt = 0; mt < 4; mt++)
                #pragma unroll
                for (int nt = 0; nt < 8; nt++)
                    mma8(acc[mt][nt], af[kk8 & 1][mt], bf[kk8 & 1][nt]);
        }
        __syncthreads();
    }

    #pragma unroll
    for (int mt = 0; mt < 4; mt++) {
        int r0 = i0 + wm * 64 + mt * 16 + g;
        #pragma unroll
        for (int nt = 0; nt < 8; nt++) {
            int c = j0 + wn * 64 + nt * 8 + tg * 2;
            float2 v0, v1;
            v0.x = acc[mt][nt][0] * 0.03125f;
            v0.y = acc[mt][nt][1] * 0.03125f;
            v1.x = acc[mt][nt][2] * 0.03125f;
            v1.y = acc[mt][nt][3] * 0.03125f;
            *reinterpret_cast<float2*>(sb + (size_t)r0 * W_ + c) = v0;
            *reinterpret_cast<float2*>(sb + (size_t)(r0 + 8) * W_ + c) = v1;
        }
    }
}

// ---------------- row softmax over n=1024 (output rounded to tf32) ----------------
__global__ void softmax_kernel(float* __restrict__ s)
{
    const int n = W_;
    float* row = s + (size_t)blockIdx.x * n;
    int tid = threadIdx.x;
    __shared__ float red[8];

    float m = -3.4e38f;
    for (int i = tid; i < n; i += 256) m = fmaxf(m, row[i]);
    #pragma unroll
    for (int o = 16; o; o >>= 1) m = fmaxf(m, __shfl_xor_sync(0xffffffffu, m, o));
    if ((tid & 31) == 0) red[tid >> 5] = m;
    __syncthreads();
    m = red[0];
    #pragma unroll
    for (int wi = 1; wi < 8; wi++) m = fmaxf(m, red[wi]);

    float sum = 0.f;
    for (int i = tid; i < n; i += 256) { float e = __expf(row[i] - m); row[i] = e; sum += e; }
    #pragma unroll
    for (int o = 16; o; o >>= 1) sum += __shfl_xor_sync(0xffffffffu, sum, o);
    __syncthreads();
    if ((tid & 31) == 0) red[tid >> 5] = sum;
    __syncthreads();
    float tot = 0.f;
    #pragma unroll
    for (int wi = 0; wi < 8; wi++) tot += red[wi];
    float inv = 1.f / tot;
    for (int i = tid; i < n; i += 256) row[i] = tfr(row[i] * inv);
}

// ---------------- fused (a*omega + b(partial-width) + c) -> LayerNorm ----------------
// bsrc row width bw (<= R): adds bsrc[row*bw + i] for i < bw only.
__global__ void ln_kernel(const float* __restrict__ a, const float* __restrict__ bsrc,
                          int bw,
                          const float* __restrict__ csrc, const float* __restrict__ omega,
                          const float* __restrict__ g, const float* __restrict__ bet,
                          float* __restrict__ out, int R, int rnd)
{
    extern __shared__ float sm[];
    __shared__ float rs[8], rq[8];
    size_t base = (size_t)blockIdx.x * R;
    size_t baseb = (size_t)blockIdx.x * bw;
    int tid = threadIdx.x;

    float s = 0.f, sq = 0.f;
    for (int i = tid; i < R; i += 256) {
        float v = a[base + i];
        if (omega) v *= omega[i];
        if (bsrc && i < bw) v += bsrc[baseb + i];
        if (csrc)  v += csrc[base + i];
        sm[i] = v; s += v; sq += v * v;
    }
    #pragma unroll
    for (int o = 16; o; o >>= 1) {
        s  += __shfl_xor_sync(0xffffffffu, s, o);
        sq += __shfl_xor_sync(0xffffffffu, sq, o);
    }
    if ((tid & 31) == 0) { rs[tid >> 5] = s; rq[tid >> 5] = sq; }
    __syncthreads();
    float ts = 0.f, tq = 0.f;
    #pragma unroll
    for (int wi = 0; wi < 8; wi++) { ts += rs[wi]; tq += rq[wi]; }
    float mean = ts / (float)R;
    float var  = tq / (float)R - mean * mean;
    float inv  = rsqrtf(var + 1e-5f);
    for (int i = tid; i < R; i += 256) {
        float v = (sm[i] - mean) * inv * g[i] + bet[i];
        out[base + i] = rnd ? tfr(v) : v;
    }
}

// ---------------- depthwise conv along w, layout [B, W, Ch] (output rounded) ----------------
__global__ void dwconv_kernel(const float* __restrict__ in, const float* __restrict__ wk,
                              float* __restrict__ out, int Ch, int Kt, int pad)
{
    int c = blockIdx.x * blockDim.x + threadIdx.x;
    int w = blockIdx.y, b = blockIdx.z;
    const float* ib = in + ((size_t)b * W_) * Ch;
    float acc = 0.f;
    for (int t = 0; t < Kt; t++) {
        int ww = w + t - pad;
        if (ww >= 0 && ww < W_) acc += ib[(size_t)ww * Ch + c] * wk[c * Kt + t];
    }
    out[((size_t)b * W_ + w) * Ch + c] = tfr(acc);
}

// =========================================================================
static void launch_tgemm(const float* A, int lda, long soA, long siA,
                         const float* Bp, int ldb, long soB, long siB,
                         const float* bias, float* C, int ldc, long soC, long siC,
                         int M, int N, int K, int nz, int zdiv, int BT, int act, int rnd,
                         cudaStream_t st)
{
    dim3 g(N / 128, M / 128, nz);
    if (BT)
        tgemm_kernel<1><<<g, 128, SMEM_BYTES, st>>>(A, lda, soA, siA, Bp, ldb, soB, siB, bias,
                                                    C, ldc, soC, siC, K, zdiv, act, rnd);
    else
        tgemm_kernel<0><<<g, 128, SMEM_BYTES, st>>>(A, lda, soA, siA, Bp, ldb, soB, siB, bias,
                                                    C, ldc, soC, siC, K, zdiv, act, rnd);
}

// Attention core (scores -> softmax -> AV -> out-proj) on packed QKV.
static void attn_core(const float* w, const float* bias, const float* er,
                      float* qkv, float* att, float* scores, float* outp,
                      int rnd_out, cudaStream_t st)
{
    const long NK = (long)BINS_ * BINS_;
    const int  M  = B_ * W_;
    dim3 gs(W_ / 128, W_ / 128, B_ * H_);
    scores_kernel<<<gs, 128, SMEM_BYTES, st>>>(qkv, QKV_, qkv + BINS_, QKV_, er, scores);
    softmax_kernel<<<B_ * H_ * W_, 256, 0, st>>>(scores);
    launch_tgemm(scores, W_, 4L * W_ * W_, (long)W_ * W_,
                 qkv + 2 * BINS_, QKV_, (long)W_ * QKV_, DH_,
                 nullptr,
                 att, BINS_, (long)W_ * BINS_, DH_,
                 W_, DH_, W_, B_ * H_, H_, 0, 0, 1, st);
    launch_tgemm(att, BINS_, 0, 0, w + 3 * NK, BINS_, 0, 0, bias + 3 * BINS_,
                 outp, BINS_, 0, 0, M, BINS_, BINS_, 1, 1, 1, 0, rnd_out, st);
}

extern "C" void kernel_launch(void* const* d_in, const int* in_sizes, int n_in,
                              void* d_out, int out_size)
{
    (void)in_sizes; (void)n_in; (void)out_size;

    cudaFuncSetAttribute(tgemm_kernel<0>, cudaFuncAttributeMaxDynamicSharedMemorySize, SMEM_BYTES);
    cudaFuncSetAttribute(tgemm_kernel<1>, cudaFuncAttributeMaxDynamicSharedMemorySize, SMEM_BYTES);
    cudaFuncSetAttribute(scores_kernel,   cudaFuncAttributeMaxDynamicSharedMemorySize, SMEM_BYTES);

    // Side stream + fork/join events (created once on the first, uncaptured, call).
    static cudaStream_t s2 = nullptr;
    static cudaEvent_t  ev[6] = {};
    if (!s2) {
        cudaStreamCreateWithFlags(&s2, cudaStreamNonBlocking);
        for (int i = 0; i < 6; i++) cudaEventCreateWithFlags(&ev[i], cudaEventDisableTiming);
    }

    const float* x      = (const float*)d_in[0];
    const float* mem    = (const float*)d_in[1];
    const float* in_w   = (const float*)d_in[2];
    const float* skip_w = (const float*)d_in[3];
    const float* attn_w = (const float*)d_in[4];
    const float* attn_b = (const float*)d_in[5];
    const float* er     = (const float*)d_in[6];
    const float* omega  = (const float*)d_in[7];
    const float* ln_g   = (const float*)d_in[8];
    const float* ln_b   = (const float*)d_in[9];
    const float* ln2_g  = (const float*)d_in[10];
    const float* ln2_b  = (const float*)d_in[11];
    const float* c1L_dw = (const float*)d_in[12];
    const float* c1L_pw = (const float*)d_in[13];
    const float* c1R_dw = (const float*)d_in[14];
    const float* c1R_pw = (const float*)d_in[15];
    const float* c2_dw  = (const float*)d_in[16];
    const float* c2_pw  = (const float*)d_in[17];
    const float* c3_w   = (const float*)d_in[18];
    const float* c4_w   = (const float*)d_in[19];

    float *p_xs, *p_ms, *p_qkv, *p_qkv2, *p_att, *p_att2, *p_hs, *p_hm, *p_t1, *p_t2;
    float *p_dwc, *p_dwc2, *p_ffb, *p_scores, *p_scores2, *p_ffa, *p_dwf, *p_wr;
    cudaGetSymbolAddress((void**)&p_xs,   g_xs);
    cudaGetSymbolAddress((void**)&p_ms,   g_ms);
    cudaGetSymbolAddress((void**)&p_qkv,  g_qkv);
    cudaGetSymbolAddress((void**)&p_qkv2, g_qkv2);
    cudaGetSymbolAddress((void**)&p_att,  g_att);
    cudaGetSymbolAddress((void**)&p_att2, g_att2);
    cudaGetSymbolAddress((void**)&p_hs,   g_hs);
    cudaGetSymbolAddress((void**)&p_hm,   g_hm);
    cudaGetSymbolAddress((void**)&p_t1,   g_t1);
    cudaGetSymbolAddress((void**)&p_t2,   g_t2);
    cudaGetSymbolAddress((void**)&p_dwc,  g_dwc);
    cudaGetSymbolAddress((void**)&p_dwc2, g_dwc2);
    cudaGetSymbolAddress((void**)&p_ffb,  g_ffb);
    cudaGetSymbolAddress((void**)&p_scores,  g_scores);
    cudaGetSymbolAddress((void**)&p_scores2, g_scores2);
    cudaGetSymbolAddress((void**)&p_ffa,  g_ffa);
    cudaGetSymbolAddress((void**)&p_dwf,  g_dwf);
    cudaGetSymbolAddress((void**)&p_wr,   g_wr);

    // ---- round all GEMM weight operands to tf32, ONE launch ----
    round_all_kernel<<<(int)((8912896L + 255) / 256), 256>>>(
        (const float4*)attn_w, (const float4*)er, (const float4*)c1L_pw,
        (const float4*)c1R_pw, (const float4*)c2_pw, (const float4*)c3_w,
        (const float4*)c4_w, (float4*)p_wr);

    const float* aw_r  = p_wr + OFF_AW;
    const float* er_r  = p_wr + OFF_ER;
    const float* c1L_r = p_wr + OFF_C1L;
    const float* c1R_r = p_wr + OFF_C1R;
    const float* c2_r  = p_wr + OFF_C2;
    const float* c3_r  = p_wr + OFF_C3;
    const float* c4_r  = p_wr + OFF_C4;

    const int  M  = B_ * W_;
    const long ANK = 4L * BINS_ * BINS_;   // per-attention weight stride
    const long ERS = (long)DH_ * W_;
    const long NK  = (long)BINS_ * BINS_;

    // input / skip projections
    {
        dim3 g(W_ / 32, BINS_ / 32, B_), blk(32, 8);
        project_kernel<<<g, blk>>>(x,   in_w,   8, p_xs);
        project_kernel<<<g, blk>>>(mem, skip_w, 8, p_ms);
    }

    // self_attn1 (stream 0)  ||  enc_attn1 (stream s2)
    cudaEventRecord(ev[0], 0);
    cudaStreamWaitEvent(s2, ev[0], 0);
    // self: fused QKV (N=3072)
    launch_tgemm(p_xs, BINS_, 0, 0, aw_r + 0 * ANK, BINS_, 0, 0, attn_b + 0 * 4 * BINS_,
                 p_qkv, QKV_, 0, 0, M, QKV_, BINS_, 1, 1, 1, 0, 1, 0);
    attn_core(aw_r + 0 * ANK, attn_b + 0 * 4 * BINS_, er_r + 0 * ERS,
              p_qkv, p_att, p_scores, p_hs, 0, 0);
    // enc: Q from xs, K/V (N=2048) from ms
    launch_tgemm(p_xs, BINS_, 0, 0, aw_r + 1 * ANK, BINS_, 0, 0, attn_b + 1 * 4 * BINS_,
                 p_qkv2, QKV_, 0, 0, M, BINS_, BINS_, 1, 1, 1, 0, 1, s2);
    launch_tgemm(p_ms, BINS_, 0, 0, aw_r + 1 * ANK + NK, BINS_, 0, 0, attn_b + 1 * 4 * BINS_ + BINS_,
                 p_qkv2 + BINS_, QKV_, 0, 0, M, 2 * BINS_, BINS_, 1, 1, 1, 0, 1, s2);
    attn_core(aw_r + 1 * ANK, attn_b + 1 * 4 * BINS_, er_r + 1 * ERS,
              p_qkv2, p_att2, p_scores2, p_hm, 0, s2);
    cudaEventRecord(ev[1], s2);
    cudaStreamWaitEvent(0, ev[1], 0);

    // x1 = LN(xs*omega0 + hs + hm)
    ln_kernel<<<M, 256, BINS_ * 4>>>(p_xs, p_hs, BINS_, p_hm, omega + 0 * BINS_,
                                     ln_g + 0 * BINS_, ln_b + 0 * BINS_, p_t1, BINS_, 0);

    // conv block: c1L chain (stream 0) || c1R chain (s2); then enc_attn2 K/V early on s2
    cudaEventRecord(ev[2], 0);
    cudaStreamWaitEvent(s2, ev[2], 0);
    dwconv_kernel<<<dim3(BINS_ / 256, W_, B_), 256>>>(p_t1, c1L_dw, p_dwc, BINS_, 11, 5);
    launch_tgemm(p_dwc, BINS_, 0, 0, c1L_r, BINS_, 0, 0, nullptr, p_ffa, FF2_, 0, 0,
                 M, FF2_, BINS_, 1, 1, 1, 1 /*lrelu*/, 0, 0);
    dwconv_kernel<<<dim3(BINS_ / 256, W_, B_), 256, 0, s2>>>(p_t1, c1R_dw, p_dwc2, BINS_, 7, 3);
    launch_tgemm(p_dwc2, BINS_, 0, 0, c1R_r, BINS_, 0, 0, nullptr, p_ffb, FFH_, 0, 0,
                 M, FFH_, BINS_, 1, 1, 1, 0, 0, s2);
    cudaEventRecord(ev[3], s2);
    cudaStreamWaitEvent(0, ev[3], 0);

    // enc_attn2 K/V depends only on p_ms + weights -> run on s2 overlapping the middle section
    launch_tgemm(p_ms, BINS_, 0, 0, aw_r + 3 * ANK + NK, BINS_, 0, 0, attn_b + 3 * 4 * BINS_ + BINS_,
                 p_qkv2 + BINS_, QKV_, 0, 0, M, 2 * BINS_, BINS_, 1, 1, 1, 0, 1, s2);
    cudaEventRecord(ev[4], s2);

    // h = LN2(ffa + pad(ffb)) [fused add_pad], then c2 chain
    ln_kernel<<<M, 256, FF2_ * 4>>>(p_ffa, p_ffb, FFH_, nullptr, nullptr, ln2_g, ln2_b, p_ffa, FF2_, 0);
    dwconv_kernel<<<dim3(FF2_ / 256, W_, B_), 256>>>(p_ffa, c2_dw, p_dwf, FF2_, 7, 3);
    launch_tgemm(p_dwf, FF2_, 0, 0, c2_r, FF2_, 0, 0, nullptr, p_hs, BINS_, 0, 0,
                 M, BINS_, FF2_, 1, 1, 1, 0, 0, 0);

    // x2 = LN(x1*omega1 + h)
    ln_kernel<<<M, 256, BINS_ * 4>>>(p_t1, p_hs, BINS_, nullptr, omega + 1 * BINS_,
                                     ln_g + 1 * BINS_, ln_b + 1 * BINS_, p_t2, BINS_, 1);

    // self_attn2 (fused QKV) ; x3 = LN(x2*omega2 + h)
    launch_tgemm(p_t2, BINS_, 0, 0, aw_r + 2 * ANK, BINS_, 0, 0, attn_b + 2 * 4 * BINS_,
                 p_qkv, QKV_, 0, 0, M, QKV_, BINS_, 1, 1, 1, 0, 1, 0);
    attn_core(aw_r + 2 * ANK, attn_b + 2 * 4 * BINS_, er_r + 2 * ERS,
              p_qkv, p_att, p_scores, p_hs, 0, 0);
    ln_kernel<<<M, 256, BINS_ * 4>>>(p_t2, p_hs, BINS_, nullptr, omega + 2 * BINS_,
                                     ln_g + 2 * BINS_, ln_b + 2 * BINS_, p_t1, BINS_, 1);

    // enc_attn2: Q from x3 (stream 0); K/V already computed on s2
    launch_tgemm(p_t1, BINS_, 0, 0, aw_r + 3 * ANK, BINS_, 0, 0, attn_b + 3 * 4 * BINS_,
                 p_qkv2, QKV_, 0, 0, M, BINS_, BINS_, 1, 1, 1, 0, 1, 0);
    cudaStreamWaitEvent(0, ev[4], 0);
    attn_core(aw_r + 3 * ANK, attn_b + 3 * 4 * BINS_, er_r + 3 * ERS,
              p_qkv2, p_att, p_scores, p_hs, 0, 0);
    ln_kernel<<<M, 256, BINS_ * 4>>>(p_t1, p_hs, BINS_, nullptr, omega + 3 * BINS_,
                                     ln_g + 3 * BINS_, ln_b + 3 * BINS_, p_t2, BINS_, 1);

    // FFN: silu(x4 @ c3^T) @ c4^T
    launch_tgemm(p_t2, BINS_, 0, 0, c3_r, BINS_, 0, 0, nullptr, p_ffa, FF2_, 0, 0,
                 M, FF2_, BINS_, 1, 1, 1, 2 /*silu*/, 1, 0);
    launch_tgemm(p_ffa, FF2_, 0, 0, c4_r, FF2_, 0, 0, nullptr, p_hs, BINS_, 0, 0,
                 M, BINS_, FF2_, 1, 1, 1, 0, 0, 0);

    // out = LN(x4*omega4 + h), then transpose to [B, BINS, W]
    ln_kernel<<<M, 256, BINS_ * 4>>>(p_t2, p_hs, BINS_, nullptr, omega + 4 * BINS_,
                                     ln_g + 4 * BINS_, ln_b + 4 * BINS_, p_t1, BINS_, 0);
    {
        dim3 g(W_ / 32, BINS_ / 32, B_), blk(32, 8);
        transpose_out_kernel<<<g, blk>>>(p_t1, (float*)d_out);
    }
}

// round 16
// speedup vs baseline: 1.7147x; 1.5638x over previous
#include <cuda_runtime.h>
#include <cuda_fp16.h>
#include <math.h>

#define B_    4
#define W_    1024
#define BINS_ 1024
#define H_    4
#define DH_   256
#define FF2_  4096
#define FFH_  1024
#define QKV_  (3 * BINS_)

// fp16 GEMM stages: A 128x40 halfs (5120) + B 5120 halfs per stage, 3 stages
// (40-half row stride = 80 B = multiple of 16 -> cp.async-16 legal; NN B uses 136-half rows = 272 B)
#define A_H     5120
#define STG_H   10240
#define NSTAGE  3
#define SMEM_BYTES (NSTAGE * STG_H * 2)

// ---------------- scratch (static device memory; no allocations) ----------------
__device__ float g_xs  [(size_t)B_*W_*BINS_];
__device__ float g_ms  [(size_t)B_*W_*BINS_];
__device__ float g_hs  [(size_t)B_*W_*BINS_];
__device__ float g_hm  [(size_t)B_*W_*BINS_];
__device__ float g_t1  [(size_t)B_*W_*BINS_];
__device__ float g_t2  [(size_t)B_*W_*BINS_];
__device__ float g_ffa [(size_t)B_*W_*FF2_];
__device__ float g_ffb [(size_t)B_*W_*FFH_];
__device__ float g_scores [(size_t)B_*H_*W_*W_];
__device__ float g_scores2[(size_t)B_*H_*W_*W_];

__device__ __half g_xsh [(size_t)B_*W_*BINS_];
__device__ __half g_msh [(size_t)B_*W_*BINS_];
__device__ __half g_qkvh [(size_t)B_*W_*QKV_];
__device__ __half g_qkv2h[(size_t)B_*W_*QKV_];
__device__ __half g_atth [(size_t)B_*W_*BINS_];
__device__ __half g_att2h[(size_t)B_*W_*BINS_];
__device__ __half g_xh   [(size_t)B_*W_*BINS_];
__device__ __half g_scoresh [(size_t)B_*H_*W_*W_];
__device__ __half g_scores2h[(size_t)B_*H_*W_*W_];
__device__ __half g_dwch [(size_t)B_*W_*BINS_];
__device__ __half g_dwc2h[(size_t)B_*W_*BINS_];
__device__ __half g_dwfh [(size_t)B_*W_*FF2_];
__device__ __half g_ffah [(size_t)B_*W_*FF2_];

// half weights: attn_w | er | c1L_pw | c1R_pw | c2_pw | c3_w | c4_w (element offsets)
#define OFF_AW   0L
#define OFF_ER   16777216L
#define OFF_C1L  17825792L
#define OFF_C1R  22020096L
#define OFF_C2   23068672L
#define OFF_C3   27262976L
#define OFF_C4   31457280L
#define WH_TOTAL 35651584L
__device__ __half g_wh[WH_TOTAL];

// ---------------- helpers ----------------
__device__ __forceinline__ void mma16(float* d, const unsigned* a, const unsigned* b) {
    asm("mma.sync.aligned.m16n8k16.row.col.f32.f16.f16.f32 "
        "{%0,%1,%2,%3},{%4,%5,%6,%7},{%8,%9},{%0,%1,%2,%3};"
        : "+f"(d[0]), "+f"(d[1]), "+f"(d[2]), "+f"(d[3])
        : "r"(a[0]), "r"(a[1]), "r"(a[2]), "r"(a[3]), "r"(b[0]), "r"(b[1]));
}

__device__ __forceinline__ unsigned packh(__half a, __half b) {
    __half2 h = __halves2half2(a, b);
    return *reinterpret_cast<unsigned*>(&h);
}

__device__ __forceinline__ void cp16(void* smem_dst, const void* gsrc) {
    unsigned d = (unsigned)__cvta_generic_to_shared(smem_dst);
    asm volatile("cp.async.cg.shared.global [%0], [%1], 16;" :: "r"(d), "l"(gsrc));
}
__device__ __forceinline__ void cp_commit() { asm volatile("cp.async.commit_group;"); }
__device__ __forceinline__ void cp_wait2()  { asm volatile("cp.async.wait_group 2;"); }

__device__ __forceinline__ float apply_act(float v, int act) {
    if (act == 1) return (v >= 0.f) ? v : 0.01f * v;
    if (act == 2) return v / (1.f + __expf(-v));
    return v;
}

// ---------------- fp16 conversion of ALL weight operands in ONE launch ----------------
__global__ void round_all_kernel(const float4* __restrict__ s0, const float4* __restrict__ s1,
                                 const float4* __restrict__ s2, const float4* __restrict__ s3,
                                 const float4* __restrict__ s4, const float4* __restrict__ s5,
                                 const float4* __restrict__ s6, __half* __restrict__ out)
{
    long i = (long)blockIdx.x * 256 + threadIdx.x;
    if (i >= 8912896L) return;
    const float4* src;
    long rel = i;
    if      (i < 4194304L) { src = s0; rel = i; }
    else if (i < 4456448L) { src = s1; rel = i - 4194304L; }
    else if (i < 5505024L) { src = s2; rel = i - 4456448L; }
    else if (i < 5767168L) { src = s3; rel = i - 5505024L; }
    else if (i < 6815744L) { src = s4; rel = i - 5767168L; }
    else if (i < 7864320L) { src = s5; rel = i - 6815744L; }
    else                   { src = s6; rel = i - 7864320L; }
    float4 v = src[rel];
    __half2 lo = __floats2half2_rn(v.x, v.y);
    __half2 hi = __floats2half2_rn(v.z, v.w);
    uint2 u;
    u.x = *reinterpret_cast<unsigned*>(&lo);
    u.y = *reinterpret_cast<unsigned*>(&hi);
    reinterpret_cast<uint2*>(out)[i] = u;
}

// ---------------- input projection -> fp32 + fp16 outputs ----------------
__global__ void project_kernel(const float* __restrict__ x, const float* __restrict__ wc,
                               int Cn, float* __restrict__ out, __half* __restrict__ outh)
{
    __shared__ float tile[32][33];
    int b  = blockIdx.z;
    int h0 = blockIdx.y * 32, w0 = blockIdx.x * 32;
    int tx = threadIdx.x, ty = threadIdx.y;   // 32 x 8

    float wreg[8];
    #pragma unroll
    for (int c = 0; c < 8; c++) wreg[c] = (c < Cn) ? wc[c] : 0.f;

    #pragma unroll
    for (int r = 0; r < 4; r++) {
        int h = h0 + ty + r * 8;
        float acc = 0.f;
        #pragma unroll
        for (int c = 0; c < 8; c++)
            acc += x[(((size_t)b * Cn + c) * BINS_ + h) * W_ + (w0 + tx)] * wreg[c];
        tile[ty + r * 8][tx] = acc;
    }
    __syncthreads();
    #pragma unroll
    for (int r = 0; r < 4; r++) {
        int w = w0 + ty + r * 8;
        size_t idx = ((size_t)b * W_ + w) * BINS_ + (h0 + tx);
        float v = tile[tx][ty + r * 8];
        out[idx]  = v;
        outh[idx] = __float2half_rn(v);
    }
}

// ---------------- final transpose ----------------
__global__ void transpose_out_kernel(const float* __restrict__ in, float* __restrict__ out)
{
    __shared__ float tile[32][33];
    int b  = blockIdx.z;
    int w0 = blockIdx.x * 32, h0 = blockIdx.y * 32;
    int tx = threadIdx.x, ty = threadIdx.y;

    #pragma unroll
    for (int r = 0; r < 4; r++)
        tile[ty + r * 8][tx] = in[((size_t)b * W_ + (w0 + ty + r * 8)) * BINS_ + (h0 + tx)];
    __syncthreads();
    #pragma unroll
    for (int r = 0; r < 4; r++)
        out[((size_t)b * BINS_ + (h0 + ty + r * 8)) * W_ + (w0 + tx)] = tile[tx][ty + r * 8];
}

// ---------------- fp16 tensor-core GEMM (m16n8k16), 64x64 warp tiles ----------------
// 128 threads = 4 warps 2x2; CTA tile 128x128; K-chunk 32 (2 k16 steps).
// BT=1: B is [N,K] half (NT); BT=0: B is [K,N] half (NN).
// Output: Cf (fp32) and/or Ch (fp16), same ldc.
template <int BT>
__global__ void __launch_bounds__(128, 2)
hgemm_kernel(const __half* __restrict__ A, int lda, long soA, long siA,
             const __half* __restrict__ Bp, int ldb, long soB, long siB,
             const float* __restrict__ bias,
             float* __restrict__ Cf, __half* __restrict__ Ch,
             int ldc, long soC, long siC,
             int K, int zdiv, int act)
{
    extern __shared__ __half hsm[];

    int z = blockIdx.z;
    long zo = z / zdiv, zi = z % zdiv;
    A  += zo * soA + zi * siA;
    Bp += zo * soB + zi * siB;
    long co = zo * soC + zi * siC;

    int m0 = blockIdx.y * 128, n0 = blockIdx.x * 128;
    int tid  = threadIdx.x;
    int lane = tid & 31, wid = tid >> 5;
    int g = lane >> 2, tg2 = (lane & 3) * 2;
    int wm = wid & 1, wn = wid >> 1;

    float acc[4][8][4] = {};

    auto issue = [&](int k0, int s) {
        __half* Sa = hsm + s * STG_H;
        __half* Sb = Sa + A_H;
        #pragma unroll
        for (int i = 0; i < 4; i++) {
            int idx = tid + i * 128;
            int r = idx >> 2, c8 = (idx & 3) * 8;
            cp16(Sa + r * 40 + c8, A + (size_t)(m0 + r) * lda + k0 + c8);
            if (BT) {
                cp16(Sb + r * 40 + c8, Bp + (size_t)(n0 + r) * ldb + k0 + c8);
            } else {
                int kr = idx >> 4, cn = (idx & 15) * 8;
                cp16(Sb + kr * 136 + cn, Bp + (size_t)(k0 + kr) * ldb + n0 + cn);
            }
        }
        cp_commit();
    };

    int nc = K >> 5;
    issue(0, 0);
    if (nc > 1) issue(32, 1);
    for (int ch = 0; ch < nc; ch++) {
        if (ch + 2 < nc) issue((ch + 2) << 5, (ch + 2) % NSTAGE);
        else             cp_commit();
        cp_wait2();
        __syncthreads();

        const __half* Sa = hsm + (ch % NSTAGE) * STG_H;
        const __half* Sb = Sa + A_H;
        #pragma unroll
        for (int kk = 0; kk < 32; kk += 16) {
            unsigned af[4][4];
            #pragma unroll
            for (int mt = 0; mt < 4; mt++) {
                int m = wm * 64 + mt * 16 + g;
                af[mt][0] = *(const unsigned*)(Sa + m * 40 + kk + tg2);
                af[mt][1] = *(const unsigned*)(Sa + (m + 8) * 40 + kk + tg2);
                af[mt][2] = *(const unsigned*)(Sa + m * 40 + kk + 8 + tg2);
                af[mt][3] = *(const unsigned*)(Sa + (m + 8) * 40 + kk + 8 + tg2);
            }
            unsigned bf[8][2];
            #pragma unroll
            for (int nt = 0; nt < 8; nt++) {
                int n = wn * 64 + nt * 8 + g;
                if (BT) {
                    bf[nt][0] = *(const unsigned*)(Sb + n * 40 + kk + tg2);
                    bf[nt][1] = *(const unsigned*)(Sb + n * 40 + kk + 8 + tg2);
                } else {
                    bf[nt][0] = packh(Sb[(kk + tg2) * 136 + n], Sb[(kk + tg2 + 1) * 136 + n]);
                    bf[nt][1] = packh(Sb[(kk + 8 + tg2) * 136 + n], Sb[(kk + 9 + tg2) * 136 + n]);
                }
            }
            #pragma unroll
            for (int mt = 0; mt < 4; mt++)
                #pragma unroll
                for (int nt = 0; nt < 8; nt++)
                    mma16(acc[mt][nt], af[mt], bf[nt]);
        }
        __syncthreads();
    }

    // epilogue
    #pragma unroll
    for (int mt = 0; mt < 4; mt++) {
        int r0 = m0 + wm * 64 + mt * 16 + g;
        #pragma unroll
        for (int nt = 0; nt < 8; nt++) {
            int c = n0 + wn * 64 + nt * 8 + tg2;
            float b0 = bias ? bias[c] : 0.f, b1 = bias ? bias[c + 1] : 0.f;
            float vv[4];
            vv[0] = apply_act(acc[mt][nt][0] + b0, act);
            vv[1] = apply_act(acc[mt][nt][1] + b1, act);
            vv[2] = apply_act(acc[mt][nt][2] + b0, act);
            vv[3] = apply_act(acc[mt][nt][3] + b1, act);
            if (Cf) {
                *reinterpret_cast<float2*>(Cf + co + (size_t)r0 * ldc + c)       = make_float2(vv[0], vv[1]);
                *reinterpret_cast<float2*>(Cf + co + (size_t)(r0 + 8) * ldc + c) = make_float2(vv[2], vv[3]);
            }
            if (Ch) {
                *reinterpret_cast<__half2*>(Ch + co + (size_t)r0 * ldc + c)       = __floats2half2_rn(vv[0], vv[1]);
                *reinterpret_cast<__half2*>(Ch + co + (size_t)(r0 + 8) * ldc + c) = __floats2half2_rn(vv[2], vv[3]);
            }
        }
    }
}

// ---------------- fused attention scores (fp16, virtual K=512) ----------------
// s[i,j] = (sum_k Q[i,k]K[j,k] + sum_k er[k,i]Q[j,k]) / 32; fp32 output.
__global__ void __launch_bounds__(128, 2)
scores_kernel(const __half* __restrict__ q, int ldq,
              const __half* __restrict__ kx, int ldk,
              const __half* __restrict__ er, float* __restrict__ s)
{
    extern __shared__ __half hsm[];

    int bh = blockIdx.z;
    int b = bh >> 2, h = bh & 3;
    const __half* qb = q  + (size_t)b * W_ * ldq + h * DH_;
    const __half* kb = kx + (size_t)b * W_ * ldk + h * DH_;
    float* sb = s + (size_t)bh * W_ * W_;

    int i0 = blockIdx.y * 128, j0 = blockIdx.x * 128;
    int tid  = threadIdx.x;
    int lane = tid & 31, wid = tid >> 5;
    int g = lane >> 2, tg2 = (lane & 3) * 2;
    int wm = wid & 1, wn = wid >> 1;

    float acc[4][8][4] = {};

    auto issue = [&](int t) {
        __half* Sa = hsm + (t % NSTAGE) * STG_H;
        __half* Sb = Sa + A_H;
        int k0 = (t & 7) << 5;
        #pragma unroll
        for (int i = 0; i < 4; i++) {
            int idx = tid + i * 128;
            int r = idx >> 2, c8 = (idx & 3) * 8;
            if (t < 8) {
                cp16(Sa + r * 40 + c8, qb + (size_t)(i0 + r) * ldq + k0 + c8);
                cp16(Sb + r * 40 + c8, kb + (size_t)(j0 + r) * ldk + k0 + c8);
            } else {
                int kr = idx >> 4, cn = (idx & 15) * 8;
                cp16(Sa + kr * 136 + cn, er + (size_t)(k0 + kr) * W_ + i0 + cn);
                cp16(Sb + r * 40 + c8, qb + (size_t)(j0 + r) * ldq + k0 + c8);
            }
        }
        cp_commit();
    };

    issue(0); issue(1);
    for (int t = 0; t < 16; t++) {
        if (t + 2 < 16) issue(t + 2);
        else            cp_commit();
        cp_wait2();
        __syncthreads();

        const __half* Sa = hsm + (t % NSTAGE) * STG_H;
        const __half* Sb = Sa + A_H;
        bool nnA = (t >= 8);
        #pragma unroll
        for (int kk = 0; kk < 32; kk += 16) {
            unsigned af[4][4];
            #pragma unroll
            for (int mt = 0; mt < 4; mt++) {
                int m = wm * 64 + mt * 16 + g;
                if (!nnA) {
                    af[mt][0] = *(const unsigned*)(Sa + m * 40 + kk + tg2);
                    af[mt][1] = *(const unsigned*)(Sa + (m + 8) * 40 + kk + tg2);
                    af[mt][2] = *(const unsigned*)(Sa + m * 40 + kk + 8 + tg2);
                    af[mt][3] = *(const unsigned*)(Sa + (m + 8) * 40 + kk + 8 + tg2);
                } else {
                    af[mt][0] = packh(Sa[(kk + tg2) * 136 + m],     Sa[(kk + tg2 + 1) * 136 + m]);
                    af[mt][1] = packh(Sa[(kk + tg2) * 136 + m + 8], Sa[(kk + tg2 + 1) * 136 + m + 8]);
                    af[mt][2] = packh(Sa[(kk + 8 + tg2) * 136 + m],     Sa[(kk + 9 + tg2) * 136 + m]);
                    af[mt][3] = packh(Sa[(kk + 8 + tg2) * 136 + m + 8], Sa[(kk + 9 + tg2) * 136 + m + 8]);
                }
            }
            unsigned bf[8][2];
            #pragma unroll
            for (int nt = 0; nt < 8; nt++) {
                int n = wn * 64 + nt * 8 + g;
                bf[nt][0] = *(const unsigned*)(Sb + n * 40 + kk + tg2);
                bf[nt][1] = *(const unsigned*)(Sb + n * 40 + kk + 8 + tg2);
            }
            #pragma unroll
            for (int mt = 0; mt < 4; mt++)
                #pragma unroll
                for (int nt = 0; nt < 8; nt++)
                    mma16(acc[mt][nt], af[mt], bf[nt]);
        }
        __syncthreads();
    }

    #pragma unroll
    for (int mt = 0; mt < 4; mt++) {
        int r0 = i0 + wm * 64 + mt * 16 + g;
        #pragma unroll
        for (int nt = 0; nt < 8; nt++) {
            int c = j0 + wn * 64 + nt * 8 + tg2;
            *reinterpret_cast<float2*>(sb + (size_t)r0 * W_ + c) =
                make_float2(acc[mt][nt][0] * 0.03125f, acc[mt][nt][1] * 0.03125f);
            *reinterpret_cast<float2*>(sb + (size_t)(r0 + 8) * W_ + c) =
                make_float2(acc[mt][nt][2] * 0.03125f, acc[mt][nt][3] * 0.03125f);
        }
    }
}

// ---------------- row softmax over n=1024: fp32 in -> fp16 out ----------------
__global__ void softmax_kernel(const float* __restrict__ s, __half* __restrict__ sh)
{
    const int n = W_;
    const float* row = s + (size_t)blockIdx.x * n;
    __half* rowh = sh + (size_t)blockIdx.x * n;
    int tid = threadIdx.x;
    __shared__ float red[8];
    __shared__ float ebuf[W_];

    float m = -3.4e38f;
    for (int i = tid; i < n; i += 256) m = fmaxf(m, row[i]);
    #pragma unroll
    for (int o = 16; o; o >>= 1) m = fmaxf(m, __shfl_xor_sync(0xffffffffu, m, o));
    if ((tid & 31) == 0) red[tid >> 5] = m;
    __syncthreads();
    m = red[0];
    #pragma unroll
    for (int wi = 1; wi < 8; wi++) m = fmaxf(m, red[wi]);

    float sum = 0.f;
    for (int i = tid; i < n; i += 256) { float e = __expf(row[i] - m); ebuf[i] = e; sum += e; }
    #pragma unroll
    for (int o = 16; o; o >>= 1) sum += __shfl_xor_sync(0xffffffffu, sum, o);
    __syncthreads();
    if ((tid & 31) == 0) red[tid >> 5] = sum;
    __syncthreads();
    float tot = 0.f;
    #pragma unroll
    for (int wi = 0; wi < 8; wi++) tot += red[wi];
    float inv = 1.f / tot;
    for (int i = tid; i < n; i += 256) rowh[i] = __float2half_rn(ebuf[i] * inv);
}

// ---------------- fused (a*omega + b(partial) + c) -> LayerNorm; fp32 + optional fp16 out ----------------
__global__ void ln_kernel(const float* __restrict__ a, const float* __restrict__ bsrc,
                          int bw,
                          const float* __restrict__ csrc, const float* __restrict__ omega,
                          const float* __restrict__ g, const float* __restrict__ bet,
                          float* __restrict__ out, __half* __restrict__ outh, int R)
{
    extern __shared__ float sm[];
    __shared__ float rs[8], rq[8];
    size_t base = (size_t)blockIdx.x * R;
    size_t baseb = (size_t)blockIdx.x * bw;
    int tid = threadIdx.x;

    float s = 0.f, sq = 0.f;
    for (int i = tid; i < R; i += 256) {
        float v = a[base + i];
        if (omega) v *= omega[i];
        if (bsrc && i < bw) v += bsrc[baseb + i];
        if (csrc)  v += csrc[base + i];
        sm[i] = v; s += v; sq += v * v;
    }
    #pragma unroll
    for (int o = 16; o; o >>= 1) {
        s  += __shfl_xor_sync(0xffffffffu, s, o);
        sq += __shfl_xor_sync(0xffffffffu, sq, o);
    }
    if ((tid & 31) == 0) { rs[tid >> 5] = s; rq[tid >> 5] = sq; }
    __syncthreads();
    float ts = 0.f, tq = 0.f;
    #pragma unroll
    for (int wi = 0; wi < 8; wi++) { ts += rs[wi]; tq += rq[wi]; }
    float mean = ts / (float)R;
    float var  = tq / (float)R - mean * mean;
    float inv  = rsqrtf(var + 1e-5f);
    for (int i = tid; i < R; i += 256) {
        float v = (sm[i] - mean) * inv * g[i] + bet[i];
        if (out)  out[base + i]  = v;
        if (outh) outh[base + i] = __float2half_rn(v);
    }
}

// ---------------- depthwise conv along w: fp32 in -> fp16 out ----------------
__global__ void dwconv_kernel(const float* __restrict__ in, const float* __restrict__ wk,
                              __half* __restrict__ out, int Ch, int Kt, int pad)
{
    int c = blockIdx.x * blockDim.x + threadIdx.x;
    int w = blockIdx.y, b = blockIdx.z;
    const float* ib = in + ((size_t)b * W_) * Ch;
    float acc = 0.f;
    for (int t = 0; t < Kt; t++) {
        int ww = w + t - pad;
        if (ww >= 0 && ww < W_) acc += ib[(size_t)ww * Ch + c] * wk[c * Kt + t];
    }
    out[((size_t)b * W_ + w) * Ch + c] = __float2half_rn(acc);
}

// =========================================================================
static void launch_hgemm(const __half* A, int lda, long soA, long siA,
                         const __half* Bp, int ldb, long soB, long siB,
                         const float* bias, float* Cf, __half* Chh,
                         int ldc, long soC, long siC,
                         int M, int N, int K, int nz, int zdiv, int BT, int act,
                         cudaStream_t st)
{
    dim3 g(N / 128, M / 128, nz);
    if (BT)
        hgemm_kernel<1><<<g, 128, SMEM_BYTES, st>>>(A, lda, soA, siA, Bp, ldb, soB, siB, bias,
                                                    Cf, Chh, ldc, soC, siC, K, zdiv, act);
    else
        hgemm_kernel<0><<<g, 128, SMEM_BYTES, st>>>(A, lda, soA, siA, Bp, ldb, soB, siB, bias,
                                                    Cf, Chh, ldc, soC, siC, K, zdiv, act);
}

// Attention core on packed half QKV: scores -> softmax -> AV -> out-proj(fp32 out)
static void attn_core(const __half* wh, const float* bias, const __half* erh,
                      __half* qkvh, __half* atth, float* scores, __half* scoresh,
                      float* outp, cudaStream_t st)
{
    const long NK = (long)BINS_ * BINS_;
    const int  M  = B_ * W_;
    dim3 gs(W_ / 128, W_ / 128, B_ * H_);
    scores_kernel<<<gs, 128, SMEM_BYTES, st>>>(qkvh, QKV_, qkvh + BINS_, QKV_, erh, scores);
    softmax_kernel<<<B_ * H_ * W_, 256, 0, st>>>(scores, scoresh);
    launch_hgemm(scoresh, W_, (long)H_ * W_ * W_, (long)W_ * W_,
                 qkvh + 2 * BINS_, QKV_, (long)W_ * QKV_, DH_,
                 nullptr, nullptr, atth,
                 BINS_, (long)W_ * BINS_, DH_,
                 W_, DH_, W_, B_ * H_, H_, 0, 0, st);
    launch_hgemm(atth, BINS_, 0, 0, wh + 3 * NK, BINS_, 0, 0, bias + 3 * BINS_,
                 outp, nullptr, BINS_, 0, 0, M, BINS_, BINS_, 1, 1, 1, 0, st);
}

extern "C" void kernel_launch(void* const* d_in, const int* in_sizes, int n_in,
                              void* d_out, int out_size)
{
    (void)in_sizes; (void)n_in; (void)out_size;

    cudaFuncSetAttribute(hgemm_kernel<0>, cudaFuncAttributeMaxDynamicSharedMemorySize, SMEM_BYTES);
    cudaFuncSetAttribute(hgemm_kernel<1>, cudaFuncAttributeMaxDynamicSharedMemorySize, SMEM_BYTES);
    cudaFuncSetAttribute(scores_kernel,   cudaFuncAttributeMaxDynamicSharedMemorySize, SMEM_BYTES);

    static cudaStream_t s2 = nullptr;
    static cudaEvent_t  ev[6] = {};
    if (!s2) {
        cudaStreamCreateWithFlags(&s2, cudaStreamNonBlocking);
        for (int i = 0; i < 6; i++) cudaEventCreateWithFlags(&ev[i], cudaEventDisableTiming);
    }

    const float* x      = (const float*)d_in[0];
    const float* mem    = (const float*)d_in[1];
    const float* in_w   = (const float*)d_in[2];
    const float* skip_w = (const float*)d_in[3];
    const float* attn_w = (const float*)d_in[4];
    const float* attn_b = (const float*)d_in[5];
    const float* er     = (const float*)d_in[6];
    const float* omega  = (const float*)d_in[7];
    const float* ln_g   = (const float*)d_in[8];
    const float* ln_b   = (const float*)d_in[9];
    const float* ln2_g  = (const float*)d_in[10];
    const float* ln2_b  = (const float*)d_in[11];
    const float* c1L_dw = (const float*)d_in[12];
    const float* c1L_pw = (const float*)d_in[13];
    const float* c1R_dw = (const float*)d_in[14];
    const float* c1R_pw = (const float*)d_in[15];
    const float* c2_dw  = (const float*)d_in[16];
    const float* c2_pw  = (const float*)d_in[17];
    const float* c3_w   = (const float*)d_in[18];
    const float* c4_w   = (const float*)d_in[19];

    float *p_xs, *p_ms, *p_hs, *p_hm, *p_t1, *p_t2, *p_ffa, *p_ffb, *p_scores, *p_scores2;
    __half *p_xsh, *p_msh, *p_qkvh, *p_qkv2h, *p_atth, *p_att2h, *p_xh;
    __half *p_scoresh, *p_scores2h, *p_dwch, *p_dwc2h, *p_dwfh, *p_ffah, *p_wh;
    cudaGetSymbolAddress((void**)&p_xs, g_xs);   cudaGetSymbolAddress((void**)&p_ms, g_ms);
    cudaGetSymbolAddress((void**)&p_hs, g_hs);   cudaGetSymbolAddress((void**)&p_hm, g_hm);
    cudaGetSymbolAddress((void**)&p_t1, g_t1);   cudaGetSymbolAddress((void**)&p_t2, g_t2);
    cudaGetSymbolAddress((void**)&p_ffa, g_ffa); cudaGetSymbolAddress((void**)&p_ffb, g_ffb);
    cudaGetSymbolAddress((void**)&p_scores, g_scores);
    cudaGetSymbolAddress((void**)&p_scores2, g_scores2);
    cudaGetSymbolAddress((void**)&p_xsh, g_xsh); cudaGetSymbolAddress((void**)&p_msh, g_msh);
    cudaGetSymbolAddress((void**)&p_qkvh, g_qkvh);
    cudaGetSymbolAddress((void**)&p_qkv2h, g_qkv2h);
    cudaGetSymbolAddress((void**)&p_atth, g_atth);
    cudaGetSymbolAddress((void**)&p_att2h, g_att2h);
    cudaGetSymbolAddress((void**)&p_xh, g_xh);
    cudaGetSymbolAddress((void**)&p_scoresh, g_scoresh);
    cudaGetSymbolAddress((void**)&p_scores2h, g_scores2h);
    cudaGetSymbolAddress((void**)&p_dwch, g_dwch);
    cudaGetSymbolAddress((void**)&p_dwc2h, g_dwc2h);
    cudaGetSymbolAddress((void**)&p_dwfh, g_dwfh);
    cudaGetSymbolAddress((void**)&p_ffah, g_ffah);
    cudaGetSymbolAddress((void**)&p_wh, g_wh);

    // weights -> fp16, ONE launch
    round_all_kernel<<<(int)((8912896L + 255) / 256), 256>>>(
        (const float4*)attn_w, (const float4*)er, (const float4*)c1L_pw,
        (const float4*)c1R_pw, (const float4*)c2_pw, (const float4*)c3_w,
        (const float4*)c4_w, p_wh);

    const __half* awh  = p_wh + OFF_AW;
    const __half* erh  = p_wh + OFF_ER;
    const __half* c1Lh = p_wh + OFF_C1L;
    const __half* c1Rh = p_wh + OFF_C1R;
    const __half* c2h  = p_wh + OFF_C2;
    const __half* c3h  = p_wh + OFF_C3;
    const __half* c4h  = p_wh + OFF_C4;

    const int  M   = B_ * W_;
    const long ANK = 4L * BINS_ * BINS_;
    const long ERS = (long)DH_ * W_;
    const long NK  = (long)BINS_ * BINS_;

    // input / skip projections (fp32 + fp16)
    {
        dim3 g(W_ / 32, BINS_ / 32, B_), blk(32, 8);
        project_kernel<<<g, blk>>>(x,   in_w,   8, p_xs, p_xsh);
        project_kernel<<<g, blk>>>(mem, skip_w, 8, p_ms, p_msh);
    }

    // self_attn1 (stream 0) || enc_attn1 (s2)
    cudaEventRecord(ev[0], 0);
    cudaStreamWaitEvent(s2, ev[0], 0);
    launch_hgemm(p_xsh, BINS_, 0, 0, awh + 0 * ANK, BINS_, 0, 0, attn_b + 0 * 4 * BINS_,
                 nullptr, p_qkvh, QKV_, 0, 0, M, QKV_, BINS_, 1, 1, 1, 0, 0);
    attn_core(awh + 0 * ANK, attn_b + 0 * 4 * BINS_, erh + 0 * ERS,
              p_qkvh, p_atth, p_scores, p_scoresh, p_hs, 0);
    launch_hgemm(p_xsh, BINS_, 0, 0, awh + 1 * ANK, BINS_, 0, 0, attn_b + 1 * 4 * BINS_,
                 nullptr, p_qkv2h, QKV_, 0, 0, M, BINS_, BINS_, 1, 1, 1, 0, s2);
    launch_hgemm(p_msh, BINS_, 0, 0, awh + 1 * ANK + NK, BINS_, 0, 0, attn_b + 1 * 4 * BINS_ + BINS_,
                 nullptr, p_qkv2h + BINS_, QKV_, 0, 0, M, 2 * BINS_, BINS_, 1, 1, 1, 0, s2);
    attn_core(awh + 1 * ANK, attn_b + 1 * 4 * BINS_, erh + 1 * ERS,
              p_qkv2h, p_att2h, p_scores2, p_scores2h, p_hm, s2);
    cudaEventRecord(ev[1], s2);
    cudaStreamWaitEvent(0, ev[1], 0);

    // x1 = LN(xs*omega0 + hs + hm) -> fp32 only (feeds dwconv)
    ln_kernel<<<M, 256, BINS_ * 4>>>(p_xs, p_hs, BINS_, p_hm, omega + 0 * BINS_,
                                     ln_g + 0 * BINS_, ln_b + 0 * BINS_, p_t1, nullptr, BINS_);

    // c1L (stream 0) || c1R (s2); then enc_attn2 K/V early on s2
    cudaEventRecord(ev[2], 0);
    cudaStreamWaitEvent(s2, ev[2], 0);
    dwconv_kernel<<<dim3(BINS_ / 256, W_, B_), 256>>>(p_t1, c1L_dw, p_dwch, BINS_, 11, 5);
    launch_hgemm(p_dwch, BINS_, 0, 0, c1Lh, BINS_, 0, 0, nullptr, p_ffa, nullptr, FF2_, 0, 0,
                 M, FF2_, BINS_, 1, 1, 1, 1 /*lrelu*/, 0);
    dwconv_kernel<<<dim3(BINS_ / 256, W_, B_), 256, 0, s2>>>(p_t1, c1R_dw, p_dwc2h, BINS_, 7, 3);
    launch_hgemm(p_dwc2h, BINS_, 0, 0, c1Rh, BINS_, 0, 0, nullptr, p_ffb, nullptr, FFH_, 0, 0,
                 M, FFH_, BINS_, 1, 1, 1, 0, s2);
    cudaEventRecord(ev[3], s2);
    cudaStreamWaitEvent(0, ev[3], 0);

    // enc_attn2 K/V (depends only on ms + weights) early on s2
    launch_hgemm(p_msh, BINS_, 0, 0, awh + 3 * ANK + NK, BINS_, 0, 0, attn_b + 3 * 4 * BINS_ + BINS_,
                 nullptr, p_qkv2h + BINS_, QKV_, 0, 0, M, 2 * BINS_, BINS_, 1, 1, 1, 0, s2);
    cudaEventRecord(ev[4], s2);

    // h = LN2(ffa + pad(ffb)), c2 chain
    ln_kernel<<<M, 256, FF2_ * 4>>>(p_ffa, p_ffb, FFH_, nullptr, nullptr, ln2_g, ln2_b,
                                    p_ffa, nullptr, FF2_);
    dwconv_kernel<<<dim3(FF2_ / 256, W_, B_), 256>>>(p_ffa, c2_dw, p_dwfh, FF2_, 7, 3);
    launch_hgemm(p_dwfh, FF2_, 0, 0, c2h, FF2_, 0, 0, nullptr, p_hs, nullptr, BINS_, 0, 0,
                 M, BINS_, FF2_, 1, 1, 1, 0, 0);

    // x2 = LN(x1*omega1 + h) -> fp32 + fp16
    ln_kernel<<<M, 256, BINS_ * 4>>>(p_t1, p_hs, BINS_, nullptr, omega + 1 * BINS_,
                                     ln_g + 1 * BINS_, ln_b + 1 * BINS_, p_t2, p_xh, BINS_);

    // self_attn2 ; x3
    launch_hgemm(p_xh, BINS_, 0, 0, awh + 2 * ANK, BINS_, 0, 0, attn_b + 2 * 4 * BINS_,
                 nullptr, p_qkvh, QKV_, 0, 0, M, QKV_, BINS_, 1, 1, 1, 0, 0);
    attn_core(awh + 2 * ANK, attn_b + 2 * 4 * BINS_, erh + 2 * ERS,
              p_qkvh, p_atth, p_scores, p_scoresh, p_hs, 0);
    ln_kernel<<<M, 256, BINS_ * 4>>>(p_t2, p_hs, BINS_, nullptr, omega + 2 * BINS_,
                                     ln_g + 2 * BINS_, ln_b + 2 * BINS_, p_t1, p_xh, BINS_);

    // enc_attn2: Q on stream 0 (K/V ready via ev[4]); x4
    launch_hgemm(p_xh, BINS_, 0, 0, awh + 3 * ANK, BINS_, 0, 0, attn_b + 3 * 4 * BINS_,
                 nullptr, p_qkv2h, QKV_, 0, 0, M, BINS_, BINS_, 1, 1, 1, 0, 0);
    cudaStreamWaitEvent(0, ev[4], 0);
    attn_core(awh + 3 * ANK, attn_b + 3 * 4 * BINS_, erh + 3 * ERS,
              p_qkv2h, p_atth, p_scores, p_scoresh, p_hs, 0);
    ln_kernel<<<M, 256, BINS_ * 4>>>(p_t1, p_hs, BINS_, nullptr, omega + 3 * BINS_,
                                     ln_g + 3 * BINS_, ln_b + 3 * BINS_, p_t2, p_xh, BINS_);

    // FFN: silu(x4 @ c3^T) @ c4^T
    launch_hgemm(p_xh, BINS_, 0, 0, c3h, BINS_, 0, 0, nullptr, nullptr, p_ffah, FF2_, 0, 0,
                 M, FF2_, BINS_, 1, 1, 1, 2 /*silu*/, 0);
    launch_hgemm(p_ffah, FF2_, 0, 0, c4h, FF2_, 0, 0, nullptr, p_hs, nullptr, BINS_, 0, 0,
                 M, BINS_, FF2_, 1, 1, 1, 0, 0);

    // out = LN(x4*omega4 + h) -> fp32; transpose
    ln_kernel<<<M, 256, BINS_ * 4>>>(p_t2, p_hs, BINS_, nullptr, omega + 4 * BINS_,
                                     ln_g + 4 * BINS_, ln_b + 4 * BINS_, p_t1, nullptr, BINS_);
    {
        dim3 g(W_ / 32, BINS_ / 32, B_), blk(32, 8);
        transpose_out_kernel<<<g, blk>>>(p_t1, (float*)d_out);
    }
}

// round 17
// speedup vs baseline: 1.9198x; 1.1196x over previous
#include <cuda_runtime.h>
#include <cuda_fp16.h>
#include <math.h>

#define B_    4
#define W_    1024
#define BINS_ 1024
#define H_    4
#define DH_   256
#define FF2_  4096
#define FFH_  1024
#define QKV_  (3 * BINS_)

// fp16 GEMM stages: A 128x40 halfs (5120) + B 5120 halfs per stage, 3 stages
// (40-half row stride = 80 B; NN B uses 136-half rows = 272 B; both 16B-multiples)
#define A_H     5120
#define STG_H   10240
#define NSTAGE  3
#define SMEM_BYTES (NSTAGE * STG_H * 2)

// ---------------- scratch (static device memory; no allocations) ----------------
__device__ float g_xs  [(size_t)B_*W_*BINS_];
__device__ float g_ms  [(size_t)B_*W_*BINS_];
__device__ float g_hs  [(size_t)B_*W_*BINS_];
__device__ float g_hm  [(size_t)B_*W_*BINS_];
__device__ float g_t1  [(size_t)B_*W_*BINS_];
__device__ float g_t2  [(size_t)B_*W_*BINS_];
__device__ float g_ffa [(size_t)B_*W_*FF2_];
__device__ float g_ffb [(size_t)B_*W_*FFH_];
__device__ float g_scores [(size_t)B_*H_*W_*W_];
__device__ float g_scores2[(size_t)B_*H_*W_*W_];

__device__ __half g_xsh [(size_t)B_*W_*BINS_];
__device__ __half g_msh [(size_t)B_*W_*BINS_];
__device__ __half g_qkvh [(size_t)B_*W_*QKV_];
__device__ __half g_qkv2h[(size_t)B_*W_*QKV_];
__device__ __half g_atth [(size_t)B_*W_*BINS_];
__device__ __half g_att2h[(size_t)B_*W_*BINS_];
__device__ __half g_xh   [(size_t)B_*W_*BINS_];
__device__ __half g_scoresh [(size_t)B_*H_*W_*W_];
__device__ __half g_scores2h[(size_t)B_*H_*W_*W_];
__device__ __half g_dwch [(size_t)B_*W_*BINS_];
__device__ __half g_dwc2h[(size_t)B_*W_*BINS_];
__device__ __half g_dwfh [(size_t)B_*W_*FF2_];
__device__ __half g_ffah [(size_t)B_*W_*FF2_];

// half weights: attn_w | er | c1L_pw | c1R_pw | c2_pw | c3_w | c4_w (element offsets)
#define OFF_AW   0L
#define OFF_ER   16777216L
#define OFF_C1L  17825792L
#define OFF_C1R  22020096L
#define OFF_C2   23068672L
#define OFF_C3   27262976L
#define OFF_C4   31457280L
#define WH_TOTAL 35651584L
__device__ __half g_wh[WH_TOTAL];

// ---------------- helpers ----------------
__device__ __forceinline__ void mma16(float* d, const unsigned* a, const unsigned* b) {
    asm("mma.sync.aligned.m16n8k16.row.col.f32.f16.f16.f32 "
        "{%0,%1,%2,%3},{%4,%5,%6,%7},{%8,%9},{%0,%1,%2,%3};"
        : "+f"(d[0]), "+f"(d[1]), "+f"(d[2]), "+f"(d[3])
        : "r"(a[0]), "r"(a[1]), "r"(a[2]), "r"(a[3]), "r"(b[0]), "r"(b[1]));
}

__device__ __forceinline__ void ldsm4(unsigned* r, unsigned a) {
    asm volatile("ldmatrix.sync.aligned.m8n8.x4.shared.b16 {%0,%1,%2,%3}, [%4];"
        : "=r"(r[0]), "=r"(r[1]), "=r"(r[2]), "=r"(r[3]) : "r"(a));
}
__device__ __forceinline__ void ldsm4t(unsigned* r, unsigned a) {
    asm volatile("ldmatrix.sync.aligned.m8n8.x4.trans.shared.b16 {%0,%1,%2,%3}, [%4];"
        : "=r"(r[0]), "=r"(r[1]), "=r"(r[2]), "=r"(r[3]) : "r"(a));
}

__device__ __forceinline__ unsigned sm_u32(const void* p) {
    return (unsigned)__cvta_generic_to_shared(p);
}

__device__ __forceinline__ void cp16(void* smem_dst, const void* gsrc) {
    unsigned d = (unsigned)__cvta_generic_to_shared(smem_dst);
    asm volatile("cp.async.cg.shared.global [%0], [%1], 16;" :: "r"(d), "l"(gsrc));
}
__device__ __forceinline__ void cp_commit() { asm volatile("cp.async.commit_group;"); }
__device__ __forceinline__ void cp_wait2()  { asm volatile("cp.async.wait_group 2;"); }

__device__ __forceinline__ float apply_act(float v, int act) {
    if (act == 1) return (v >= 0.f) ? v : 0.01f * v;
    if (act == 2) return v / (1.f + __expf(-v));
    return v;
}

// ---------------- fp16 conversion of ALL weight operands in ONE launch ----------------
__global__ void round_all_kernel(const float4* __restrict__ s0, const float4* __restrict__ s1,
                                 const float4* __restrict__ s2, const float4* __restrict__ s3,
                                 const float4* __restrict__ s4, const float4* __restrict__ s5,
                                 const float4* __restrict__ s6, __half* __restrict__ out)
{
    long i = (long)blockIdx.x * 256 + threadIdx.x;
    if (i >= 8912896L) return;
    const float4* src;
    long rel = i;
    if      (i < 4194304L) { src = s0; rel = i; }
    else if (i < 4456448L) { src = s1; rel = i - 4194304L; }
    else if (i < 5505024L) { src = s2; rel = i - 4456448L; }
    else if (i < 5767168L) { src = s3; rel = i - 5505024L; }
    else if (i < 6815744L) { src = s4; rel = i - 5767168L; }
    else if (i < 7864320L) { src = s5; rel = i - 6815744L; }
    else                   { src = s6; rel = i - 7864320L; }
    float4 v = src[rel];
    __half2 lo = __floats2half2_rn(v.x, v.y);
    __half2 hi = __floats2half2_rn(v.z, v.w);
    uint2 u;
    u.x = *reinterpret_cast<unsigned*>(&lo);
    u.y = *reinterpret_cast<unsigned*>(&hi);
    reinterpret_cast<uint2*>(out)[i] = u;
}

// ---------------- input projection -> fp32 + fp16 outputs ----------------
__global__ void project_kernel(const float* __restrict__ x, const float* __restrict__ wc,
                               int Cn, float* __restrict__ out, __half* __restrict__ outh)
{
    __shared__ float tile[32][33];
    int b  = blockIdx.z;
    int h0 = blockIdx.y * 32, w0 = blockIdx.x * 32;
    int tx = threadIdx.x, ty = threadIdx.y;   // 32 x 8

    float wreg[8];
    #pragma unroll
    for (int c = 0; c < 8; c++) wreg[c] = (c < Cn) ? wc[c] : 0.f;

    #pragma unroll
    for (int r = 0; r < 4; r++) {
        int h = h0 + ty + r * 8;
        float acc = 0.f;
        #pragma unroll
        for (int c = 0; c < 8; c++)
            acc += x[(((size_t)b * Cn + c) * BINS_ + h) * W_ + (w0 + tx)] * wreg[c];
        tile[ty + r * 8][tx] = acc;
    }
    __syncthreads();
    #pragma unroll
    for (int r = 0; r < 4; r++) {
        int w = w0 + ty + r * 8;
        size_t idx = ((size_t)b * W_ + w) * BINS_ + (h0 + tx);
        float v = tile[tx][ty + r * 8];
        out[idx]  = v;
        outh[idx] = __float2half_rn(v);
    }
}

// ---------------- final transpose ----------------
__global__ void transpose_out_kernel(const float* __restrict__ in, float* __restrict__ out)
{
    __shared__ float tile[32][33];
    int b  = blockIdx.z;
    int w0 = blockIdx.x * 32, h0 = blockIdx.y * 32;
    int tx = threadIdx.x, ty = threadIdx.y;

    #pragma unroll
    for (int r = 0; r < 4; r++)
        tile[ty + r * 8][tx] = in[((size_t)b * W_ + (w0 + ty + r * 8)) * BINS_ + (h0 + tx)];
    __syncthreads();
    #pragma unroll
    for (int r = 0; r < 4; r++)
        out[((size_t)b * BINS_ + (h0 + ty + r * 8)) * W_ + (w0 + tx)] = tile[tx][ty + r * 8];
}

// ---------------- fp16 tensor-core GEMM (m16n8k16 + ldmatrix), 64x64 warp tiles ----------------
// 128 threads = 4 warps 2x2; CTA tile 128x128; K-chunk 32 (2 k16 steps).
// BT=1: B is [N,K] half (NT); BT=0: B is [K,N] half (NN, read via ldmatrix.trans).
// Output: Cf (fp32) and/or Ch (fp16), same ldc.
template <int BT>
__global__ void __launch_bounds__(128, 2)
hgemm_kernel(const __half* __restrict__ A, int lda, long soA, long siA,
             const __half* __restrict__ Bp, int ldb, long soB, long siB,
             const float* __restrict__ bias,
             float* __restrict__ Cf, __half* __restrict__ Ch,
             int ldc, long soC, long siC,
             int K, int zdiv, int act)
{
    extern __shared__ __half hsm[];

    int z = blockIdx.z;
    long zo = z / zdiv, zi = z % zdiv;
    A  += zo * soA + zi * siA;
    Bp += zo * soB + zi * siB;
    long co = zo * soC + zi * siC;

    int m0 = blockIdx.y * 128, n0 = blockIdx.x * 128;
    int tid  = threadIdx.x;
    int lane = tid & 31, wid = tid >> 5;
    int g = lane >> 2, tg2 = (lane & 3) * 2;
    int lr = lane & 7, q = lane >> 3;      // ldmatrix lane decomposition
    int wm = wid & 1, wn = wid >> 1;

    float acc[4][8][4] = {};

    auto issue = [&](int k0, int s) {
        __half* Sa = hsm + s * STG_H;
        __half* Sb = Sa + A_H;
        #pragma unroll
        for (int i = 0; i < 4; i++) {
            int idx = tid + i * 128;
            int r = idx >> 2, c8 = (idx & 3) * 8;
            cp16(Sa + r * 40 + c8, A + (size_t)(m0 + r) * lda + k0 + c8);
            if (BT) {
                cp16(Sb + r * 40 + c8, Bp + (size_t)(n0 + r) * ldb + k0 + c8);
            } else {
                int kr = idx >> 4, cn = (idx & 15) * 8;
                cp16(Sb + kr * 136 + cn, Bp + (size_t)(k0 + kr) * ldb + n0 + cn);
            }
        }
        cp_commit();
    };

    int nc = K >> 5;
    issue(0, 0);
    if (nc > 1) issue(32, 1);
    for (int ch = 0; ch < nc; ch++) {
        if (ch + 2 < nc) issue((ch + 2) << 5, (ch + 2) % NSTAGE);
        else             cp_commit();
        cp_wait2();
        __syncthreads();

        const __half* Sa = hsm + (ch % NSTAGE) * STG_H;
        const __half* Sb = Sa + A_H;
        unsigned sa = sm_u32(Sa), sb = sm_u32(Sb);

        unsigned af[2][4][4], bf[2][8][2];
        auto ldf = [&](int kk, int bi) {
            #pragma unroll
            for (int mt = 0; mt < 4; mt++) {
                int m = wm * 64 + mt * 16;
                ldsm4(af[bi][mt],
                      sa + (unsigned)(((m + (q & 1) * 8 + lr) * 40 + kk + (q >> 1) * 8) * 2));
            }
            #pragma unroll
            for (int p = 0; p < 4; p++) {
                int nb = wn * 64 + p * 16;
                unsigned r[4];
                if (BT) {
                    ldsm4(r, sb + (unsigned)(((nb + (q >> 1) * 8 + lr) * 40 + kk + (q & 1) * 8) * 2));
                } else {
                    ldsm4t(r, sb + (unsigned)(((kk + (q & 1) * 8 + lr) * 136 + nb + (q >> 1) * 8) * 2));
                }
                bf[bi][p * 2][0]     = r[0]; bf[bi][p * 2][1]     = r[1];
                bf[bi][p * 2 + 1][0] = r[2]; bf[bi][p * 2 + 1][1] = r[3];
            }
        };

        ldf(0, 0);
        #pragma unroll
        for (int kk8 = 0; kk8 < 2; kk8++) {
            if (kk8 < 1) ldf(16, 1);
            #pragma unroll
            for (int mt = 0; mt < 4; mt++)
                #pragma unroll
                for (int nt = 0; nt < 8; nt++)
                    mma16(acc[mt][nt], af[kk8][mt], bf[kk8][nt]);
        }
        __syncthreads();
    }

    // epilogue
    #pragma unroll
    for (int mt = 0; mt < 4; mt++) {
        int r0 = m0 + wm * 64 + mt * 16 + g;
        #pragma unroll
        for (int nt = 0; nt < 8; nt++) {
            int c = n0 + wn * 64 + nt * 8 + tg2;
            float b0 = bias ? bias[c] : 0.f, b1 = bias ? bias[c + 1] : 0.f;
            float vv[4];
            vv[0] = apply_act(acc[mt][nt][0] + b0, act);
            vv[1] = apply_act(acc[mt][nt][1] + b1, act);
            vv[2] = apply_act(acc[mt][nt][2] + b0, act);
            vv[3] = apply_act(acc[mt][nt][3] + b1, act);
            if (Cf) {
                *reinterpret_cast<float2*>(Cf + co + (size_t)r0 * ldc + c)       = make_float2(vv[0], vv[1]);
                *reinterpret_cast<float2*>(Cf + co + (size_t)(r0 + 8) * ldc + c) = make_float2(vv[2], vv[3]);
            }
            if (Ch) {
                *reinterpret_cast<__half2*>(Ch + co + (size_t)r0 * ldc + c)       = __floats2half2_rn(vv[0], vv[1]);
                *reinterpret_cast<__half2*>(Ch + co + (size_t)(r0 + 8) * ldc + c) = __floats2half2_rn(vv[2], vv[3]);
            }
        }
    }
}

// ---------------- fused attention scores (fp16 + ldmatrix, virtual K=512) ----------------
// s[i,j] = (sum_k Q[i,k]K[j,k] + sum_k er[k,i]Q[j,k]) / 32; fp32 output.
__global__ void __launch_bounds__(128, 2)
scores_kernel(const __half* __restrict__ q, int ldq,
              const __half* __restrict__ kx, int ldk,
              const __half* __restrict__ er, float* __restrict__ s)
{
    extern __shared__ __half hsm[];

    int bh = blockIdx.z;
    int b = bh >> 2, h = bh & 3;
    const __half* qb = q  + (size_t)b * W_ * ldq + h * DH_;
    const __half* kb = kx + (size_t)b * W_ * ldk + h * DH_;
    float* sb = s + (size_t)bh * W_ * W_;

    int i0 = blockIdx.y * 128, j0 = blockIdx.x * 128;
    int tid  = threadIdx.x;
    int lane = tid & 31, wid = tid >> 5;
    int g = lane >> 2, tg2 = (lane & 3) * 2;
    int lr = lane & 7, qq = lane >> 3;
    int wm = wid & 1, wn = wid >> 1;

    float acc[4][8][4] = {};

    auto issue = [&](int t) {
        __half* Sa = hsm + (t % NSTAGE) * STG_H;
        __half* Sb = Sa + A_H;
        int k0 = (t & 7) << 5;
        #pragma unroll
        for (int i = 0; i < 4; i++) {
            int idx = tid + i * 128;
            int r = idx >> 2, c8 = (idx & 3) * 8;
            if (t < 8) {
                cp16(Sa + r * 40 + c8, qb + (size_t)(i0 + r) * ldq + k0 + c8);
                cp16(Sb + r * 40 + c8, kb + (size_t)(j0 + r) * ldk + k0 + c8);
            } else {
                int kr = idx >> 4, cn = (idx & 15) * 8;
                cp16(Sa + kr * 136 + cn, er + (size_t)(k0 + kr) * W_ + i0 + cn);
                cp16(Sb + r * 40 + c8, qb + (size_t)(j0 + r) * ldq + k0 + c8);
            }
        }
        cp_commit();
    };

    issue(0); issue(1);
    for (int t = 0; t < 16; t++) {
        if (t + 2 < 16) issue(t + 2);
        else            cp_commit();
        cp_wait2();
        __syncthreads();

        const __half* Sa = hsm + (t % NSTAGE) * STG_H;
        const __half* Sb = Sa + A_H;
        unsigned sa = sm_u32(Sa), sbu = sm_u32(Sb);
        bool nnA = (t >= 8);

        unsigned af[2][4][4], bf[2][8][2];
        auto ldf = [&](int kk, int bi) {
            #pragma unroll
            for (int mt = 0; mt < 4; mt++) {
                int m = wm * 64 + mt * 16;
                if (!nnA) {
                    ldsm4(af[bi][mt],
                          sa + (unsigned)(((m + (qq & 1) * 8 + lr) * 40 + kk + (qq >> 1) * 8) * 2));
                } else {
                    ldsm4t(af[bi][mt],
                           sa + (unsigned)(((kk + (qq >> 1) * 8 + lr) * 136 + m + (qq & 1) * 8) * 2));
                }
            }
            #pragma unroll
            for (int p = 0; p < 4; p++) {
                int nb = wn * 64 + p * 16;
                unsigned r[4];
                ldsm4(r, sbu + (unsigned)(((nb + (qq >> 1) * 8 + lr) * 40 + kk + (qq & 1) * 8) * 2));
                bf[bi][p * 2][0]     = r[0]; bf[bi][p * 2][1]     = r[1];
                bf[bi][p * 2 + 1][0] = r[2]; bf[bi][p * 2 + 1][1] = r[3];
            }
        };

        ldf(0, 0);
        #pragma unroll
        for (int kk8 = 0; kk8 < 2; kk8++) {
            if (kk8 < 1) ldf(16, 1);
            #pragma unroll
            for (int mt = 0; mt < 4; mt++)
                #pragma unroll
                for (int nt = 0; nt < 8; nt++)
                    mma16(acc[mt][nt], af[kk8][mt], bf[kk8][nt]);
        }
        __syncthreads();
    }

    #pragma unroll
    for (int mt = 0; mt < 4; mt++) {
        int r0 = i0 + wm * 64 + mt * 16 + g;
        #pragma unroll
        for (int nt = 0; nt < 8; nt++) {
            int c = j0 + wn * 64 + nt * 8 + tg2;
            *reinterpret_cast<float2*>(sb + (size_t)r0 * W_ + c) =
                make_float2(acc[mt][nt][0] * 0.03125f, acc[mt][nt][1] * 0.03125f);
            *reinterpret_cast<float2*>(sb + (size_t)(r0 + 8) * W_ + c) =
                make_float2(acc[mt][nt][2] * 0.03125f, acc[mt][nt][3] * 0.03125f);
        }
    }
}

// ---------------- row softmax over n=1024: fp32 in -> fp16 out ----------------
__global__ void softmax_kernel(const float* __restrict__ s, __half* __restrict__ sh)
{
    const int n = W_;
    const float* row = s + (size_t)blockIdx.x * n;
    __half* rowh = sh + (size_t)blockIdx.x * n;
    int tid = threadIdx.x;
    __shared__ float red[8];
    __shared__ float ebuf[W_];

    float m = -3.4e38f;
    for (int i = tid; i < n; i += 256) m = fmaxf(m, row[i]);
    #pragma unroll
    for (int o = 16; o; o >>= 1) m = fmaxf(m, __shfl_xor_sync(0xffffffffu, m, o));
    if ((tid & 31) == 0) red[tid >> 5] = m;
    __syncthreads();
    m = red[0];
    #pragma unroll
    for (int wi = 1; wi < 8; wi++) m = fmaxf(m, red[wi]);

    float sum = 0.f;
    for (int i = tid; i < n; i += 256) { float e = __expf(row[i] - m); ebuf[i] = e; sum += e; }
    #pragma unroll
    for (int o = 16; o; o >>= 1) sum += __shfl_xor_sync(0xffffffffu, sum, o);
    __syncthreads();
    if ((tid & 31) == 0) red[tid >> 5] = sum;
    __syncthreads();
    float tot = 0.f;
    #pragma unroll
    for (int wi = 0; wi < 8; wi++) tot += red[wi];
    float inv = 1.f / tot;
    for (int i = tid; i < n; i += 256) rowh[i] = __float2half_rn(ebuf[i] * inv);
}

// ---------------- fused (a*omega + b(partial) + c) -> LayerNorm; fp32 + optional fp16 out ----------------
__global__ void ln_kernel(const float* __restrict__ a, const float* __restrict__ bsrc,
                          int bw,
                          const float* __restrict__ csrc, const float* __restrict__ omega,
                          const float* __restrict__ g, const float* __restrict__ bet,
                          float* __restrict__ out, __half* __restrict__ outh, int R)
{
    extern __shared__ float sm[];
    __shared__ float rs[8], rq[8];
    size_t base = (size_t)blockIdx.x * R;
    size_t baseb = (size_t)blockIdx.x * bw;
    int tid = threadIdx.x;

    float s = 0.f, sq = 0.f;
    for (int i = tid; i < R; i += 256) {
        float v = a[base + i];
        if (omega) v *= omega[i];
        if (bsrc && i < bw) v += bsrc[baseb + i];
        if (csrc)  v += csrc[base + i];
        sm[i] = v; s += v; sq += v * v;
    }
    #pragma unroll
    for (int o = 16; o; o >>= 1) {
        s  += __shfl_xor_sync(0xffffffffu, s, o);
        sq += __shfl_xor_sync(0xffffffffu, sq, o);
    }
    if ((tid & 31) == 0) { rs[tid >> 5] = s; rq[tid >> 5] = sq; }
    __syncthreads();
    float ts = 0.f, tq = 0.f;
    #pragma unroll
    for (int wi = 0; wi < 8; wi++) { ts += rs[wi]; tq += rq[wi]; }
    float mean = ts / (float)R;
    float var  = tq / (float)R - mean * mean;
    float inv  = rsqrtf(var + 1e-5f);
    for (int i = tid; i < R; i += 256) {
        float v = (sm[i] - mean) * inv * g[i] + bet[i];
        if (out)  out[base + i]  = v;
        if (outh) outh[base + i] = __float2half_rn(v);
    }
}

// ---------------- depthwise conv along w: fp32 in -> fp16 out ----------------
__global__ void dwconv_kernel(const float* __restrict__ in, const float* __restrict__ wk,
                              __half* __restrict__ out, int Ch, int Kt, int pad)
{
    int c = blockIdx.x * blockDim.x + threadIdx.x;
    int w = blockIdx.y, b = blockIdx.z;
    const float* ib = in + ((size_t)b * W_) * Ch;
    float acc = 0.f;
    for (int t = 0; t < Kt; t++) {
        int ww = w + t - pad;
        if (ww >= 0 && ww < W_) acc += ib[(size_t)ww * Ch + c] * wk[c * Kt + t];
    }
    out[((size_t)b * W_ + w) * Ch + c] = __float2half_rn(acc);
}

// =========================================================================
static void launch_hgemm(const __half* A, int lda, long soA, long siA,
                         const __half* Bp, int ldb, long soB, long siB,
                         const float* bias, float* Cf, __half* Chh,
                         int ldc, long soC, long siC,
                         int M, int N, int K, int nz, int zdiv, int BT, int act,
                         cudaStream_t st)
{
    dim3 g(N / 128, M / 128, nz);
    if (BT)
        hgemm_kernel<1><<<g, 128, SMEM_BYTES, st>>>(A, lda, soA, siA, Bp, ldb, soB, siB, bias,
                                                    Cf, Chh, ldc, soC, siC, K, zdiv, act);
    else
        hgemm_kernel<0><<<g, 128, SMEM_BYTES, st>>>(A, lda, soA, siA, Bp, ldb, soB, siB, bias,
                                                    Cf, Chh, ldc, soC, siC, K, zdiv, act);
}

// Attention core on packed half QKV: scores -> softmax -> AV -> out-proj(fp32 out)
static void attn_core(const __half* wh, const float* bias, const __half* erh,
                      __half* qkvh, __half* atth, float* scores, __half* scoresh,
                      float* outp, cudaStream_t st)
{
    const long NK = (long)BINS_ * BINS_;
    const int  M  = B_ * W_;
    dim3 gs(W_ / 128, W_ / 128, B_ * H_);
    scores_kernel<<<gs, 128, SMEM_BYTES, st>>>(qkvh, QKV_, qkvh + BINS_, QKV_, erh, scores);
    softmax_kernel<<<B_ * H_ * W_, 256, 0, st>>>(scores, scoresh);
    launch_hgemm(scoresh, W_, (long)H_ * W_ * W_, (long)W_ * W_,
                 qkvh + 2 * BINS_, QKV_, (long)W_ * QKV_, DH_,
                 nullptr, nullptr, atth,
                 BINS_, (long)W_ * BINS_, DH_,
                 W_, DH_, W_, B_ * H_, H_, 0, 0, st);
    launch_hgemm(atth, BINS_, 0, 0, wh + 3 * NK, BINS_, 0, 0, bias + 3 * BINS_,
                 outp, nullptr, BINS_, 0, 0, M, BINS_, BINS_, 1, 1, 1, 0, st);
}

extern "C" void kernel_launch(void* const* d_in, const int* in_sizes, int n_in,
                              void* d_out, int out_size)
{
    (void)in_sizes; (void)n_in; (void)out_size;

    cudaFuncSetAttribute(hgemm_kernel<0>, cudaFuncAttributeMaxDynamicSharedMemorySize, SMEM_BYTES);
    cudaFuncSetAttribute(hgemm_kernel<1>, cudaFuncAttributeMaxDynamicSharedMemorySize, SMEM_BYTES);
    cudaFuncSetAttribute(scores_kernel,   cudaFuncAttributeMaxDynamicSharedMemorySize, SMEM_BYTES);

    static cudaStream_t s2 = nullptr;
    static cudaEvent_t  ev[6] = {};
    if (!s2) {
        cudaStreamCreateWithFlags(&s2, cudaStreamNonBlocking);
        for (int i = 0; i < 6; i++) cudaEventCreateWithFlags(&ev[i], cudaEventDisableTiming);
    }

    const float* x      = (const float*)d_in[0];
    const float* mem    = (const float*)d_in[1];
    const float* in_w   = (const float*)d_in[2];
    const float* skip_w = (const float*)d_in[3];
    const float* attn_w = (const float*)d_in[4];
    const float* attn_b = (const float*)d_in[5];
    const float* er     = (const float*)d_in[6];
    const float* omega  = (const float*)d_in[7];
    const float* ln_g   = (const float*)d_in[8];
    const float* ln_b   = (const float*)d_in[9];
    const float* ln2_g  = (const float*)d_in[10];
    const float* ln2_b  = (const float*)d_in[11];
    const float* c1L_dw = (const float*)d_in[12];
    const float* c1L_pw = (const float*)d_in[13];
    const float* c1R_dw = (const float*)d_in[14];
    const float* c1R_pw = (const float*)d_in[15];
    const float* c2_dw  = (const float*)d_in[16];
    const float* c2_pw  = (const float*)d_in[17];
    const float* c3_w   = (const float*)d_in[18];
    const float* c4_w   = (const float*)d_in[19];

    float *p_xs, *p_ms, *p_hs, *p_hm, *p_t1, *p_t2, *p_ffa, *p_ffb, *p_scores, *p_scores2;
    __half *p_xsh, *p_msh, *p_qkvh, *p_qkv2h, *p_atth, *p_att2h, *p_xh;
    __half *p_scoresh, *p_scores2h, *p_dwch, *p_dwc2h, *p_dwfh, *p_ffah, *p_wh;
    cudaGetSymbolAddress((void**)&p_xs, g_xs);   cudaGetSymbolAddress((void**)&p_ms, g_ms);
    cudaGetSymbolAddress((void**)&p_hs, g_hs);   cudaGetSymbolAddress((void**)&p_hm, g_hm);
    cudaGetSymbolAddress((void**)&p_t1, g_t1);   cudaGetSymbolAddress((void**)&p_t2, g_t2);
    cudaGetSymbolAddress((void**)&p_ffa, g_ffa); cudaGetSymbolAddress((void**)&p_ffb, g_ffb);
    cudaGetSymbolAddress((void**)&p_scores, g_scores);
    cudaGetSymbolAddress((void**)&p_scores2, g_scores2);
    cudaGetSymbolAddress((void**)&p_xsh, g_xsh); cudaGetSymbolAddress((void**)&p_msh, g_msh);
    cudaGetSymbolAddress((void**)&p_qkvh, g_qkvh);
    cudaGetSymbolAddress((void**)&p_qkv2h, g_qkv2h);
    cudaGetSymbolAddress((void**)&p_atth, g_atth);
    cudaGetSymbolAddress((void**)&p_att2h, g_att2h);
    cudaGetSymbolAddress((void**)&p_xh, g_xh);
    cudaGetSymbolAddress((void**)&p_scoresh, g_scoresh);
    cudaGetSymbolAddress((void**)&p_scores2h, g_scores2h);
    cudaGetSymbolAddress((void**)&p_dwch, g_dwch);
    cudaGetSymbolAddress((void**)&p_dwc2h, g_dwc2h);
    cudaGetSymbolAddress((void**)&p_dwfh, g_dwfh);
    cudaGetSymbolAddress((void**)&p_ffah, g_ffah);
    cudaGetSymbolAddress((void**)&p_wh, g_wh);

    // weights -> fp16, ONE launch
    round_all_kernel<<<(int)((8912896L + 255) / 256), 256>>>(
        (const float4*)attn_w, (const float4*)er, (const float4*)c1L_pw,
        (const float4*)c1R_pw, (const float4*)c2_pw, (const float4*)c3_w,
        (const float4*)c4_w, p_wh);

    const __half* awh  = p_wh + OFF_AW;
    const __half* erh  = p_wh + OFF_ER;
    const __half* c1Lh = p_wh + OFF_C1L;
    const __half* c1Rh = p_wh + OFF_C1R;
    const __half* c2h  = p_wh + OFF_C2;
    const __half* c3h  = p_wh + OFF_C3;
    const __half* c4h  = p_wh + OFF_C4;

    const int  M   = B_ * W_;
    const long ANK = 4L * BINS_ * BINS_;
    const long ERS = (long)DH_ * W_;
    const long NK  = (long)BINS_ * BINS_;

    // input / skip projections (fp32 + fp16)
    {
        dim3 g(W_ / 32, BINS_ / 32, B_), blk(32, 8);
        project_kernel<<<g, blk>>>(x,   in_w,   8, p_xs, p_xsh);
        project_kernel<<<g, blk>>>(mem, skip_w, 8, p_ms, p_msh);
    }

    // self_attn1 (stream 0) || enc_attn1 (s2)
    cudaEventRecord(ev[0], 0);
    cudaStreamWaitEvent(s2, ev[0], 0);
    launch_hgemm(p_xsh, BINS_, 0, 0, awh + 0 * ANK, BINS_, 0, 0, attn_b + 0 * 4 * BINS_,
                 nullptr, p_qkvh, QKV_, 0, 0, M, QKV_, BINS_, 1, 1, 1, 0, 0);
    attn_core(awh + 0 * ANK, attn_b + 0 * 4 * BINS_, erh + 0 * ERS,
              p_qkvh, p_atth, p_scores, p_scoresh, p_hs, 0);
    launch_hgemm(p_xsh, BINS_, 0, 0, awh + 1 * ANK, BINS_, 0, 0, attn_b + 1 * 4 * BINS_,
                 nullptr, p_qkv2h, QKV_, 0, 0, M, BINS_, BINS_, 1, 1, 1, 0, s2);
    launch_hgemm(p_msh, BINS_, 0, 0, awh + 1 * ANK + NK, BINS_, 0, 0, attn_b + 1 * 4 * BINS_ + BINS_,
                 nullptr, p_qkv2h + BINS_, QKV_, 0, 0, M, 2 * BINS_, BINS_, 1, 1, 1, 0, s2);
    attn_core(awh + 1 * ANK, attn_b + 1 * 4 * BINS_, erh + 1 * ERS,
              p_qkv2h, p_att2h, p_scores2, p_scores2h, p_hm, s2);
    cudaEventRecord(ev[1], s2);
    cudaStreamWaitEvent(0, ev[1], 0);

    // x1 = LN(xs*omega0 + hs + hm) -> fp32 only (feeds dwconv)
    ln_kernel<<<M, 256, BINS_ * 4>>>(p_xs, p_hs, BINS_, p_hm, omega + 0 * BINS_,
                                     ln_g + 0 * BINS_, ln_b + 0 * BINS_, p_t1, nullptr, BINS_);

    // c1L (stream 0) || c1R (s2); then enc_attn2 K/V early on s2
    cudaEventRecord(ev[2], 0);
    cudaStreamWaitEvent(s2, ev[2], 0);
    dwconv_kernel<<<dim3(BINS_ / 256, W_, B_), 256>>>(p_t1, c1L_dw, p_dwch, BINS_, 11, 5);
    launch_hgemm(p_dwch, BINS_, 0, 0, c1Lh, BINS_, 0, 0, nullptr, p_ffa, nullptr, FF2_, 0, 0,
                 M, FF2_, BINS_, 1, 1, 1, 1 /*lrelu*/, 0);
    dwconv_kernel<<<dim3(BINS_ / 256, W_, B_), 256, 0, s2>>>(p_t1, c1R_dw, p_dwc2h, BINS_, 7, 3);
    launch_hgemm(p_dwc2h, BINS_, 0, 0, c1Rh, BINS_, 0, 0, nullptr, p_ffb, nullptr, FFH_, 0, 0,
                 M, FFH_, BINS_, 1, 1, 1, 0, s2);
    cudaEventRecord(ev[3], s2);
    cudaStreamWaitEvent(0, ev[3], 0);

    // enc_attn2 K/V (depends only on ms + weights) early on s2
    launch_hgemm(p_msh, BINS_, 0, 0, awh + 3 * ANK + NK, BINS_, 0, 0, attn_b + 3 * 4 * BINS_ + BINS_,
                 nullptr, p_qkv2h + BINS_, QKV_, 0, 0, M, 2 * BINS_, BINS_, 1, 1, 1, 0, s2);
    cudaEventRecord(ev[4], s2);

    // h = LN2(ffa + pad(ffb)), c2 chain
    ln_kernel<<<M, 256, FF2_ * 4>>>(p_ffa, p_ffb, FFH_, nullptr, nullptr, ln2_g, ln2_b,
                                    p_ffa, nullptr, FF2_);
    dwconv_kernel<<<dim3(FF2_ / 256, W_, B_), 256>>>(p_ffa, c2_dw, p_dwfh, FF2_, 7, 3);
    launch_hgemm(p_dwfh, FF2_, 0, 0, c2h, FF2_, 0, 0, nullptr, p_hs, nullptr, BINS_, 0, 0,
                 M, BINS_, FF2_, 1, 1, 1, 0, 0);

    // x2 = LN(x1*omega1 + h) -> fp32 + fp16
    ln_kernel<<<M, 256, BINS_ * 4>>>(p_t1, p_hs, BINS_, nullptr, omega + 1 * BINS_,
                                     ln_g + 1 * BINS_, ln_b + 1 * BINS_, p_t2, p_xh, BINS_);

    // self_attn2 ; x3
    launch_hgemm(p_xh, BINS_, 0, 0, awh + 2 * ANK, BINS_, 0, 0, attn_b + 2 * 4 * BINS_,
                 nullptr, p_qkvh, QKV_, 0, 0, M, QKV_, BINS_, 1, 1, 1, 0, 0);
    attn_core(awh + 2 * ANK, attn_b + 2 * 4 * BINS_, erh + 2 * ERS,
              p_qkvh, p_atth, p_scores, p_scoresh, p_hs, 0);
    ln_kernel<<<M, 256, BINS_ * 4>>>(p_t2, p_hs, BINS_, nullptr, omega + 2 * BINS_,
                                     ln_g + 2 * BINS_, ln_b + 2 * BINS_, p_t1, p_xh, BINS_);

    // enc_attn2: Q on stream 0 (K/V ready via ev[4]); x4
    launch_hgemm(p_xh, BINS_, 0, 0, awh + 3 * ANK, BINS_, 0, 0, attn_b + 3 * 4 * BINS_,
                 nullptr, p_qkv2h, QKV_, 0, 0, M, BINS_, BINS_, 1, 1, 1, 0, 0);
    cudaStreamWaitEvent(0, ev[4], 0);
    attn_core(awh + 3 * ANK, attn_b + 3 * 4 * BINS_, erh + 3 * ERS,
              p_qkv2h, p_atth, p_scores, p_scoresh, p_hs, 0);
    ln_kernel<<<M, 256, BINS_ * 4>>>(p_t1, p_hs, BINS_, nullptr, omega + 3 * BINS_,
                                     ln_g + 3 * BINS_, ln_b + 3 * BINS_, p_t2, p_xh, BINS_);

    // FFN: silu(x4 @ c3^T) @ c4^T
    launch_hgemm(p_xh, BINS_, 0, 0, c3h, BINS_, 0, 0, nullptr, nullptr, p_ffah, FF2_, 0, 0,
                 M, FF2_, BINS_, 1, 1, 1, 2 /*silu*/, 0);
    launch_hgemm(p_ffah, FF2_, 0, 0, c4h, FF2_, 0, 0, nullptr, p_hs, nullptr, BINS_, 0, 0,
                 M, BINS_, FF2_, 1, 1, 1, 0, 0);

    // out = LN(x4*omega4 + h) -> fp32; transpose
    ln_kernel<<<M, 256, BINS_ * 4>>>(p_t2, p_hs, BINS_, nullptr, omega + 4 * BINS_,
                                     ln_g + 4 * BINS_, ln_b + 4 * BINS_, p_t1, nullptr, BINS_);
    {
        dim3 g(W_ / 32, BINS_ / 32, B_), blk(32, 8);
        transpose_out_kernel<<<g, blk>>>(p_t1, (float*)d_out);
    }
}